// round 11
// baseline (speedup 1.0000x reference)
#include <cuda_runtime.h>
#include <stdint.h>
#include <math.h>

#define BB 4
#define CC 64
#define HH 256
#define WW 256
#define WF 129
#define HWF (HH*WF)            // 33024
#define NPIX (BB*CC*HWF)       // 8454144
#define NP (BB*HWF)            // 132096
#define FPAD 261

// ---------------- scratch (branch axis f: 0=amp, 1=pha) ----------------
__device__ float2 g_XF[NPIX];
__device__ float  g_amp[NPIX];
__device__ float  g_pha[NPIX];
__device__ float  g_a3[NPIX];
__device__ float  g_p3[NPIX];
__device__ float  g_offs[2*BB*18*HWF];
__device__ float  g_S[(size_t)2*BB*CC*9*HWF];   // sample planes [f][b][c][n][h][w]
__device__ float  g_xr[(size_t)BB*CC*HH*WW];
__device__ float2 g_tw[129];

#define SBR ((size_t)BB*CC*9*HWF)

// ---------------- packed f32x2 helpers ----------------
typedef unsigned long long u64;
__device__ __forceinline__ u64 pack2(float lo, float hi) {
    u64 r; asm("mov.b64 %0, {%1, %2};" : "=l"(r) : "f"(lo), "f"(hi)); return r;
}
__device__ __forceinline__ void unpack2(u64 v, float& lo, float& hi) {
    asm("mov.b64 {%0, %1}, %2;" : "=f"(lo), "=f"(hi) : "l"(v));
}
__device__ __forceinline__ void fma2(u64& d, u64 a, u64 b) {
    asm("fma.rn.f32x2 %0, %1, %2, %0;" : "+l"(d) : "l"(a), "l"(b));
}

// ---------------- cp.async helpers ----------------
__device__ __forceinline__ void cpa4(uint32_t dst, const float* src, bool pred) {
    int sz = pred ? 4 : 0;
    asm volatile("cp.async.ca.shared.global [%0], [%1], 4, %2;" :: "r"(dst), "l"(src), "r"(sz));
}
#define CP_COMMIT() asm volatile("cp.async.commit_group;" ::: "memory")
#define CP_WAIT1()  asm volatile("cp.async.wait_group 1;" ::: "memory")
#define CP_WAIT0()  asm volatile("cp.async.wait_group 0;" ::: "memory")

// ---------------- precise transcendentals ----------------
__device__ __forceinline__ void sincos_acc(float x, float* sp, float* cp) {
    float k = rintf(x * 0.63661977236758134f);
    float r = fmaf(k, -1.5707963705062866f, x);
    r = fmaf(k, 4.37113900018624e-8f, r);
    int q = (int)k;
    float z = r * r;
    float ss = 2.75573192e-6f;
    ss = fmaf(ss, z, -1.98412698e-4f);
    ss = fmaf(ss, z, 8.33333333e-3f);
    ss = fmaf(ss, z, -1.66666667e-1f);
    ss = fmaf(ss * z, r, r);
    float cc = -2.75573192e-7f;
    cc = fmaf(cc, z, 2.48015873e-5f);
    cc = fmaf(cc, z, -1.38888889e-3f);
    cc = fmaf(cc, z, 4.16666667e-2f);
    cc = fmaf(cc, z, -0.5f);
    cc = fmaf(cc, z, 1.0f);
    int qq = q & 3;
    float s_ = (qq & 1) ? cc : ss;
    float c_ = (qq & 1) ? ss : cc;
    if (qq == 1 || qq == 2) c_ = -c_;
    if (qq >= 2) s_ = -s_;
    *sp = s_; *cp = c_;
}

__device__ __forceinline__ float atan2_acc(float y, float x) {
    float ax = fabsf(x), ay = fabsf(y);
    float mx = fmaxf(ax, ay), mn = fminf(ax, ay);
    float t = (mx > 0.f) ? __fdiv_rn(mn, mx) : 0.f;
    float base = 0.f;
    if (t > 0.414213562f) { t = __fdiv_rn(t - 1.f, t + 1.f); base = 0.78539816339744831f; }
    float z = t * t;
    float p = -0.066666667f;
    p = fmaf(p, z,  0.076923077f);
    p = fmaf(p, z, -0.090909091f);
    p = fmaf(p, z,  0.111111111f);
    p = fmaf(p, z, -0.142857143f);
    p = fmaf(p, z,  0.2f);
    p = fmaf(p, z, -0.333333333f);
    float r = fmaf(t * z, p, t) + base;
    if (ay > ax) r = 1.57079632679489662f - r;
    if (x < 0.f) r = 3.14159265358979323f - r;
    return copysignf(r, y);
}

__global__ void twiddle_init() {
    int k = threadIdx.x;
    if (k < 129) {
        double a = -2.0 * 3.14159265358979323846 * (double)k / 256.0;
        float2 v = make_float2((float)cos(a), (float)sin(a));
        if (k == 0) v = make_float2(1.f, 0.f);
        g_tw[k] = v;
    }
}

// ---------------- FFT-256 (table = forward twiddles). sign=+1 fwd, -1 inv ----------------
__device__ __forceinline__ void fft256_tab(float2* s, const float2* tw, int t, float sign) {
#pragma unroll
    for (int kk = 0; kk < 2; kk++) {
        int i = t + (kk << 7);
        int j = __brev(i) >> 24;
        if (i < j) { float2 a = s[i]; s[i] = s[j]; s[j] = a; }
    }
    __syncthreads();
#pragma unroll
    for (int st = 1; st <= 8; st++) {
        int half = 1 << (st - 1);
        int g = t >> (st - 1);
        int p = t & (half - 1);
        int i0 = (g << st) + p;
        int i1 = i0 + half;
        float2 w = tw[p << (8 - st)];
        float wy = sign * w.y;
        float2 a = s[i0], b = s[i1];
        float2 wb = make_float2(w.x * b.x - wy * b.y, w.x * b.y + wy * b.x);
        s[i0] = make_float2(a.x + wb.x, a.y + wb.y);
        s[i1] = make_float2(a.x - wb.x, a.y - wb.y);
        __syncthreads();
    }
}

// ---- row forward rFFT, two real rows packed per complex FFT (exact) ----
__global__ void fft_row_fwd_pair(const float* __restrict__ x) {
    __shared__ float2 s[256];
    __shared__ float2 tw[128];
    int r = blockIdx.x & 127, bc = blockIdx.x >> 7, t = threadIdx.x;
    tw[t] = g_tw[t];
    const float* row0 = x + ((size_t)bc * 256 + 2 * r) * 256;
    const float* row1 = row0 + 256;
    s[t]       = make_float2(row0[t], row1[t]);
    s[t + 128] = make_float2(row0[t + 128], row1[t + 128]);
    __syncthreads();
    fft256_tab(s, tw, t, +1.f);
    size_t b0 = ((size_t)bc * 256 + 2 * r) * WF;
    size_t b1 = b0 + WF;
    float2 A = s[t];
    float2 Zr = s[(256 - t) & 255];
    g_XF[b0 + t] = make_float2(0.5f * (A.x + Zr.x), 0.5f * (A.y - Zr.y));
    g_XF[b1 + t] = make_float2(0.5f * (A.y + Zr.y), 0.5f * (Zr.x - A.x));
    if (t == 0) {
        float2 M = s[128];
        g_XF[b0 + 128] = make_float2(M.x, 0.f);
        g_XF[b1 + 128] = make_float2(M.y, 0.f);
    }
}

__global__ void fft_col_kernel(int dir) {
    __shared__ float2 S[16 * FPAD];
    __shared__ float2 tw[128];
    int k0 = blockIdx.x * 16;
    int c = blockIdx.y, b = blockIdx.z;
    int tid = threadIdx.x;
    if (tid < 128) tw[tid] = g_tw[tid];
    size_t base = ((size_t)(b * CC + c)) * HH * WF;

    for (int idx = tid; idx < 256 * 16; idx += 256) {
        int h = idx >> 4, kk = idx & 15;
        int k = k0 + kk;
        float2 v = (k < WF) ? g_XF[base + (size_t)h * WF + k] : make_float2(0.f, 0.f);
        S[kk * FPAD + h] = v;
    }
    __syncthreads();

    int f = tid >> 4;
    int l = tid & 15;
    float2* s = &S[f * FPAD];
#pragma unroll
    for (int m = 0; m < 16; m++) {
        int i = l + (m << 4);
        int j = __brev(i) >> 24;
        if (i < j) { float2 a = s[i]; s[i] = s[j]; s[j] = a; }
    }
    __syncthreads();
    float sign = dir ? -1.f : 1.f;
#pragma unroll
    for (int st = 1; st <= 8; st++) {
        int half = 1 << (st - 1);
#pragma unroll
        for (int m = 0; m < 8; m++) {
            int t = l + (m << 4);
            int g = t >> (st - 1);
            int p = t & (half - 1);
            int i0 = (g << st) + p;
            int i1 = i0 + half;
            float2 w = tw[p << (8 - st)];
            float wy = sign * w.y;
            float2 a = s[i0], bv = s[i1];
            float2 wb = make_float2(w.x * bv.x - wy * bv.y, w.x * bv.y + wy * bv.x);
            s[i0] = make_float2(a.x + wb.x, a.y + wb.y);
            s[i1] = make_float2(a.x - wb.x, a.y - wb.y);
        }
        __syncthreads();
    }

    if (dir == 0) {
        for (int idx = tid; idx < 256 * 16; idx += 256) {
            int h = idx >> 4, kk = idx & 15;
            int k = k0 + kk;
            if (k < WF) {
                float2 v = S[kk * FPAD + h];
                size_t o = base + (size_t)h * WF + k;
                g_amp[o] = __fsqrt_rn(fmaf(v.x, v.x, v.y * v.y));
                g_pha[o] = atan2_acc(v.y, v.x);
            }
        }
    } else {
        for (int idx = tid; idx < 256 * 16; idx += 256) {
            int h = idx >> 4, kk = idx & 15;
            int k = k0 + kk;
            if (k < WF) g_XF[base + (size_t)h * WF + k] = S[kk * FPAD + h];
        }
    }
}

// ---- row inverse rFFT, two rows per complex iFFT.
// pocketfft irfft semantics: imaginary parts of DC (k=0) and Nyquist (k=128)
// are DISCARDED. Zeroing them here keeps X1/X2 exactly hermitian so the two
// packed rows separate cleanly into Re/Im.
__global__ void ifft_row_pair() {
    __shared__ float2 s[256];
    __shared__ float2 tw[128];
    int r = blockIdx.x & 127, bc = blockIdx.x >> 7, t = threadIdx.x;
    tw[t] = g_tw[t];
    size_t b0 = ((size_t)bc * 256 + 2 * r) * WF;
    size_t b1 = b0 + WF;
    {
        float2 a1 = g_XF[b0 + t], a2 = g_XF[b1 + t];
        if (t == 0) {
            s[0] = make_float2(a1.x, a2.x);          // drop Im(DC)
            float2 m1 = g_XF[b0 + 128], m2 = g_XF[b1 + 128];
            s[128] = make_float2(m1.x, m2.x);        // drop Im(Nyquist)
        } else {
            s[t] = make_float2(a1.x - a2.y, a1.y + a2.x);
            float2 c1 = g_XF[b0 + 128 - t], c2 = g_XF[b1 + 128 - t];
            s[t + 128] = make_float2(c1.x + c2.y, -c1.y + c2.x);
        }
    }
    __syncthreads();
    fft256_tab(s, tw, t, -1.f);
    const float inv = 1.f / 65536.f;
    float* orow0 = g_xr + ((size_t)bc * 256 + 2 * r) * 256;
    float* orow1 = orow0 + 256;
    orow0[t]       = fabsf(s[t].x * inv);
    orow0[t + 128] = fabsf(s[t + 128].x * inv);
    orow1[t]       = fabsf(s[t].y * inv);
    orow1[t + 128] = fabsf(s[t + 128].y * inv);
}

// ------- merged 3x3 pad-1 conv 64->18, register-prefetch pipeline -------
__global__ void __launch_bounds__(256, 3)
conv_off_kernel(const float* __restrict__ wp_a, const float* __restrict__ bp_a,
                const float* __restrict__ wp_p, const float* __restrict__ bp_p) {
    __shared__ float TT[612];      // 34 rows x 18 cols
    __shared__ float WS[180];      // 9 taps x 20 (padded for float4 reads)
    int w0b = blockIdx.x * 16, h0 = blockIdx.y * 32;
    int bz = blockIdx.z;
    int f = bz & 1, b = bz >> 1;
    const float* src = f ? g_pha : g_amp;
    const float* wp = f ? wp_p : wp_a;
    const float* bp = f ? bp_p : bp_a;
    int tid = threadIdx.x;
    int tx = tid & 15, ty = tid >> 4;

    int i0 = tid, i1 = tid + 256, i2 = tid + 512;
    bool v0, v1, v2;
    int o0, o1, o2;
    {
        int r, cc, gh, gw;
        r = i0 / 18; cc = i0 - r * 18; gh = h0 + r - 1; gw = w0b + cc - 1;
        v0 = (gh >= 0 && gh < HH && gw >= 0 && gw < WF); o0 = gh * WF + gw;
        r = i1 / 18; cc = i1 - r * 18; gh = h0 + r - 1; gw = w0b + cc - 1;
        v1 = (gh >= 0 && gh < HH && gw >= 0 && gw < WF); o1 = gh * WF + gw;
        r = i2 / 18; cc = i2 - r * 18; gh = h0 + r - 1; gw = w0b + cc - 1;
        v2 = (i2 < 612) && (gh >= 0 && gh < HH && gw >= 0 && gw < WF); o2 = gh * WF + gw;
    }
    bool wq = tid < 162;
    int wk = tid / 18, wo = tid % 18;
    int wslot = wk * 20 + wo;
    int wbase = wo * CC * 9 + wk;     // + ic*9

    const float* P = src + (size_t)b * CC * HWF;
    float rA = v0 ? __ldg(P + o0) : 0.f;
    float rB = v1 ? __ldg(P + o1) : 0.f;
    float rC = v2 ? __ldg(P + o2) : 0.f;
    float rW = wq ? __ldg(wp + wbase) : 0.f;

    u64 acc0[9], acc1[9];
#pragma unroll
    for (int j = 0; j < 9; j++) { acc0[j] = pack2(0.f, 0.f); acc1[j] = pack2(0.f, 0.f); }

    for (int ic = 0; ic < CC; ic++) {
        __syncthreads();
        TT[i0] = rA;
        TT[i1] = rB;
        if (i2 < 612) TT[i2] = rC;
        if (wq) WS[wslot] = rW;
        if (ic < CC - 1) {
            const float* Pn = P + (size_t)(ic + 1) * HWF;
            rA = v0 ? __ldg(Pn + o0) : 0.f;
            rB = v1 ? __ldg(Pn + o1) : 0.f;
            rC = v2 ? __ldg(Pn + o2) : 0.f;
            rW = wq ? __ldg(wp + wbase + (ic + 1) * 9) : 0.f;
        }
        __syncthreads();
#pragma unroll
        for (int k = 0; k < 9; k++) {
            int ky = k / 3, kx = k % 3;
            float va = TT[(2 * ty + ky) * 18 + tx + kx];
            float vb = TT[(2 * ty + 1 + ky) * 18 + tx + kx];
            u64 V0 = pack2(va, va);
            u64 V1 = pack2(vb, vb);
            const float* Wr = &WS[k * 20];
            float4 q0 = *reinterpret_cast<const float4*>(Wr);
            float4 q1 = *reinterpret_cast<const float4*>(Wr + 4);
            float4 q2 = *reinterpret_cast<const float4*>(Wr + 8);
            float4 q3 = *reinterpret_cast<const float4*>(Wr + 12);
            u64 w8 = *reinterpret_cast<const u64*>(Wr + 16);
            u64 Wv[9] = { pack2(q0.x, q0.y), pack2(q0.z, q0.w),
                          pack2(q1.x, q1.y), pack2(q1.z, q1.w),
                          pack2(q2.x, q2.y), pack2(q2.z, q2.w),
                          pack2(q3.x, q3.y), pack2(q3.z, q3.w), w8 };
#pragma unroll
            for (int j = 0; j < 9; j++) {
                fma2(acc0[j], Wv[j], V0);
                fma2(acc1[j], Wv[j], V1);
            }
        }
    }
    int h = h0 + 2 * ty, w = w0b + tx;
    if (w < WF) {
#pragma unroll
        for (int j = 0; j < 9; j++) {
            float lo0, hi0, lo1, hi1;
            unpack2(acc0[j], lo0, hi0);
            unpack2(acc1[j], lo1, hi1);
            float blo = bp[2 * j], bhi = bp[2 * j + 1];
            size_t base = (size_t)((f * BB + b) * 18);
            g_offs[((base + 2 * j    ) * HH + h) * WF + w]     = lo0 + blo;
            g_offs[((base + 2 * j + 1) * HH + h) * WF + w]     = hi0 + bhi;
            g_offs[((base + 2 * j    ) * HH + h + 1) * WF + w] = lo1 + blo;
            g_offs[((base + 2 * j + 1) * HH + h + 1) * WF + w] = hi1 + bhi;
        }
    }
}

// ---------------- fused sampling-params + gather ----------------
__device__ __forceinline__ int padidx(float qx, float qy) {
    int X = (int)qx, Y = (int)qy;
    if (X >= 1 && X <= 256 && Y >= 1 && Y <= 129) return (X - 1) * WF + (Y - 1);
    return -1;
}

__global__ void gather_kernel() {
    int t = blockIdx.x * 256 + threadIdx.x;
    if (t >= NP) return;
    int f = blockIdx.y;
    int w = t % WF;
    int r = t / WF;
    int h = r % HH;
    int b = r / HH;

    const float* Pb = (f ? g_pha : g_amp) + (size_t)b * CC * HWF;
    float* Sbase = g_S + (size_t)f * SBR + ((size_t)b * CC * 9) * HWF + (size_t)h * WF + w;
    size_t obase = (size_t)((f * BB + b) * 18);
    const float HMax = 257.f, WMax = 130.f;

#pragma unroll
    for (int n = 0; n < 9; n++) {
        int i = n / 3, j = n % 3;
        float offx = g_offs[((obase + n    ) * HH + h) * WF + w];
        float offy = g_offs[((obase + n + 9) * HH + h) * WF + w];
        float px = (float)(h + 1) + (float)(i - 1) + offx;
        float py = (float)(w + 1) + (float)(j - 1) + offy;
        float qx = floorf(px), qy = floorf(py);
        float qltx = fminf(fmaxf(qx, 0.f), HMax);
        float qlty = fminf(fmaxf(qy, 0.f), WMax);
        float qrbx = fminf(fmaxf(qx + 1.f, 0.f), HMax);
        float qrby = fminf(fmaxf(qy + 1.f, 0.f), WMax);
        float cpx  = fminf(fmaxf(px, 0.f), HMax);
        float cpy  = fminf(fmaxf(py, 0.f), WMax);
        float glt = (1.f + (qltx - cpx)) * (1.f + (qlty - cpy));
        float grb = (1.f - (qrbx - cpx)) * (1.f - (qrby - cpy));
        float glb = (1.f + (qltx - cpx)) * (1.f - (qrby - cpy));
        float grt = (1.f - (qrbx - cpx)) * (1.f + (qlty - cpy));
        int ilt = padidx(qltx, qlty);
        int irb = padidx(qrbx, qrby);
        int ilb = padidx(qltx, qrby);
        int irt = padidx(qrbx, qlty);
        float* Sn = Sbase + (size_t)n * HWF;
#pragma unroll 4
        for (int c = 0; c < CC; c++) {
            const float* P = Pb + (size_t)c * HWF;
            float v = 0.f;
            if (ilt >= 0) v += glt * __ldg(P + ilt);
            if (irb >= 0) v += grb * __ldg(P + irb);
            if (ilb >= 0) v += glb * __ldg(P + ilb);
            if (irt >= 0) v += grt * __ldg(P + irt);
            Sn[(size_t)c * 9 * HWF] = v;
        }
    }
}

// ------- deform conv (merged): cp.async double-buffered, 32 oc/block, 2 px/thread -------
__global__ void conv_s3_kernel(const float* __restrict__ wc_a, const float* __restrict__ wc_p) {
    __shared__ float SS[2][5346];    // 9 planes x 33 x 18
    __shared__ float WSS[2][288];
    int w0 = blockIdx.x * 16, h0 = blockIdx.y * 32;
    int bz = blockIdx.z;
    int og = bz & 1;
    int f = (bz >> 1) & 1;
    int b = bz >> 2;
    const float* wc = f ? wc_p : wc_a;
    int tid = threadIdx.x;
    int tx = tid & 15, ty = tid >> 4;
    u64 acc0[16], acc1[16];
#pragma unroll
    for (int j = 0; j < 16; j++) { acc0[j] = pack2(0.f, 0.f); acc1[j] = pack2(0.f, 0.f); }

    const int ni[3] = {2, 0, 1};
    const int dd[3] = {-1, 0, 0};
    const float* Sbr = g_S + (size_t)f * SBR + ((size_t)b * CC * 9) * HWF;

    int poff[3]; bool ppred[3];
#pragma unroll
    for (int u = 0; u < 3; u++) {
        int idx2 = tid + (u << 8);
        int rr = idx2 / 18, cc = idx2 - rr * 18;
        int gh = h0 - 1 + rr, gw = w0 - 1 + cc;
        ppred[u] = (idx2 < 594) && (gh >= 0 && gh < HH && gw >= 0 && gw < WF);
        poff[u] = gh * WF + gw;
    }
    int wo0 = ((og * 32 + (tid & 31)) * CC) * 9 + (tid >> 5);
    int idxw1 = tid + 256;
    int wo1 = ((og * 32 + (idxw1 & 31)) * CC) * 9 + (idxw1 >> 5);
    bool wp1 = idxw1 < 288;

    uint32_t tb[2], wb2[2];
    tb[0] = (uint32_t)__cvta_generic_to_shared(&SS[0][0]);
    tb[1] = (uint32_t)__cvta_generic_to_shared(&SS[1][0]);
    wb2[0] = (uint32_t)__cvta_generic_to_shared(&WSS[0][0]);
    wb2[1] = (uint32_t)__cvta_generic_to_shared(&WSS[1][0]);

    auto load_stage = [&](int ic, int bufi) {
        const float* Sb = Sbr + (size_t)ic * 9 * HWF;
#pragma unroll
        for (int n = 0; n < 9; n++) {
            const float* Pn = Sb + (size_t)n * HWF;
            uint32_t dbs = tb[bufi] + 4u * (n * 594);
#pragma unroll
            for (int u = 0; u < 3; u++) {
                int idx2 = tid + (u << 8);
                if (idx2 < 594) cpa4(dbs + 4u * idx2, Pn + poff[u], ppred[u]);
            }
        }
        cpa4(wb2[bufi] + 4u * tid, wc + wo0 + ic * 9, true);
        if (wp1) cpa4(wb2[bufi] + 4u * idxw1, wc + wo1 + ic * 9, true);
    };

    load_stage(0, 0);
    CP_COMMIT();

    for (int ic = 0; ic < CC; ic++) {
        int cur = ic & 1;
        if (ic + 1 < CC) {
            load_stage(ic + 1, cur ^ 1);
            CP_COMMIT();
            CP_WAIT1();
        } else {
            CP_WAIT0();
        }
        __syncthreads();
        const float* Sc = &SS[cur][0];
        const float* Wc = &WSS[cur][0];
#pragma unroll
        for (int rr = 0; rr < 3; rr++) {
#pragma unroll
            for (int c3 = 0; c3 < 3; c3++) {
                int n = ni[rr] * 3 + ni[c3];
                int row = 2 * ty + 1 + dd[rr];
                int col = tx + 1 + dd[c3];
                float v0 = Sc[n * 594 + row * 18 + col];
                float v1 = Sc[n * 594 + (row + 1) * 18 + col];
                u64 V0 = pack2(v0, v0);
                u64 V1 = pack2(v1, v1);
                int k = rr * 3 + c3;
                const float* Wr = &Wc[k * 32];
#pragma unroll
                for (int m = 0; m < 8; m++) {
                    float4 q = *reinterpret_cast<const float4*>(Wr + 4 * m);
                    u64 Wv0 = pack2(q.x, q.y);
                    u64 Wv1 = pack2(q.z, q.w);
                    fma2(acc0[2 * m],     Wv0, V0);
                    fma2(acc1[2 * m],     Wv0, V1);
                    fma2(acc0[2 * m + 1], Wv1, V0);
                    fma2(acc1[2 * m + 1], Wv1, V1);
                }
            }
        }
        __syncthreads();
    }
    int oh = h0 + 2 * ty, ow = w0 + tx;
    if (ow < WF) {
        float* dst = f ? g_p3 : g_a3;
#pragma unroll
        for (int j = 0; j < 16; j++) {
            float lo0, hi0, lo1, hi1;
            unpack2(acc0[j], lo0, hi0);
            unpack2(acc1[j], lo1, hi1);
            int oc = og * 32 + 2 * j;
            dst[((size_t)(b * CC + oc    ) * HH + oh) * WF + ow]     = lo0;
            dst[((size_t)(b * CC + oc + 1) * HH + oh) * WF + ow]     = hi0;
            dst[((size_t)(b * CC + oc    ) * HH + oh + 1) * WF + ow] = lo1;
            dst[((size_t)(b * CC + oc + 1) * HH + oh + 1) * WF + ow] = hi1;
        }
    }
}

// ---------------- fused conv1x1(both branches) + combine ----------------
extern __shared__ float dynC[];
__global__ void combine1x1_kernel(const float* __restrict__ w1_a, const float* __restrict__ b1_a,
                                  const float* __restrict__ w1_p, const float* __restrict__ b1_p) {
    float* XSa = dynC;
    float* XSp = XSa + 64 * 33;
    float* WTa = XSp + 64 * 33;
    float* WTp = WTa + 64 * 64;
    int p0 = blockIdx.x * 32;
    int b = blockIdx.y;
    int tid = threadIdx.x;
    const float* sa = g_amp + (size_t)b * CC * HWF;
    const float* sp = g_pha + (size_t)b * CC * HWF;
    for (int idx = tid; idx < 2048; idx += 256) {
        int c = idx >> 5, p = idx & 31;
        XSa[c * 33 + p] = sa[(size_t)c * HWF + p0 + p];
        XSp[c * 33 + p] = sp[(size_t)c * HWF + p0 + p];
    }
    for (int idx = tid; idx < 4096; idx += 256) {
        int oc = idx >> 6, k = idx & 63;
        WTa[k * 64 + oc] = w1_a[idx];
        WTp[k * 64 + oc] = w1_p[idx];
    }
    __syncthreads();
    int px = tid & 31, ocg = tid >> 5;
    float a1acc[8] = {0.f, 0.f, 0.f, 0.f, 0.f, 0.f, 0.f, 0.f};
    float p1acc[8] = {0.f, 0.f, 0.f, 0.f, 0.f, 0.f, 0.f, 0.f};
    for (int k = 0; k < 64; k++) {
        float xa = XSa[k * 33 + px];
        float xp = XSp[k * 33 + px];
#pragma unroll
        for (int j = 0; j < 8; j++) {
            a1acc[j] = fmaf(WTa[k * 64 + ocg + 8 * j], xa, a1acc[j]);
            p1acc[j] = fmaf(WTp[k * 64 + ocg + 8 * j], xp, p1acc[j]);
        }
    }
#pragma unroll
    for (int j = 0; j < 8; j++) {
        int oc = ocg + 8 * j;
        float a1 = a1acc[j] + b1_a[oc];
        float p1 = p1acc[j] + b1_p[oc];
        size_t o = (size_t)(b * CC + oc) * HWF + p0 + px;
        float a3 = g_a3[o], p3 = g_p3[o];
        float s1, c1, s3, c3;
        sincos_acc(p1, &s1, &c1);
        sincos_acc(p3, &s3, &c3);
        g_XF[o] = make_float2(a1 * c3 + a3 * c1 + 3e-8f,
                              a3 * s1 + a1 * s3 + 2e-8f);
    }
}

// ------- final 5x5 conv: cp.async double-buffered, 16 oc packed, 2x2 px, 8-ic batch -------
extern __shared__ float dyn5[];
__global__ void conv5x5_kernel(const float* __restrict__ w0, const float* __restrict__ b0,
                               float* __restrict__ out) {
    float* T0 = dyn5;                      // 8 x 1332
    float* T1 = T0 + 8 * 1332;
    float* W0b = T1 + 8 * 1332;            // 3200
    float* W1b = W0b + 3200;
    int w0b = blockIdx.x * 32, h0 = blockIdx.y * 32;
    int bz = blockIdx.z;
    int og = bz & 3;
    int b = bz >> 2;
    int tid = threadIdx.x;
    int tx = tid & 15, ty = tid >> 4;
    u64 acc00[8], acc01[8], acc10[8], acc11[8];
#pragma unroll
    for (int j = 0; j < 8; j++) {
        acc00[j] = pack2(0.f, 0.f); acc01[j] = pack2(0.f, 0.f);
        acc10[j] = pack2(0.f, 0.f); acc11[j] = pack2(0.f, 0.f);
    }

    int poff[6], pdst[6]; bool ppred[6];
#pragma unroll
    for (int u = 0; u < 6; u++) {
        int idx2 = tid + (u << 8);
        int rr = idx2 / 36, cc = idx2 - rr * 36;
        int gh = h0 + rr - 2, gw = w0b + cc - 2;
        ppred[u] = (idx2 < 1296) && (gh >= 0 && gh < HH && gw >= 0 && gw < WW);
        poff[u] = gh * WW + gw;
        pdst[u] = rr * 37 + cc;
    }
    int wk0 = tid / 16, wo0 = tid % 16;
    int idxw1 = tid + 256;
    int wk1 = idxw1 / 16, wo1 = idxw1 % 16;
    bool wpq1 = idxw1 < 400;
    int wbase0 = ((og * 16 + wo0) * CC) * 25 + wk0;
    int wbase1 = ((og * 16 + wo1) * CC) * 25 + wk1;

    const float* Pb = g_xr + (size_t)(b * CC) * HH * WW;
    uint32_t tb[2], wb2[2];
    tb[0] = (uint32_t)__cvta_generic_to_shared(T0);
    tb[1] = (uint32_t)__cvta_generic_to_shared(T1);
    wb2[0] = (uint32_t)__cvta_generic_to_shared(W0b);
    wb2[1] = (uint32_t)__cvta_generic_to_shared(W1b);

    auto load_stage = [&](int ic0, int bufi) {
#pragma unroll
        for (int ii = 0; ii < 8; ii++) {
            const float* Pn = Pb + (size_t)(ic0 + ii) * HH * WW;
            uint32_t dbs = tb[bufi] + 4u * (ii * 1332);
#pragma unroll
            for (int u = 0; u < 6; u++) {
                int idx2 = tid + (u << 8);
                if (idx2 < 1296) cpa4(dbs + 4u * pdst[u], Pn + poff[u], ppred[u]);
            }
            uint32_t wdbs = wb2[bufi] + 4u * (ii * 400);
            cpa4(wdbs + 4u * tid, w0 + wbase0 + (ic0 + ii) * 25, true);
            if (wpq1) cpa4(wdbs + 4u * idxw1, w0 + wbase1 + (ic0 + ii) * 25, true);
        }
    };

    load_stage(0, 0);
    CP_COMMIT();

    for (int s = 0; s < 8; s++) {
        int cur = s & 1;
        if (s + 1 < 8) {
            load_stage((s + 1) * 8, cur ^ 1);
            CP_COMMIT();
            CP_WAIT1();
        } else {
            CP_WAIT0();
        }
        __syncthreads();
        const float* Tc = cur ? T1 : T0;
        const float* Wc = cur ? W1b : W0b;
#pragma unroll
        for (int ii = 0; ii < 8; ii++) {
            const float* Tb = &Tc[ii * 1332];
            const float* Wb = &Wc[ii * 400];
#pragma unroll
            for (int k = 0; k < 25; k++) {
                int ky = k / 5, kx = k % 5;
                const float* row0 = Tb + (2 * ty + ky) * 37 + 2 * tx + kx;
                float v00 = row0[0];
                float v01 = row0[1];
                float v10 = row0[37];
                float v11 = row0[38];
                u64 V00 = pack2(v00, v00);
                u64 V01 = pack2(v01, v01);
                u64 V10 = pack2(v10, v10);
                u64 V11 = pack2(v11, v11);
                const float* Wr = &Wb[k * 16];
#pragma unroll
                for (int m = 0; m < 4; m++) {
                    float4 q = *reinterpret_cast<const float4*>(Wr + 4 * m);
                    u64 Wv0 = pack2(q.x, q.y);
                    u64 Wv1 = pack2(q.z, q.w);
                    fma2(acc00[2 * m],     Wv0, V00);
                    fma2(acc01[2 * m],     Wv0, V01);
                    fma2(acc10[2 * m],     Wv0, V10);
                    fma2(acc11[2 * m],     Wv0, V11);
                    fma2(acc00[2 * m + 1], Wv1, V00);
                    fma2(acc01[2 * m + 1], Wv1, V01);
                    fma2(acc10[2 * m + 1], Wv1, V10);
                    fma2(acc11[2 * m + 1], Wv1, V11);
                }
            }
        }
        __syncthreads();
    }
    int h = h0 + 2 * ty, w = w0b + 2 * tx;
#pragma unroll
    for (int j = 0; j < 8; j++) {
        int oc = og * 16 + 2 * j;
        float l00, h00, l01, h01, l10, h10, l11, h11;
        unpack2(acc00[j], l00, h00);
        unpack2(acc01[j], l01, h01);
        unpack2(acc10[j], l10, h10);
        unpack2(acc11[j], l11, h11);
        float blo = b0[oc], bhi = b0[oc + 1];
        float* o0 = out + ((size_t)(b * CC + oc) * HH + h) * WW + w;
        float* o1 = out + ((size_t)(b * CC + oc + 1) * HH + h) * WW + w;
        o0[0] = l00 + blo;  o0[1] = l01 + blo;
        o0[WW] = l10 + blo; o0[WW + 1] = l11 + blo;
        o1[0] = h00 + bhi;  o1[1] = h01 + bhi;
        o1[WW] = h10 + bhi; o1[WW + 1] = h11 + bhi;
    }
}

// ---------------- launcher ----------------
extern "C" void kernel_launch(void* const* d_in, const int* in_sizes, int n_in,
                              void* d_out, int out_size) {
    (void)in_sizes; (void)n_in; (void)out_size;
    const float* x    = (const float*)d_in[0];
    const float* wp_a = (const float*)d_in[1];
    const float* bp_a = (const float*)d_in[2];
    const float* wc_a = (const float*)d_in[3];
    const float* w1_a = (const float*)d_in[4];
    const float* b1_a = (const float*)d_in[5];
    const float* wp_p = (const float*)d_in[6];
    const float* bp_p = (const float*)d_in[7];
    const float* wc_p = (const float*)d_in[8];
    const float* w1_p = (const float*)d_in[9];
    const float* b1_p = (const float*)d_in[10];
    const float* w0   = (const float*)d_in[11];
    const float* b0   = (const float*)d_in[12];
    float* out = (float*)d_out;

    static int attr_done = 0;
    if (!attr_done) {
        cudaFuncSetAttribute(combine1x1_kernel, cudaFuncAttributeMaxDynamicSharedMemorySize, 49664);
        cudaFuncSetAttribute(conv5x5_kernel, cudaFuncAttributeMaxDynamicSharedMemorySize, 110848);
        attr_done = 1;
    }

    twiddle_init<<<1, 129>>>();

    fft_row_fwd_pair<<<BB * CC * 128, 128>>>(x);
    fft_col_kernel<<<dim3(9, CC, BB), 256>>>(0);

    // merged amp+pha deform pipeline
    conv_off_kernel<<<dim3(9, 8, BB * 2), 256>>>(wp_a, bp_a, wp_p, bp_p);
    gather_kernel<<<dim3(NP / 256, 2), 256>>>();
    conv_s3_kernel<<<dim3(9, 8, BB * 4), 256>>>(wc_a, wc_p);

    // fused 1x1 conv + recombine, then inverse transform
    combine1x1_kernel<<<dim3(HWF / 32, BB), 256, 49664>>>(w1_a, b1_a, w1_p, b1_p);
    fft_col_kernel<<<dim3(9, CC, BB), 256>>>(1);
    ifft_row_pair<<<BB * CC * 128, 128>>>();

    conv5x5_kernel<<<dim3(8, 8, BB * 4), 256, 110848>>>(w0, b0, out);
}

// round 12
// speedup vs baseline: 1.1630x; 1.1630x over previous
#include <cuda_runtime.h>
#include <stdint.h>
#include <math.h>

#define BB 4
#define CC 64
#define HH 256
#define WW 256
#define WF 129
#define HWF (HH*WF)            // 33024
#define NPIX (BB*CC*HWF)       // 8454144
#define NP (BB*HWF)            // 132096
#define FPAD 261

// ---------------- scratch (branch axis f: 0=amp, 1=pha) ----------------
__device__ float2 g_XF[NPIX];
__device__ float  g_amp[NPIX];
__device__ float  g_pha[NPIX];
__device__ float  g_a3[NPIX];
__device__ float  g_p3[NPIX];
__device__ float  g_offs[2*BB*18*HWF];
__device__ float  g_S[(size_t)2*BB*CC*9*HWF];   // sample planes [f][b][c][n][h][w]
__device__ float  g_xr[(size_t)BB*CC*HH*WW];
__device__ float2 g_tw[129];

#define SBR ((size_t)BB*CC*9*HWF)

// ---------------- packed f32x2 helpers ----------------
typedef unsigned long long u64;
__device__ __forceinline__ u64 pack2(float lo, float hi) {
    u64 r; asm("mov.b64 %0, {%1, %2};" : "=l"(r) : "f"(lo), "f"(hi)); return r;
}
__device__ __forceinline__ void unpack2(u64 v, float& lo, float& hi) {
    asm("mov.b64 {%0, %1}, %2;" : "=f"(lo), "=f"(hi) : "l"(v));
}
__device__ __forceinline__ void fma2(u64& d, u64 a, u64 b) {
    asm("fma.rn.f32x2 %0, %1, %2, %0;" : "+l"(d) : "l"(a), "l"(b));
}

// ---------------- cp.async helpers ----------------
__device__ __forceinline__ void cpa4(uint32_t dst, const float* src, bool pred) {
    int sz = pred ? 4 : 0;
    asm volatile("cp.async.ca.shared.global [%0], [%1], 4, %2;" :: "r"(dst), "l"(src), "r"(sz));
}
#define CP_COMMIT() asm volatile("cp.async.commit_group;" ::: "memory")
#define CP_WAIT1()  asm volatile("cp.async.wait_group 1;" ::: "memory")
#define CP_WAIT0()  asm volatile("cp.async.wait_group 0;" ::: "memory")

// ---------------- precise transcendentals ----------------
__device__ __forceinline__ void sincos_acc(float x, float* sp, float* cp) {
    float k = rintf(x * 0.63661977236758134f);
    float r = fmaf(k, -1.5707963705062866f, x);
    r = fmaf(k, 4.37113900018624e-8f, r);
    int q = (int)k;
    float z = r * r;
    float ss = 2.75573192e-6f;
    ss = fmaf(ss, z, -1.98412698e-4f);
    ss = fmaf(ss, z, 8.33333333e-3f);
    ss = fmaf(ss, z, -1.66666667e-1f);
    ss = fmaf(ss * z, r, r);
    float cc = -2.75573192e-7f;
    cc = fmaf(cc, z, 2.48015873e-5f);
    cc = fmaf(cc, z, -1.38888889e-3f);
    cc = fmaf(cc, z, 4.16666667e-2f);
    cc = fmaf(cc, z, -0.5f);
    cc = fmaf(cc, z, 1.0f);
    int qq = q & 3;
    float s_ = (qq & 1) ? cc : ss;
    float c_ = (qq & 1) ? ss : cc;
    if (qq == 1 || qq == 2) c_ = -c_;
    if (qq >= 2) s_ = -s_;
    *sp = s_; *cp = c_;
}

__device__ __forceinline__ float atan2_acc(float y, float x) {
    float ax = fabsf(x), ay = fabsf(y);
    float mx = fmaxf(ax, ay), mn = fminf(ax, ay);
    float t = (mx > 0.f) ? __fdiv_rn(mn, mx) : 0.f;
    float base = 0.f;
    if (t > 0.414213562f) { t = __fdiv_rn(t - 1.f, t + 1.f); base = 0.78539816339744831f; }
    float z = t * t;
    float p = -0.066666667f;
    p = fmaf(p, z,  0.076923077f);
    p = fmaf(p, z, -0.090909091f);
    p = fmaf(p, z,  0.111111111f);
    p = fmaf(p, z, -0.142857143f);
    p = fmaf(p, z,  0.2f);
    p = fmaf(p, z, -0.333333333f);
    float r = fmaf(t * z, p, t) + base;
    if (ay > ax) r = 1.57079632679489662f - r;
    if (x < 0.f) r = 3.14159265358979323f - r;
    return copysignf(r, y);
}

__global__ void twiddle_init() {
    int k = threadIdx.x;
    if (k < 129) {
        double a = -2.0 * 3.14159265358979323846 * (double)k / 256.0;
        float2 v = make_float2((float)cos(a), (float)sin(a));
        if (k == 0) v = make_float2(1.f, 0.f);
        g_tw[k] = v;
    }
}

// ---------------- FFT-256 (table = forward twiddles). sign=+1 fwd, -1 inv ----------------
__device__ __forceinline__ void fft256_tab(float2* s, const float2* tw, int t, float sign) {
#pragma unroll
    for (int kk = 0; kk < 2; kk++) {
        int i = t + (kk << 7);
        int j = __brev(i) >> 24;
        if (i < j) { float2 a = s[i]; s[i] = s[j]; s[j] = a; }
    }
    __syncthreads();
#pragma unroll
    for (int st = 1; st <= 8; st++) {
        int half = 1 << (st - 1);
        int g = t >> (st - 1);
        int p = t & (half - 1);
        int i0 = (g << st) + p;
        int i1 = i0 + half;
        float2 w = tw[p << (8 - st)];
        float wy = sign * w.y;
        float2 a = s[i0], b = s[i1];
        float2 wb = make_float2(w.x * b.x - wy * b.y, w.x * b.y + wy * b.x);
        s[i0] = make_float2(a.x + wb.x, a.y + wb.y);
        s[i1] = make_float2(a.x - wb.x, a.y - wb.y);
        __syncthreads();
    }
}

// ---- row forward rFFT, two real rows packed per complex FFT (exact) ----
__global__ void fft_row_fwd_pair(const float* __restrict__ x) {
    __shared__ float2 s[256];
    __shared__ float2 tw[128];
    int r = blockIdx.x & 127, bc = blockIdx.x >> 7, t = threadIdx.x;
    tw[t] = g_tw[t];
    const float* row0 = x + ((size_t)bc * 256 + 2 * r) * 256;
    const float* row1 = row0 + 256;
    s[t]       = make_float2(row0[t], row1[t]);
    s[t + 128] = make_float2(row0[t + 128], row1[t + 128]);
    __syncthreads();
    fft256_tab(s, tw, t, +1.f);
    size_t b0 = ((size_t)bc * 256 + 2 * r) * WF;
    size_t b1 = b0 + WF;
    float2 A = s[t];
    float2 Zr = s[(256 - t) & 255];
    g_XF[b0 + t] = make_float2(0.5f * (A.x + Zr.x), 0.5f * (A.y - Zr.y));
    g_XF[b1 + t] = make_float2(0.5f * (A.y + Zr.y), 0.5f * (Zr.x - A.x));
    if (t == 0) {
        float2 M = s[128];
        g_XF[b0 + 128] = make_float2(M.x, 0.f);
        g_XF[b1 + 128] = make_float2(M.y, 0.f);
    }
}

__global__ void fft_col_kernel(int dir) {
    __shared__ float2 S[16 * FPAD];
    __shared__ float2 tw[128];
    int k0 = blockIdx.x * 16;
    int c = blockIdx.y, b = blockIdx.z;
    int tid = threadIdx.x;
    if (tid < 128) tw[tid] = g_tw[tid];
    size_t base = ((size_t)(b * CC + c)) * HH * WF;

    for (int idx = tid; idx < 256 * 16; idx += 256) {
        int h = idx >> 4, kk = idx & 15;
        int k = k0 + kk;
        float2 v = (k < WF) ? g_XF[base + (size_t)h * WF + k] : make_float2(0.f, 0.f);
        S[kk * FPAD + h] = v;
    }
    __syncthreads();

    int f = tid >> 4;
    int l = tid & 15;
    float2* s = &S[f * FPAD];
#pragma unroll
    for (int m = 0; m < 16; m++) {
        int i = l + (m << 4);
        int j = __brev(i) >> 24;
        if (i < j) { float2 a = s[i]; s[i] = s[j]; s[j] = a; }
    }
    __syncthreads();
    float sign = dir ? -1.f : 1.f;
#pragma unroll
    for (int st = 1; st <= 8; st++) {
        int half = 1 << (st - 1);
#pragma unroll
        for (int m = 0; m < 8; m++) {
            int t = l + (m << 4);
            int g = t >> (st - 1);
            int p = t & (half - 1);
            int i0 = (g << st) + p;
            int i1 = i0 + half;
            float2 w = tw[p << (8 - st)];
            float wy = sign * w.y;
            float2 a = s[i0], bv = s[i1];
            float2 wb = make_float2(w.x * bv.x - wy * bv.y, w.x * bv.y + wy * bv.x);
            s[i0] = make_float2(a.x + wb.x, a.y + wb.y);
            s[i1] = make_float2(a.x - wb.x, a.y - wb.y);
        }
        __syncthreads();
    }

    if (dir == 0) {
        for (int idx = tid; idx < 256 * 16; idx += 256) {
            int h = idx >> 4, kk = idx & 15;
            int k = k0 + kk;
            if (k < WF) {
                float2 v = S[kk * FPAD + h];
                size_t o = base + (size_t)h * WF + k;
                g_amp[o] = __fsqrt_rn(fmaf(v.x, v.x, v.y * v.y));
                g_pha[o] = atan2_acc(v.y, v.x);
            }
        }
    } else {
        for (int idx = tid; idx < 256 * 16; idx += 256) {
            int h = idx >> 4, kk = idx & 15;
            int k = k0 + kk;
            if (k < WF) g_XF[base + (size_t)h * WF + k] = S[kk * FPAD + h];
        }
    }
}

// ---- row inverse rFFT, two rows per complex iFFT (drops Im at DC/Nyquist) ----
__global__ void ifft_row_pair() {
    __shared__ float2 s[256];
    __shared__ float2 tw[128];
    int r = blockIdx.x & 127, bc = blockIdx.x >> 7, t = threadIdx.x;
    tw[t] = g_tw[t];
    size_t b0 = ((size_t)bc * 256 + 2 * r) * WF;
    size_t b1 = b0 + WF;
    {
        float2 a1 = g_XF[b0 + t], a2 = g_XF[b1 + t];
        if (t == 0) {
            s[0] = make_float2(a1.x, a2.x);
            float2 m1 = g_XF[b0 + 128], m2 = g_XF[b1 + 128];
            s[128] = make_float2(m1.x, m2.x);
        } else {
            s[t] = make_float2(a1.x - a2.y, a1.y + a2.x);
            float2 c1 = g_XF[b0 + 128 - t], c2 = g_XF[b1 + 128 - t];
            s[t + 128] = make_float2(c1.x + c2.y, -c1.y + c2.x);
        }
    }
    __syncthreads();
    fft256_tab(s, tw, t, -1.f);
    const float inv = 1.f / 65536.f;
    float* orow0 = g_xr + ((size_t)bc * 256 + 2 * r) * 256;
    float* orow1 = orow0 + 256;
    orow0[t]       = fabsf(s[t].x * inv);
    orow0[t + 128] = fabsf(s[t + 128].x * inv);
    orow1[t]       = fabsf(s[t].y * inv);
    orow1[t + 128] = fabsf(s[t + 128].y * inv);
}

// ------- merged 3x3 pad-1 conv 64->18, register-prefetch pipeline (R11 variant, measured best) -------
__global__ void __launch_bounds__(256, 3)
conv_off_kernel(const float* __restrict__ wp_a, const float* __restrict__ bp_a,
                const float* __restrict__ wp_p, const float* __restrict__ bp_p) {
    __shared__ float TT[612];      // 34 rows x 18 cols
    __shared__ float WS[180];      // 9 taps x 20 (padded for float4 reads)
    int w0b = blockIdx.x * 16, h0 = blockIdx.y * 32;
    int bz = blockIdx.z;
    int f = bz & 1, b = bz >> 1;
    const float* src = f ? g_pha : g_amp;
    const float* wp = f ? wp_p : wp_a;
    const float* bp = f ? bp_p : bp_a;
    int tid = threadIdx.x;
    int tx = tid & 15, ty = tid >> 4;

    int i0 = tid, i1 = tid + 256, i2 = tid + 512;
    bool v0, v1, v2;
    int o0, o1, o2;
    {
        int r, cc, gh, gw;
        r = i0 / 18; cc = i0 - r * 18; gh = h0 + r - 1; gw = w0b + cc - 1;
        v0 = (gh >= 0 && gh < HH && gw >= 0 && gw < WF); o0 = gh * WF + gw;
        r = i1 / 18; cc = i1 - r * 18; gh = h0 + r - 1; gw = w0b + cc - 1;
        v1 = (gh >= 0 && gh < HH && gw >= 0 && gw < WF); o1 = gh * WF + gw;
        r = i2 / 18; cc = i2 - r * 18; gh = h0 + r - 1; gw = w0b + cc - 1;
        v2 = (i2 < 612) && (gh >= 0 && gh < HH && gw >= 0 && gw < WF); o2 = gh * WF + gw;
    }
    bool wq = tid < 162;
    int wk = tid / 18, wo = tid % 18;
    int wslot = wk * 20 + wo;
    int wbase = wo * CC * 9 + wk;     // + ic*9

    const float* P = src + (size_t)b * CC * HWF;
    float rA = v0 ? __ldg(P + o0) : 0.f;
    float rB = v1 ? __ldg(P + o1) : 0.f;
    float rC = v2 ? __ldg(P + o2) : 0.f;
    float rW = wq ? __ldg(wp + wbase) : 0.f;

    u64 acc0[9], acc1[9];
#pragma unroll
    for (int j = 0; j < 9; j++) { acc0[j] = pack2(0.f, 0.f); acc1[j] = pack2(0.f, 0.f); }

    for (int ic = 0; ic < CC; ic++) {
        __syncthreads();
        TT[i0] = rA;
        TT[i1] = rB;
        if (i2 < 612) TT[i2] = rC;
        if (wq) WS[wslot] = rW;
        if (ic < CC - 1) {
            const float* Pn = P + (size_t)(ic + 1) * HWF;
            rA = v0 ? __ldg(Pn + o0) : 0.f;
            rB = v1 ? __ldg(Pn + o1) : 0.f;
            rC = v2 ? __ldg(Pn + o2) : 0.f;
            rW = wq ? __ldg(wp + wbase + (ic + 1) * 9) : 0.f;
        }
        __syncthreads();
#pragma unroll
        for (int k = 0; k < 9; k++) {
            int ky = k / 3, kx = k % 3;
            float va = TT[(2 * ty + ky) * 18 + tx + kx];
            float vb = TT[(2 * ty + 1 + ky) * 18 + tx + kx];
            u64 V0 = pack2(va, va);
            u64 V1 = pack2(vb, vb);
            const float* Wr = &WS[k * 20];
            float4 q0 = *reinterpret_cast<const float4*>(Wr);
            float4 q1 = *reinterpret_cast<const float4*>(Wr + 4);
            float4 q2 = *reinterpret_cast<const float4*>(Wr + 8);
            float4 q3 = *reinterpret_cast<const float4*>(Wr + 12);
            u64 w8 = *reinterpret_cast<const u64*>(Wr + 16);
            u64 Wv[9] = { pack2(q0.x, q0.y), pack2(q0.z, q0.w),
                          pack2(q1.x, q1.y), pack2(q1.z, q1.w),
                          pack2(q2.x, q2.y), pack2(q2.z, q2.w),
                          pack2(q3.x, q3.y), pack2(q3.z, q3.w), w8 };
#pragma unroll
            for (int j = 0; j < 9; j++) {
                fma2(acc0[j], Wv[j], V0);
                fma2(acc1[j], Wv[j], V1);
            }
        }
    }
    int h = h0 + 2 * ty, w = w0b + tx;
    if (w < WF) {
#pragma unroll
        for (int j = 0; j < 9; j++) {
            float lo0, hi0, lo1, hi1;
            unpack2(acc0[j], lo0, hi0);
            unpack2(acc1[j], lo1, hi1);
            float blo = bp[2 * j], bhi = bp[2 * j + 1];
            size_t base = (size_t)((f * BB + b) * 18);
            g_offs[((base + 2 * j    ) * HH + h) * WF + w]     = lo0 + blo;
            g_offs[((base + 2 * j + 1) * HH + h) * WF + w]     = hi0 + bhi;
            g_offs[((base + 2 * j    ) * HH + h + 1) * WF + w] = lo1 + blo;
            g_offs[((base + 2 * j + 1) * HH + h + 1) * WF + w] = hi1 + bhi;
        }
    }
}

// ---------------- fused sampling-params + gather ----------------
__device__ __forceinline__ int padidx(float qx, float qy) {
    int X = (int)qx, Y = (int)qy;
    if (X >= 1 && X <= 256 && Y >= 1 && Y <= 129) return (X - 1) * WF + (Y - 1);
    return -1;
}

__global__ void gather_kernel() {
    int t = blockIdx.x * 256 + threadIdx.x;
    if (t >= NP) return;
    int f = blockIdx.y;
    int w = t % WF;
    int r = t / WF;
    int h = r % HH;
    int b = r / HH;

    const float* Pb = (f ? g_pha : g_amp) + (size_t)b * CC * HWF;
    float* Sbase = g_S + (size_t)f * SBR + ((size_t)b * CC * 9) * HWF + (size_t)h * WF + w;
    size_t obase = (size_t)((f * BB + b) * 18);
    const float HMax = 257.f, WMax = 130.f;

#pragma unroll
    for (int n = 0; n < 9; n++) {
        int i = n / 3, j = n % 3;
        float offx = g_offs[((obase + n    ) * HH + h) * WF + w];
        float offy = g_offs[((obase + n + 9) * HH + h) * WF + w];
        float px = (float)(h + 1) + (float)(i - 1) + offx;
        float py = (float)(w + 1) + (float)(j - 1) + offy;
        float qx = floorf(px), qy = floorf(py);
        float qltx = fminf(fmaxf(qx, 0.f), HMax);
        float qlty = fminf(fmaxf(qy, 0.f), WMax);
        float qrbx = fminf(fmaxf(qx + 1.f, 0.f), HMax);
        float qrby = fminf(fmaxf(qy + 1.f, 0.f), WMax);
        float cpx  = fminf(fmaxf(px, 0.f), HMax);
        float cpy  = fminf(fmaxf(py, 0.f), WMax);
        float glt = (1.f + (qltx - cpx)) * (1.f + (qlty - cpy));
        float grb = (1.f - (qrbx - cpx)) * (1.f - (qrby - cpy));
        float glb = (1.f + (qltx - cpx)) * (1.f - (qrby - cpy));
        float grt = (1.f - (qrbx - cpx)) * (1.f + (qlty - cpy));
        int ilt = padidx(qltx, qlty);
        int irb = padidx(qrbx, qrby);
        int ilb = padidx(qltx, qrby);
        int irt = padidx(qrbx, qlty);
        float* Sn = Sbase + (size_t)n * HWF;
#pragma unroll 4
        for (int c = 0; c < CC; c++) {
            const float* P = Pb + (size_t)c * HWF;
            float v = 0.f;
            if (ilt >= 0) v += glt * __ldg(P + ilt);
            if (irb >= 0) v += grb * __ldg(P + irb);
            if (ilb >= 0) v += glb * __ldg(P + ilb);
            if (irt >= 0) v += grt * __ldg(P + irt);
            Sn[(size_t)c * 9 * HWF] = v;
        }
    }
}

// ------- deform conv (merged): cp.async double-buffered, u64 weight loads (R9 inner loop) -------
__global__ void conv_s3_kernel(const float* __restrict__ wc_a, const float* __restrict__ wc_p) {
    __shared__ float SS[2][5346];    // 9 planes x 33 x 18
    __shared__ float WSS[2][288];
    int w0 = blockIdx.x * 16, h0 = blockIdx.y * 32;
    int bz = blockIdx.z;
    int og = bz & 1;
    int f = (bz >> 1) & 1;
    int b = bz >> 2;
    const float* wc = f ? wc_p : wc_a;
    int tid = threadIdx.x;
    int tx = tid & 15, ty = tid >> 4;
    u64 acc0[16], acc1[16];
#pragma unroll
    for (int j = 0; j < 16; j++) { acc0[j] = pack2(0.f, 0.f); acc1[j] = pack2(0.f, 0.f); }

    const int ni[3] = {2, 0, 1};
    const int dd[3] = {-1, 0, 0};
    const float* Sbr = g_S + (size_t)f * SBR + ((size_t)b * CC * 9) * HWF;

    int poff[3]; bool ppred[3];
#pragma unroll
    for (int u = 0; u < 3; u++) {
        int idx2 = tid + (u << 8);
        int rr = idx2 / 18, cc = idx2 - rr * 18;
        int gh = h0 - 1 + rr, gw = w0 - 1 + cc;
        ppred[u] = (idx2 < 594) && (gh >= 0 && gh < HH && gw >= 0 && gw < WF);
        poff[u] = gh * WF + gw;
    }
    int wo0 = ((og * 32 + (tid & 31)) * CC) * 9 + (tid >> 5);
    int idxw1 = tid + 256;
    int wo1 = ((og * 32 + (idxw1 & 31)) * CC) * 9 + (idxw1 >> 5);
    bool wp1 = idxw1 < 288;

    uint32_t tb[2], wb2[2];
    tb[0] = (uint32_t)__cvta_generic_to_shared(&SS[0][0]);
    tb[1] = (uint32_t)__cvta_generic_to_shared(&SS[1][0]);
    wb2[0] = (uint32_t)__cvta_generic_to_shared(&WSS[0][0]);
    wb2[1] = (uint32_t)__cvta_generic_to_shared(&WSS[1][0]);

    auto load_stage = [&](int ic, int bufi) {
        const float* Sb = Sbr + (size_t)ic * 9 * HWF;
#pragma unroll
        for (int n = 0; n < 9; n++) {
            const float* Pn = Sb + (size_t)n * HWF;
            uint32_t dbs = tb[bufi] + 4u * (n * 594);
#pragma unroll
            for (int u = 0; u < 3; u++) {
                int idx2 = tid + (u << 8);
                if (idx2 < 594) cpa4(dbs + 4u * idx2, Pn + poff[u], ppred[u]);
            }
        }
        cpa4(wb2[bufi] + 4u * tid, wc + wo0 + ic * 9, true);
        if (wp1) cpa4(wb2[bufi] + 4u * idxw1, wc + wo1 + ic * 9, true);
    };

    load_stage(0, 0);
    CP_COMMIT();

    for (int ic = 0; ic < CC; ic++) {
        int cur = ic & 1;
        if (ic + 1 < CC) {
            load_stage(ic + 1, cur ^ 1);
            CP_COMMIT();
            CP_WAIT1();
        } else {
            CP_WAIT0();
        }
        __syncthreads();
        const float* Sc = &SS[cur][0];
        const float* Wc = &WSS[cur][0];
#pragma unroll
        for (int rr = 0; rr < 3; rr++) {
#pragma unroll
            for (int c3 = 0; c3 < 3; c3++) {
                int n = ni[rr] * 3 + ni[c3];
                int row = 2 * ty + 1 + dd[rr];
                int col = tx + 1 + dd[c3];
                float v0 = Sc[n * 594 + row * 18 + col];
                float v1 = Sc[n * 594 + (row + 1) * 18 + col];
                u64 V0 = pack2(v0, v0);
                u64 V1 = pack2(v1, v1);
                int k = rr * 3 + c3;
#pragma unroll
                for (int j = 0; j < 16; j++) {
                    u64 Wv = *reinterpret_cast<const u64*>(&Wc[k * 32 + 2 * j]);
                    fma2(acc0[j], Wv, V0);
                    fma2(acc1[j], Wv, V1);
                }
            }
        }
        __syncthreads();
    }
    int oh = h0 + 2 * ty, ow = w0 + tx;
    if (ow < WF) {
        float* dst = f ? g_p3 : g_a3;
#pragma unroll
        for (int j = 0; j < 16; j++) {
            float lo0, hi0, lo1, hi1;
            unpack2(acc0[j], lo0, hi0);
            unpack2(acc1[j], lo1, hi1);
            int oc = og * 32 + 2 * j;
            dst[((size_t)(b * CC + oc    ) * HH + oh) * WF + ow]     = lo0;
            dst[((size_t)(b * CC + oc + 1) * HH + oh) * WF + ow]     = hi0;
            dst[((size_t)(b * CC + oc    ) * HH + oh + 1) * WF + ow] = lo1;
            dst[((size_t)(b * CC + oc + 1) * HH + oh + 1) * WF + ow] = hi1;
        }
    }
}

// ---------------- fused conv1x1(both branches) + combine ----------------
extern __shared__ float dynC[];
__global__ void combine1x1_kernel(const float* __restrict__ w1_a, const float* __restrict__ b1_a,
                                  const float* __restrict__ w1_p, const float* __restrict__ b1_p) {
    float* XSa = dynC;
    float* XSp = XSa + 64 * 33;
    float* WTa = XSp + 64 * 33;
    float* WTp = WTa + 64 * 64;
    int p0 = blockIdx.x * 32;
    int b = blockIdx.y;
    int tid = threadIdx.x;
    const float* sa = g_amp + (size_t)b * CC * HWF;
    const float* sp = g_pha + (size_t)b * CC * HWF;
    for (int idx = tid; idx < 2048; idx += 256) {
        int c = idx >> 5, p = idx & 31;
        XSa[c * 33 + p] = sa[(size_t)c * HWF + p0 + p];
        XSp[c * 33 + p] = sp[(size_t)c * HWF + p0 + p];
    }
    for (int idx = tid; idx < 4096; idx += 256) {
        int oc = idx >> 6, k = idx & 63;
        WTa[k * 64 + oc] = w1_a[idx];
        WTp[k * 64 + oc] = w1_p[idx];
    }
    __syncthreads();
    int px = tid & 31, ocg = tid >> 5;
    float a1acc[8] = {0.f, 0.f, 0.f, 0.f, 0.f, 0.f, 0.f, 0.f};
    float p1acc[8] = {0.f, 0.f, 0.f, 0.f, 0.f, 0.f, 0.f, 0.f};
    for (int k = 0; k < 64; k++) {
        float xa = XSa[k * 33 + px];
        float xp = XSp[k * 33 + px];
#pragma unroll
        for (int j = 0; j < 8; j++) {
            a1acc[j] = fmaf(WTa[k * 64 + ocg + 8 * j], xa, a1acc[j]);
            p1acc[j] = fmaf(WTp[k * 64 + ocg + 8 * j], xp, p1acc[j]);
        }
    }
#pragma unroll
    for (int j = 0; j < 8; j++) {
        int oc = ocg + 8 * j;
        float a1 = a1acc[j] + b1_a[oc];
        float p1 = p1acc[j] + b1_p[oc];
        size_t o = (size_t)(b * CC + oc) * HWF + p0 + px;
        float a3 = g_a3[o], p3 = g_p3[o];
        float s1, c1, s3, c3;
        sincos_acc(p1, &s1, &c1);
        sincos_acc(p3, &s3, &c3);
        g_XF[o] = make_float2(a1 * c3 + a3 * c1 + 3e-8f,
                              a3 * s1 + a1 * s3 + 2e-8f);
    }
}

// ------- final 5x5 conv: cp.async double-buffered, u64 weight loads (R9 inner loop) -------
extern __shared__ float dyn5[];
__global__ void conv5x5_kernel(const float* __restrict__ w0, const float* __restrict__ b0,
                               float* __restrict__ out) {
    float* T0 = dyn5;                      // 8 x 1332
    float* T1 = T0 + 8 * 1332;
    float* W0b = T1 + 8 * 1332;            // 3200
    float* W1b = W0b + 3200;
    int w0b = blockIdx.x * 32, h0 = blockIdx.y * 32;
    int bz = blockIdx.z;
    int og = bz & 3;
    int b = bz >> 2;
    int tid = threadIdx.x;
    int tx = tid & 15, ty = tid >> 4;
    u64 acc00[8], acc01[8], acc10[8], acc11[8];
#pragma unroll
    for (int j = 0; j < 8; j++) {
        acc00[j] = pack2(0.f, 0.f); acc01[j] = pack2(0.f, 0.f);
        acc10[j] = pack2(0.f, 0.f); acc11[j] = pack2(0.f, 0.f);
    }

    int poff[6], pdst[6]; bool ppred[6];
#pragma unroll
    for (int u = 0; u < 6; u++) {
        int idx2 = tid + (u << 8);
        int rr = idx2 / 36, cc = idx2 - rr * 36;
        int gh = h0 + rr - 2, gw = w0b + cc - 2;
        ppred[u] = (idx2 < 1296) && (gh >= 0 && gh < HH && gw >= 0 && gw < WW);
        poff[u] = gh * WW + gw;
        pdst[u] = rr * 37 + cc;
    }
    int wk0 = tid / 16, wo0 = tid % 16;
    int idxw1 = tid + 256;
    int wk1 = idxw1 / 16, wo1 = idxw1 % 16;
    bool wpq1 = idxw1 < 400;
    int wbase0 = ((og * 16 + wo0) * CC) * 25 + wk0;
    int wbase1 = ((og * 16 + wo1) * CC) * 25 + wk1;

    const float* Pb = g_xr + (size_t)(b * CC) * HH * WW;
    uint32_t tb[2], wb2[2];
    tb[0] = (uint32_t)__cvta_generic_to_shared(T0);
    tb[1] = (uint32_t)__cvta_generic_to_shared(T1);
    wb2[0] = (uint32_t)__cvta_generic_to_shared(W0b);
    wb2[1] = (uint32_t)__cvta_generic_to_shared(W1b);

    auto load_stage = [&](int ic0, int bufi) {
#pragma unroll
        for (int ii = 0; ii < 8; ii++) {
            const float* Pn = Pb + (size_t)(ic0 + ii) * HH * WW;
            uint32_t dbs = tb[bufi] + 4u * (ii * 1332);
#pragma unroll
            for (int u = 0; u < 6; u++) {
                int idx2 = tid + (u << 8);
                if (idx2 < 1296) cpa4(dbs + 4u * pdst[u], Pn + poff[u], ppred[u]);
            }
            uint32_t wdbs = wb2[bufi] + 4u * (ii * 400);
            cpa4(wdbs + 4u * tid, w0 + wbase0 + (ic0 + ii) * 25, true);
            if (wpq1) cpa4(wdbs + 4u * idxw1, w0 + wbase1 + (ic0 + ii) * 25, true);
        }
    };

    load_stage(0, 0);
    CP_COMMIT();

    for (int s = 0; s < 8; s++) {
        int cur = s & 1;
        if (s + 1 < 8) {
            load_stage((s + 1) * 8, cur ^ 1);
            CP_COMMIT();
            CP_WAIT1();
        } else {
            CP_WAIT0();
        }
        __syncthreads();
        const float* Tc = cur ? T1 : T0;
        const float* Wc = cur ? W1b : W0b;
#pragma unroll
        for (int ii = 0; ii < 8; ii++) {
            const float* Tb = &Tc[ii * 1332];
            const float* Wb = &Wc[ii * 400];
#pragma unroll
            for (int k = 0; k < 25; k++) {
                int ky = k / 5, kx = k % 5;
                const float* row0 = Tb + (2 * ty + ky) * 37 + 2 * tx + kx;
                float v00 = row0[0];
                float v01 = row0[1];
                float v10 = row0[37];
                float v11 = row0[38];
                u64 V00 = pack2(v00, v00);
                u64 V01 = pack2(v01, v01);
                u64 V10 = pack2(v10, v10);
                u64 V11 = pack2(v11, v11);
#pragma unroll
                for (int j = 0; j < 8; j++) {
                    u64 Wv = *reinterpret_cast<const u64*>(&Wb[k * 16 + 2 * j]);
                    fma2(acc00[j], Wv, V00);
                    fma2(acc01[j], Wv, V01);
                    fma2(acc10[j], Wv, V10);
                    fma2(acc11[j], Wv, V11);
                }
            }
        }
        __syncthreads();
    }
    int h = h0 + 2 * ty, w = w0b + 2 * tx;
#pragma unroll
    for (int j = 0; j < 8; j++) {
        int oc = og * 16 + 2 * j;
        float l00, h00, l01, h01, l10, h10, l11, h11;
        unpack2(acc00[j], l00, h00);
        unpack2(acc01[j], l01, h01);
        unpack2(acc10[j], l10, h10);
        unpack2(acc11[j], l11, h11);
        float blo = b0[oc], bhi = b0[oc + 1];
        float* o0 = out + ((size_t)(b * CC + oc) * HH + h) * WW + w;
        float* o1 = out + ((size_t)(b * CC + oc + 1) * HH + h) * WW + w;
        o0[0] = l00 + blo;  o0[1] = l01 + blo;
        o0[WW] = l10 + blo; o0[WW + 1] = l11 + blo;
        o1[0] = h00 + bhi;  o1[1] = h01 + bhi;
        o1[WW] = h10 + bhi; o1[WW + 1] = h11 + bhi;
    }
}

// ---------------- launcher ----------------
extern "C" void kernel_launch(void* const* d_in, const int* in_sizes, int n_in,
                              void* d_out, int out_size) {
    (void)in_sizes; (void)n_in; (void)out_size;
    const float* x    = (const float*)d_in[0];
    const float* wp_a = (const float*)d_in[1];
    const float* bp_a = (const float*)d_in[2];
    const float* wc_a = (const float*)d_in[3];
    const float* w1_a = (const float*)d_in[4];
    const float* b1_a = (const float*)d_in[5];
    const float* wp_p = (const float*)d_in[6];
    const float* bp_p = (const float*)d_in[7];
    const float* wc_p = (const float*)d_in[8];
    const float* w1_p = (const float*)d_in[9];
    const float* b1_p = (const float*)d_in[10];
    const float* w0   = (const float*)d_in[11];
    const float* b0   = (const float*)d_in[12];
    float* out = (float*)d_out;

    static int attr_done = 0;
    if (!attr_done) {
        cudaFuncSetAttribute(combine1x1_kernel, cudaFuncAttributeMaxDynamicSharedMemorySize, 49664);
        cudaFuncSetAttribute(conv5x5_kernel, cudaFuncAttributeMaxDynamicSharedMemorySize, 110848);
        attr_done = 1;
    }

    twiddle_init<<<1, 129>>>();

    fft_row_fwd_pair<<<BB * CC * 128, 128>>>(x);
    fft_col_kernel<<<dim3(9, CC, BB), 256>>>(0);

    // merged amp+pha deform pipeline
    conv_off_kernel<<<dim3(9, 8, BB * 2), 256>>>(wp_a, bp_a, wp_p, bp_p);
    gather_kernel<<<dim3(NP / 256, 2), 256>>>();
    conv_s3_kernel<<<dim3(9, 8, BB * 4), 256>>>(wc_a, wc_p);

    // fused 1x1 conv + recombine, then inverse transform
    combine1x1_kernel<<<dim3(HWF / 32, BB), 256, 49664>>>(w1_a, b1_a, w1_p, b1_p);
    fft_col_kernel<<<dim3(9, CC, BB), 256>>>(1);
    ifft_row_pair<<<BB * CC * 128, 128>>>();

    conv5x5_kernel<<<dim3(8, 8, BB * 4), 256, 110848>>>(w0, b0, out);
}

// round 13
// speedup vs baseline: 1.1982x; 1.0303x over previous
#include <cuda_runtime.h>
#include <stdint.h>
#include <math.h>

#define BB 4
#define CC 64
#define HH 256
#define WW 256
#define WF 129
#define HWF (HH*WF)            // 33024
#define NPIX (BB*CC*HWF)       // 8454144
#define NP (BB*HWF)            // 132096
#define FPAD 261

// ---------------- scratch (branch axis f: 0=amp, 1=pha) ----------------
__device__ float2 g_XF[NPIX];
__device__ float  g_amp[NPIX];
__device__ float  g_pha[NPIX];
__device__ float  g_a3[NPIX];
__device__ float  g_p3[NPIX];
__device__ float  g_offs[2*BB*18*HWF];
__device__ float  g_S[(size_t)2*BB*CC*9*HWF];   // sample planes [f][b][c][n][h][w]
__device__ float  g_xr[(size_t)BB*CC*HH*WW];
__device__ float2 g_tw[129];

#define SBR ((size_t)BB*CC*9*HWF)

// ---------------- packed f32x2 helpers ----------------
typedef unsigned long long u64;
__device__ __forceinline__ u64 pack2(float lo, float hi) {
    u64 r; asm("mov.b64 %0, {%1, %2};" : "=l"(r) : "f"(lo), "f"(hi)); return r;
}
__device__ __forceinline__ void unpack2(u64 v, float& lo, float& hi) {
    asm("mov.b64 {%0, %1}, %2;" : "=f"(lo), "=f"(hi) : "l"(v));
}
__device__ __forceinline__ void fma2(u64& d, u64 a, u64 b) {
    asm("fma.rn.f32x2 %0, %1, %2, %0;" : "+l"(d) : "l"(a), "l"(b));
}

// ---------------- cp.async helpers ----------------
__device__ __forceinline__ void cpa4(uint32_t dst, const float* src, bool pred) {
    int sz = pred ? 4 : 0;
    asm volatile("cp.async.ca.shared.global [%0], [%1], 4, %2;" :: "r"(dst), "l"(src), "r"(sz));
}
#define CP_COMMIT() asm volatile("cp.async.commit_group;" ::: "memory")
#define CP_WAIT1()  asm volatile("cp.async.wait_group 1;" ::: "memory")
#define CP_WAIT0()  asm volatile("cp.async.wait_group 0;" ::: "memory")

// ---------------- precise transcendentals ----------------
__device__ __forceinline__ void sincos_acc(float x, float* sp, float* cp) {
    float k = rintf(x * 0.63661977236758134f);
    float r = fmaf(k, -1.5707963705062866f, x);
    r = fmaf(k, 4.37113900018624e-8f, r);
    int q = (int)k;
    float z = r * r;
    float ss = 2.75573192e-6f;
    ss = fmaf(ss, z, -1.98412698e-4f);
    ss = fmaf(ss, z, 8.33333333e-3f);
    ss = fmaf(ss, z, -1.66666667e-1f);
    ss = fmaf(ss * z, r, r);
    float cc = -2.75573192e-7f;
    cc = fmaf(cc, z, 2.48015873e-5f);
    cc = fmaf(cc, z, -1.38888889e-3f);
    cc = fmaf(cc, z, 4.16666667e-2f);
    cc = fmaf(cc, z, -0.5f);
    cc = fmaf(cc, z, 1.0f);
    int qq = q & 3;
    float s_ = (qq & 1) ? cc : ss;
    float c_ = (qq & 1) ? ss : cc;
    if (qq == 1 || qq == 2) c_ = -c_;
    if (qq >= 2) s_ = -s_;
    *sp = s_; *cp = c_;
}

__device__ __forceinline__ float atan2_acc(float y, float x) {
    float ax = fabsf(x), ay = fabsf(y);
    float mx = fmaxf(ax, ay), mn = fminf(ax, ay);
    float t = (mx > 0.f) ? __fdiv_rn(mn, mx) : 0.f;
    float base = 0.f;
    if (t > 0.414213562f) { t = __fdiv_rn(t - 1.f, t + 1.f); base = 0.78539816339744831f; }
    float z = t * t;
    float p = -0.066666667f;
    p = fmaf(p, z,  0.076923077f);
    p = fmaf(p, z, -0.090909091f);
    p = fmaf(p, z,  0.111111111f);
    p = fmaf(p, z, -0.142857143f);
    p = fmaf(p, z,  0.2f);
    p = fmaf(p, z, -0.333333333f);
    float r = fmaf(t * z, p, t) + base;
    if (ay > ax) r = 1.57079632679489662f - r;
    if (x < 0.f) r = 3.14159265358979323f - r;
    return copysignf(r, y);
}

__global__ void twiddle_init() {
    int k = threadIdx.x;
    if (k < 129) {
        double a = -2.0 * 3.14159265358979323846 * (double)k / 256.0;
        float2 v = make_float2((float)cos(a), (float)sin(a));
        if (k == 0) v = make_float2(1.f, 0.f);
        g_tw[k] = v;
    }
}

// ---------------- FFT-256 (table = forward twiddles). sign=+1 fwd, -1 inv ----------------
__device__ __forceinline__ void fft256_tab(float2* s, const float2* tw, int t, float sign) {
#pragma unroll
    for (int kk = 0; kk < 2; kk++) {
        int i = t + (kk << 7);
        int j = __brev(i) >> 24;
        if (i < j) { float2 a = s[i]; s[i] = s[j]; s[j] = a; }
    }
    __syncthreads();
#pragma unroll
    for (int st = 1; st <= 8; st++) {
        int half = 1 << (st - 1);
        int g = t >> (st - 1);
        int p = t & (half - 1);
        int i0 = (g << st) + p;
        int i1 = i0 + half;
        float2 w = tw[p << (8 - st)];
        float wy = sign * w.y;
        float2 a = s[i0], b = s[i1];
        float2 wb = make_float2(w.x * b.x - wy * b.y, w.x * b.y + wy * b.x);
        s[i0] = make_float2(a.x + wb.x, a.y + wb.y);
        s[i1] = make_float2(a.x - wb.x, a.y - wb.y);
        __syncthreads();
    }
}

// ---- row forward rFFT, two real rows packed per complex FFT (exact) ----
__global__ void fft_row_fwd_pair(const float* __restrict__ x) {
    __shared__ float2 s[256];
    __shared__ float2 tw[128];
    int r = blockIdx.x & 127, bc = blockIdx.x >> 7, t = threadIdx.x;
    tw[t] = g_tw[t];
    const float* row0 = x + ((size_t)bc * 256 + 2 * r) * 256;
    const float* row1 = row0 + 256;
    s[t]       = make_float2(row0[t], row1[t]);
    s[t + 128] = make_float2(row0[t + 128], row1[t + 128]);
    __syncthreads();
    fft256_tab(s, tw, t, +1.f);
    size_t b0 = ((size_t)bc * 256 + 2 * r) * WF;
    size_t b1 = b0 + WF;
    float2 A = s[t];
    float2 Zr = s[(256 - t) & 255];
    g_XF[b0 + t] = make_float2(0.5f * (A.x + Zr.x), 0.5f * (A.y - Zr.y));
    g_XF[b1 + t] = make_float2(0.5f * (A.y + Zr.y), 0.5f * (Zr.x - A.x));
    if (t == 0) {
        float2 M = s[128];
        g_XF[b0 + 128] = make_float2(M.x, 0.f);
        g_XF[b1 + 128] = make_float2(M.y, 0.f);
    }
}

__global__ void fft_col_kernel(int dir) {
    __shared__ float2 S[16 * FPAD];
    __shared__ float2 tw[128];
    int k0 = blockIdx.x * 16;
    int c = blockIdx.y, b = blockIdx.z;
    int tid = threadIdx.x;
    if (tid < 128) tw[tid] = g_tw[tid];
    size_t base = ((size_t)(b * CC + c)) * HH * WF;

    for (int idx = tid; idx < 256 * 16; idx += 256) {
        int h = idx >> 4, kk = idx & 15;
        int k = k0 + kk;
        float2 v = (k < WF) ? g_XF[base + (size_t)h * WF + k] : make_float2(0.f, 0.f);
        S[kk * FPAD + h] = v;
    }
    __syncthreads();

    int f = tid >> 4;
    int l = tid & 15;
    float2* s = &S[f * FPAD];
#pragma unroll
    for (int m = 0; m < 16; m++) {
        int i = l + (m << 4);
        int j = __brev(i) >> 24;
        if (i < j) { float2 a = s[i]; s[i] = s[j]; s[j] = a; }
    }
    __syncthreads();
    float sign = dir ? -1.f : 1.f;
#pragma unroll
    for (int st = 1; st <= 8; st++) {
        int half = 1 << (st - 1);
#pragma unroll
        for (int m = 0; m < 8; m++) {
            int t = l + (m << 4);
            int g = t >> (st - 1);
            int p = t & (half - 1);
            int i0 = (g << st) + p;
            int i1 = i0 + half;
            float2 w = tw[p << (8 - st)];
            float wy = sign * w.y;
            float2 a = s[i0], bv = s[i1];
            float2 wb = make_float2(w.x * bv.x - wy * bv.y, w.x * bv.y + wy * bv.x);
            s[i0] = make_float2(a.x + wb.x, a.y + wb.y);
            s[i1] = make_float2(a.x - wb.x, a.y - wb.y);
        }
        __syncthreads();
    }

    if (dir == 0) {
        for (int idx = tid; idx < 256 * 16; idx += 256) {
            int h = idx >> 4, kk = idx & 15;
            int k = k0 + kk;
            if (k < WF) {
                float2 v = S[kk * FPAD + h];
                size_t o = base + (size_t)h * WF + k;
                g_amp[o] = __fsqrt_rn(fmaf(v.x, v.x, v.y * v.y));
                g_pha[o] = atan2_acc(v.y, v.x);
            }
        }
    } else {
        for (int idx = tid; idx < 256 * 16; idx += 256) {
            int h = idx >> 4, kk = idx & 15;
            int k = k0 + kk;
            if (k < WF) g_XF[base + (size_t)h * WF + k] = S[kk * FPAD + h];
        }
    }
}

// ---- row inverse rFFT, two rows per complex iFFT (drops Im at DC/Nyquist) ----
__global__ void ifft_row_pair() {
    __shared__ float2 s[256];
    __shared__ float2 tw[128];
    int r = blockIdx.x & 127, bc = blockIdx.x >> 7, t = threadIdx.x;
    tw[t] = g_tw[t];
    size_t b0 = ((size_t)bc * 256 + 2 * r) * WF;
    size_t b1 = b0 + WF;
    {
        float2 a1 = g_XF[b0 + t], a2 = g_XF[b1 + t];
        if (t == 0) {
            s[0] = make_float2(a1.x, a2.x);
            float2 m1 = g_XF[b0 + 128], m2 = g_XF[b1 + 128];
            s[128] = make_float2(m1.x, m2.x);
        } else {
            s[t] = make_float2(a1.x - a2.y, a1.y + a2.x);
            float2 c1 = g_XF[b0 + 128 - t], c2 = g_XF[b1 + 128 - t];
            s[t + 128] = make_float2(c1.x + c2.y, -c1.y + c2.x);
        }
    }
    __syncthreads();
    fft256_tab(s, tw, t, -1.f);
    const float inv = 1.f / 65536.f;
    float* orow0 = g_xr + ((size_t)bc * 256 + 2 * r) * 256;
    float* orow1 = orow0 + 256;
    orow0[t]       = fabsf(s[t].x * inv);
    orow0[t + 128] = fabsf(s[t + 128].x * inv);
    orow1[t]       = fabsf(s[t].y * inv);
    orow1[t + 128] = fabsf(s[t + 128].y * inv);
}

// ------- merged 3x3 pad-1 conv 64->18, register-prefetch pipeline -------
__global__ void __launch_bounds__(256, 3)
conv_off_kernel(const float* __restrict__ wp_a, const float* __restrict__ bp_a,
                const float* __restrict__ wp_p, const float* __restrict__ bp_p) {
    __shared__ float TT[612];      // 34 rows x 18 cols
    __shared__ float WS[180];      // 9 taps x 20
    int w0b = blockIdx.x * 16, h0 = blockIdx.y * 32;
    int bz = blockIdx.z;
    int f = bz & 1, b = bz >> 1;
    const float* src = f ? g_pha : g_amp;
    const float* wp = f ? wp_p : wp_a;
    const float* bp = f ? bp_p : bp_a;
    int tid = threadIdx.x;
    int tx = tid & 15, ty = tid >> 4;

    int i0 = tid, i1 = tid + 256, i2 = tid + 512;
    bool v0, v1, v2;
    int o0, o1, o2;
    {
        int r, cc, gh, gw;
        r = i0 / 18; cc = i0 - r * 18; gh = h0 + r - 1; gw = w0b + cc - 1;
        v0 = (gh >= 0 && gh < HH && gw >= 0 && gw < WF); o0 = gh * WF + gw;
        r = i1 / 18; cc = i1 - r * 18; gh = h0 + r - 1; gw = w0b + cc - 1;
        v1 = (gh >= 0 && gh < HH && gw >= 0 && gw < WF); o1 = gh * WF + gw;
        r = i2 / 18; cc = i2 - r * 18; gh = h0 + r - 1; gw = w0b + cc - 1;
        v2 = (i2 < 612) && (gh >= 0 && gh < HH && gw >= 0 && gw < WF); o2 = gh * WF + gw;
    }
    bool wq = tid < 162;
    int wk = tid / 18, wo = tid % 18;
    int wslot = wk * 20 + wo;
    int wbase = wo * CC * 9 + wk;     // + ic*9

    const float* P = src + (size_t)b * CC * HWF;
    float rA = v0 ? __ldg(P + o0) : 0.f;
    float rB = v1 ? __ldg(P + o1) : 0.f;
    float rC = v2 ? __ldg(P + o2) : 0.f;
    float rW = wq ? __ldg(wp + wbase) : 0.f;

    u64 acc0[9], acc1[9];
#pragma unroll
    for (int j = 0; j < 9; j++) { acc0[j] = pack2(0.f, 0.f); acc1[j] = pack2(0.f, 0.f); }

    for (int ic = 0; ic < CC; ic++) {
        __syncthreads();
        TT[i0] = rA;
        TT[i1] = rB;
        if (i2 < 612) TT[i2] = rC;
        if (wq) WS[wslot] = rW;
        if (ic < CC - 1) {
            const float* Pn = P + (size_t)(ic + 1) * HWF;
            rA = v0 ? __ldg(Pn + o0) : 0.f;
            rB = v1 ? __ldg(Pn + o1) : 0.f;
            rC = v2 ? __ldg(Pn + o2) : 0.f;
            rW = wq ? __ldg(wp + wbase + (ic + 1) * 9) : 0.f;
        }
        __syncthreads();
#pragma unroll
        for (int k = 0; k < 9; k++) {
            int ky = k / 3, kx = k % 3;
            float va = TT[(2 * ty + ky) * 18 + tx + kx];
            float vb = TT[(2 * ty + 1 + ky) * 18 + tx + kx];
            u64 V0 = pack2(va, va);
            u64 V1 = pack2(vb, vb);
            const float* Wr = &WS[k * 20];
            float4 q0 = *reinterpret_cast<const float4*>(Wr);
            float4 q1 = *reinterpret_cast<const float4*>(Wr + 4);
            float4 q2 = *reinterpret_cast<const float4*>(Wr + 8);
            float4 q3 = *reinterpret_cast<const float4*>(Wr + 12);
            u64 w8 = *reinterpret_cast<const u64*>(Wr + 16);
            u64 Wv[9] = { pack2(q0.x, q0.y), pack2(q0.z, q0.w),
                          pack2(q1.x, q1.y), pack2(q1.z, q1.w),
                          pack2(q2.x, q2.y), pack2(q2.z, q2.w),
                          pack2(q3.x, q3.y), pack2(q3.z, q3.w), w8 };
#pragma unroll
            for (int j = 0; j < 9; j++) {
                fma2(acc0[j], Wv[j], V0);
                fma2(acc1[j], Wv[j], V1);
            }
        }
    }
    int h = h0 + 2 * ty, w = w0b + tx;
    if (w < WF) {
#pragma unroll
        for (int j = 0; j < 9; j++) {
            float lo0, hi0, lo1, hi1;
            unpack2(acc0[j], lo0, hi0);
            unpack2(acc1[j], lo1, hi1);
            float blo = bp[2 * j], bhi = bp[2 * j + 1];
            size_t base = (size_t)((f * BB + b) * 18);
            g_offs[((base + 2 * j    ) * HH + h) * WF + w]     = lo0 + blo;
            g_offs[((base + 2 * j + 1) * HH + h) * WF + w]     = hi0 + bhi;
            g_offs[((base + 2 * j    ) * HH + h + 1) * WF + w] = lo1 + blo;
            g_offs[((base + 2 * j + 1) * HH + h + 1) * WF + w] = hi1 + bhi;
        }
    }
}

// ---------------- fused sampling-params + gather ----------------
__device__ __forceinline__ int padidx(float qx, float qy) {
    int X = (int)qx, Y = (int)qy;
    if (X >= 1 && X <= 256 && Y >= 1 && Y <= 129) return (X - 1) * WF + (Y - 1);
    return -1;
}

__global__ void gather_kernel() {
    int t = blockIdx.x * 256 + threadIdx.x;
    if (t >= NP) return;
    int f = blockIdx.y;
    int w = t % WF;
    int r = t / WF;
    int h = r % HH;
    int b = r / HH;

    const float* Pb = (f ? g_pha : g_amp) + (size_t)b * CC * HWF;
    float* Sbase = g_S + (size_t)f * SBR + ((size_t)b * CC * 9) * HWF + (size_t)h * WF + w;
    size_t obase = (size_t)((f * BB + b) * 18);
    const float HMax = 257.f, WMax = 130.f;

#pragma unroll
    for (int n = 0; n < 9; n++) {
        int i = n / 3, j = n % 3;
        float offx = g_offs[((obase + n    ) * HH + h) * WF + w];
        float offy = g_offs[((obase + n + 9) * HH + h) * WF + w];
        float px = (float)(h + 1) + (float)(i - 1) + offx;
        float py = (float)(w + 1) + (float)(j - 1) + offy;
        float qx = floorf(px), qy = floorf(py);
        float qltx = fminf(fmaxf(qx, 0.f), HMax);
        float qlty = fminf(fmaxf(qy, 0.f), WMax);
        float qrbx = fminf(fmaxf(qx + 1.f, 0.f), HMax);
        float qrby = fminf(fmaxf(qy + 1.f, 0.f), WMax);
        float cpx  = fminf(fmaxf(px, 0.f), HMax);
        float cpy  = fminf(fmaxf(py, 0.f), WMax);
        float glt = (1.f + (qltx - cpx)) * (1.f + (qlty - cpy));
        float grb = (1.f - (qrbx - cpx)) * (1.f - (qrby - cpy));
        float glb = (1.f + (qltx - cpx)) * (1.f - (qrby - cpy));
        float grt = (1.f - (qrbx - cpx)) * (1.f + (qlty - cpy));
        int ilt = padidx(qltx, qlty);
        int irb = padidx(qrbx, qrby);
        int ilb = padidx(qltx, qrby);
        int irt = padidx(qrbx, qlty);
        float* Sn = Sbase + (size_t)n * HWF;
#pragma unroll 4
        for (int c = 0; c < CC; c++) {
            const float* P = Pb + (size_t)c * HWF;
            float v = 0.f;
            if (ilt >= 0) v += glt * __ldg(P + ilt);
            if (irb >= 0) v += grb * __ldg(P + irb);
            if (ilb >= 0) v += glb * __ldg(P + ilb);
            if (irt >= 0) v += grt * __ldg(P + irt);
            Sn[(size_t)c * 9 * HWF] = v;
        }
    }
}

// ------- deform conv (merged): cp.async double-buffered, u64 weight loads -------
__global__ void conv_s3_kernel(const float* __restrict__ wc_a, const float* __restrict__ wc_p) {
    __shared__ float SS[2][5346];    // 9 planes x 33 x 18
    __shared__ float WSS[2][288];
    int w0 = blockIdx.x * 16, h0 = blockIdx.y * 32;
    int bz = blockIdx.z;
    int og = bz & 1;
    int f = (bz >> 1) & 1;
    int b = bz >> 2;
    const float* wc = f ? wc_p : wc_a;
    int tid = threadIdx.x;
    int tx = tid & 15, ty = tid >> 4;
    u64 acc0[16], acc1[16];
#pragma unroll
    for (int j = 0; j < 16; j++) { acc0[j] = pack2(0.f, 0.f); acc1[j] = pack2(0.f, 0.f); }

    const int ni[3] = {2, 0, 1};
    const int dd[3] = {-1, 0, 0};
    const float* Sbr = g_S + (size_t)f * SBR + ((size_t)b * CC * 9) * HWF;

    int poff[3]; bool ppred[3];
#pragma unroll
    for (int u = 0; u < 3; u++) {
        int idx2 = tid + (u << 8);
        int rr = idx2 / 18, cc = idx2 - rr * 18;
        int gh = h0 - 1 + rr, gw = w0 - 1 + cc;
        ppred[u] = (idx2 < 594) && (gh >= 0 && gh < HH && gw >= 0 && gw < WF);
        poff[u] = gh * WF + gw;
    }
    int wo0 = ((og * 32 + (tid & 31)) * CC) * 9 + (tid >> 5);
    int idxw1 = tid + 256;
    int wo1 = ((og * 32 + (idxw1 & 31)) * CC) * 9 + (idxw1 >> 5);
    bool wp1 = idxw1 < 288;

    uint32_t tb[2], wb2[2];
    tb[0] = (uint32_t)__cvta_generic_to_shared(&SS[0][0]);
    tb[1] = (uint32_t)__cvta_generic_to_shared(&SS[1][0]);
    wb2[0] = (uint32_t)__cvta_generic_to_shared(&WSS[0][0]);
    wb2[1] = (uint32_t)__cvta_generic_to_shared(&WSS[1][0]);

    auto load_stage = [&](int ic, int bufi) {
        const float* Sb = Sbr + (size_t)ic * 9 * HWF;
#pragma unroll
        for (int n = 0; n < 9; n++) {
            const float* Pn = Sb + (size_t)n * HWF;
            uint32_t dbs = tb[bufi] + 4u * (n * 594);
#pragma unroll
            for (int u = 0; u < 3; u++) {
                int idx2 = tid + (u << 8);
                if (idx2 < 594) cpa4(dbs + 4u * idx2, Pn + poff[u], ppred[u]);
            }
        }
        cpa4(wb2[bufi] + 4u * tid, wc + wo0 + ic * 9, true);
        if (wp1) cpa4(wb2[bufi] + 4u * idxw1, wc + wo1 + ic * 9, true);
    };

    load_stage(0, 0);
    CP_COMMIT();

    for (int ic = 0; ic < CC; ic++) {
        int cur = ic & 1;
        if (ic + 1 < CC) {
            load_stage(ic + 1, cur ^ 1);
            CP_COMMIT();
            CP_WAIT1();
        } else {
            CP_WAIT0();
        }
        __syncthreads();
        const float* Sc = &SS[cur][0];
        const float* Wc = &WSS[cur][0];
#pragma unroll
        for (int rr = 0; rr < 3; rr++) {
#pragma unroll
            for (int c3 = 0; c3 < 3; c3++) {
                int n = ni[rr] * 3 + ni[c3];
                int row = 2 * ty + 1 + dd[rr];
                int col = tx + 1 + dd[c3];
                float v0 = Sc[n * 594 + row * 18 + col];
                float v1 = Sc[n * 594 + (row + 1) * 18 + col];
                u64 V0 = pack2(v0, v0);
                u64 V1 = pack2(v1, v1);
                int k = rr * 3 + c3;
#pragma unroll
                for (int j = 0; j < 16; j++) {
                    u64 Wv = *reinterpret_cast<const u64*>(&Wc[k * 32 + 2 * j]);
                    fma2(acc0[j], Wv, V0);
                    fma2(acc1[j], Wv, V1);
                }
            }
        }
        __syncthreads();
    }
    int oh = h0 + 2 * ty, ow = w0 + tx;
    if (ow < WF) {
        float* dst = f ? g_p3 : g_a3;
#pragma unroll
        for (int j = 0; j < 16; j++) {
            float lo0, hi0, lo1, hi1;
            unpack2(acc0[j], lo0, hi0);
            unpack2(acc1[j], lo1, hi1);
            int oc = og * 32 + 2 * j;
            dst[((size_t)(b * CC + oc    ) * HH + oh) * WF + ow]     = lo0;
            dst[((size_t)(b * CC + oc + 1) * HH + oh) * WF + ow]     = hi0;
            dst[((size_t)(b * CC + oc    ) * HH + oh + 1) * WF + ow] = lo1;
            dst[((size_t)(b * CC + oc + 1) * HH + oh + 1) * WF + ow] = hi1;
        }
    }
}

// ---------------- fused conv1x1(both branches) + combine ----------------
extern __shared__ float dynC[];
__global__ void combine1x1_kernel(const float* __restrict__ w1_a, const float* __restrict__ b1_a,
                                  const float* __restrict__ w1_p, const float* __restrict__ b1_p) {
    float* XSa = dynC;
    float* XSp = XSa + 64 * 33;
    float* WTa = XSp + 64 * 33;
    float* WTp = WTa + 64 * 64;
    int p0 = blockIdx.x * 32;
    int b = blockIdx.y;
    int tid = threadIdx.x;
    const float* sa = g_amp + (size_t)b * CC * HWF;
    const float* sp = g_pha + (size_t)b * CC * HWF;
    for (int idx = tid; idx < 2048; idx += 256) {
        int c = idx >> 5, p = idx & 31;
        XSa[c * 33 + p] = sa[(size_t)c * HWF + p0 + p];
        XSp[c * 33 + p] = sp[(size_t)c * HWF + p0 + p];
    }
    for (int idx = tid; idx < 4096; idx += 256) {
        int oc = idx >> 6, k = idx & 63;
        WTa[k * 64 + oc] = w1_a[idx];
        WTp[k * 64 + oc] = w1_p[idx];
    }
    __syncthreads();
    int px = tid & 31, ocg = tid >> 5;
    float a1acc[8] = {0.f, 0.f, 0.f, 0.f, 0.f, 0.f, 0.f, 0.f};
    float p1acc[8] = {0.f, 0.f, 0.f, 0.f, 0.f, 0.f, 0.f, 0.f};
    for (int k = 0; k < 64; k++) {
        float xa = XSa[k * 33 + px];
        float xp = XSp[k * 33 + px];
#pragma unroll
        for (int j = 0; j < 8; j++) {
            a1acc[j] = fmaf(WTa[k * 64 + ocg + 8 * j], xa, a1acc[j]);
            p1acc[j] = fmaf(WTp[k * 64 + ocg + 8 * j], xp, p1acc[j]);
        }
    }
#pragma unroll
    for (int j = 0; j < 8; j++) {
        int oc = ocg + 8 * j;
        float a1 = a1acc[j] + b1_a[oc];
        float p1 = p1acc[j] + b1_p[oc];
        size_t o = (size_t)(b * CC + oc) * HWF + p0 + px;
        float a3 = g_a3[o], p3 = g_p3[o];
        float s1, c1, s3, c3;
        sincos_acc(p1, &s1, &c1);
        sincos_acc(p3, &s3, &c3);
        g_XF[o] = make_float2(a1 * c3 + a3 * c1 + 3e-8f,
                              a3 * s1 + a1 * s3 + 2e-8f);
    }
}

// ------- final 5x5 conv: cp.async double-buffered, 4-ic batch (55KB smem -> 4 blocks/SM) -------
extern __shared__ float dyn5[];
__global__ void conv5x5_kernel(const float* __restrict__ w0, const float* __restrict__ b0,
                               float* __restrict__ out) {
    float* T0 = dyn5;                      // 4 x 1332
    float* T1 = T0 + 4 * 1332;
    float* W0b = T1 + 4 * 1332;            // 1600
    float* W1b = W0b + 1600;
    int w0b = blockIdx.x * 32, h0 = blockIdx.y * 32;
    int bz = blockIdx.z;
    int og = bz & 3;
    int b = bz >> 2;
    int tid = threadIdx.x;
    int tx = tid & 15, ty = tid >> 4;
    u64 acc00[8], acc01[8], acc10[8], acc11[8];
#pragma unroll
    for (int j = 0; j < 8; j++) {
        acc00[j] = pack2(0.f, 0.f); acc01[j] = pack2(0.f, 0.f);
        acc10[j] = pack2(0.f, 0.f); acc11[j] = pack2(0.f, 0.f);
    }

    int poff[6], pdst[6]; bool ppred[6];
#pragma unroll
    for (int u = 0; u < 6; u++) {
        int idx2 = tid + (u << 8);
        int rr = idx2 / 36, cc = idx2 - rr * 36;
        int gh = h0 + rr - 2, gw = w0b + cc - 2;
        ppred[u] = (idx2 < 1296) && (gh >= 0 && gh < HH && gw >= 0 && gw < WW);
        poff[u] = gh * WW + gw;
        pdst[u] = rr * 37 + cc;
    }
    int wk0 = tid / 16, wo0 = tid % 16;
    int idxw1 = tid + 256;
    int wk1 = idxw1 / 16, wo1 = idxw1 % 16;
    bool wpq1 = idxw1 < 400;
    int wbase0 = ((og * 16 + wo0) * CC) * 25 + wk0;
    int wbase1 = ((og * 16 + wo1) * CC) * 25 + wk1;

    const float* Pb = g_xr + (size_t)(b * CC) * HH * WW;
    uint32_t tb[2], wb2[2];
    tb[0] = (uint32_t)__cvta_generic_to_shared(T0);
    tb[1] = (uint32_t)__cvta_generic_to_shared(T1);
    wb2[0] = (uint32_t)__cvta_generic_to_shared(W0b);
    wb2[1] = (uint32_t)__cvta_generic_to_shared(W1b);

    auto load_stage = [&](int ic0, int bufi) {
#pragma unroll
        for (int ii = 0; ii < 4; ii++) {
            const float* Pn = Pb + (size_t)(ic0 + ii) * HH * WW;
            uint32_t dbs = tb[bufi] + 4u * (ii * 1332);
#pragma unroll
            for (int u = 0; u < 6; u++) {
                int idx2 = tid + (u << 8);
                if (idx2 < 1296) cpa4(dbs + 4u * pdst[u], Pn + poff[u], ppred[u]);
            }
            uint32_t wdbs = wb2[bufi] + 4u * (ii * 400);
            cpa4(wdbs + 4u * tid, w0 + wbase0 + (ic0 + ii) * 25, true);
            if (wpq1) cpa4(wdbs + 4u * idxw1, w0 + wbase1 + (ic0 + ii) * 25, true);
        }
    };

    load_stage(0, 0);
    CP_COMMIT();

    for (int s = 0; s < 16; s++) {
        int cur = s & 1;
        if (s + 1 < 16) {
            load_stage((s + 1) * 4, cur ^ 1);
            CP_COMMIT();
            CP_WAIT1();
        } else {
            CP_WAIT0();
        }
        __syncthreads();
        const float* Tc = cur ? T1 : T0;
        const float* Wc = cur ? W1b : W0b;
#pragma unroll
        for (int ii = 0; ii < 4; ii++) {
            const float* Tb = &Tc[ii * 1332];
            const float* Wb = &Wc[ii * 400];
#pragma unroll
            for (int k = 0; k < 25; k++) {
                int ky = k / 5, kx = k % 5;
                const float* row0 = Tb + (2 * ty + ky) * 37 + 2 * tx + kx;
                float v00 = row0[0];
                float v01 = row0[1];
                float v10 = row0[37];
                float v11 = row0[38];
                u64 V00 = pack2(v00, v00);
                u64 V01 = pack2(v01, v01);
                u64 V10 = pack2(v10, v10);
                u64 V11 = pack2(v11, v11);
#pragma unroll
                for (int j = 0; j < 8; j++) {
                    u64 Wv = *reinterpret_cast<const u64*>(&Wb[k * 16 + 2 * j]);
                    fma2(acc00[j], Wv, V00);
                    fma2(acc01[j], Wv, V01);
                    fma2(acc10[j], Wv, V10);
                    fma2(acc11[j], Wv, V11);
                }
            }
        }
        __syncthreads();
    }
    int h = h0 + 2 * ty, w = w0b + 2 * tx;
#pragma unroll
    for (int j = 0; j < 8; j++) {
        int oc = og * 16 + 2 * j;
        float l00, h00, l01, h01, l10, h10, l11, h11;
        unpack2(acc00[j], l00, h00);
        unpack2(acc01[j], l01, h01);
        unpack2(acc10[j], l10, h10);
        unpack2(acc11[j], l11, h11);
        float blo = b0[oc], bhi = b0[oc + 1];
        float* o0 = out + ((size_t)(b * CC + oc) * HH + h) * WW + w;
        float* o1 = out + ((size_t)(b * CC + oc + 1) * HH + h) * WW + w;
        o0[0] = l00 + blo;  o0[1] = l01 + blo;
        o0[WW] = l10 + blo; o0[WW + 1] = l11 + blo;
        o1[0] = h00 + bhi;  o1[1] = h01 + bhi;
        o1[WW] = h10 + bhi; o1[WW + 1] = h11 + bhi;
    }
}

// ---------------- launcher ----------------
extern "C" void kernel_launch(void* const* d_in, const int* in_sizes, int n_in,
                              void* d_out, int out_size) {
    (void)in_sizes; (void)n_in; (void)out_size;
    const float* x    = (const float*)d_in[0];
    const float* wp_a = (const float*)d_in[1];
    const float* bp_a = (const float*)d_in[2];
    const float* wc_a = (const float*)d_in[3];
    const float* w1_a = (const float*)d_in[4];
    const float* b1_a = (const float*)d_in[5];
    const float* wp_p = (const float*)d_in[6];
    const float* bp_p = (const float*)d_in[7];
    const float* wc_p = (const float*)d_in[8];
    const float* w1_p = (const float*)d_in[9];
    const float* b1_p = (const float*)d_in[10];
    const float* w0   = (const float*)d_in[11];
    const float* b0   = (const float*)d_in[12];
    float* out = (float*)d_out;

    static int attr_done = 0;
    if (!attr_done) {
        cudaFuncSetAttribute(combine1x1_kernel, cudaFuncAttributeMaxDynamicSharedMemorySize, 49664);
        cudaFuncSetAttribute(conv5x5_kernel, cudaFuncAttributeMaxDynamicSharedMemorySize, 55424);
        attr_done = 1;
    }

    twiddle_init<<<1, 129>>>();

    fft_row_fwd_pair<<<BB * CC * 128, 128>>>(x);
    fft_col_kernel<<<dim3(9, CC, BB), 256>>>(0);

    // merged amp+pha deform pipeline
    conv_off_kernel<<<dim3(9, 8, BB * 2), 256>>>(wp_a, bp_a, wp_p, bp_p);
    gather_kernel<<<dim3(NP / 256, 2), 256>>>();
    conv_s3_kernel<<<dim3(9, 8, BB * 4), 256>>>(wc_a, wc_p);

    // fused 1x1 conv + recombine, then inverse transform
    combine1x1_kernel<<<dim3(HWF / 32, BB), 256, 49664>>>(w1_a, b1_a, w1_p, b1_p);
    fft_col_kernel<<<dim3(9, CC, BB), 256>>>(1);
    ifft_row_pair<<<BB * CC * 128, 128>>>();

    conv5x5_kernel<<<dim3(8, 8, BB * 4), 256, 55424>>>(w0, b0, out);
}

// round 14
// speedup vs baseline: 1.2383x; 1.0334x over previous
#include <cuda_runtime.h>
#include <stdint.h>
#include <math.h>

#define BB 4
#define CC 64
#define HH 256
#define WW 256
#define WF 129
#define HWF (HH*WF)            // 33024
#define NPIX (BB*CC*HWF)       // 8454144
#define NP (BB*HWF)            // 132096
#define FPAD 261

// ---------------- scratch (branch axis f: 0=amp, 1=pha) ----------------
__device__ float2 g_XF[NPIX];
__device__ float  g_amp[NPIX];
__device__ float  g_pha[NPIX];
__device__ float  g_a3[NPIX];
__device__ float  g_p3[NPIX];
__device__ float  g_offs[2*BB*18*HWF];
__device__ float  g_S[(size_t)2*BB*CC*9*HWF];   // sample planes [f][b][c][n][h][w]
__device__ float  g_xr[(size_t)BB*CC*HH*WW];
__device__ float2 g_tw[129];

#define SBR ((size_t)BB*CC*9*HWF)

// ---------------- packed f32x2 helpers ----------------
typedef unsigned long long u64;
__device__ __forceinline__ u64 pack2(float lo, float hi) {
    u64 r; asm("mov.b64 %0, {%1, %2};" : "=l"(r) : "f"(lo), "f"(hi)); return r;
}
__device__ __forceinline__ void unpack2(u64 v, float& lo, float& hi) {
    asm("mov.b64 {%0, %1}, %2;" : "=f"(lo), "=f"(hi) : "l"(v));
}
__device__ __forceinline__ void fma2(u64& d, u64 a, u64 b) {
    asm("fma.rn.f32x2 %0, %1, %2, %0;" : "+l"(d) : "l"(a), "l"(b));
}

// ---------------- cp.async helpers ----------------
__device__ __forceinline__ void cpa4(uint32_t dst, const float* src, bool pred) {
    int sz = pred ? 4 : 0;
    asm volatile("cp.async.ca.shared.global [%0], [%1], 4, %2;" :: "r"(dst), "l"(src), "r"(sz));
}
#define CP_COMMIT() asm volatile("cp.async.commit_group;" ::: "memory")
#define CP_WAIT1()  asm volatile("cp.async.wait_group 1;" ::: "memory")
#define CP_WAIT0()  asm volatile("cp.async.wait_group 0;" ::: "memory")

// ---------------- precise transcendentals ----------------
__device__ __forceinline__ void sincos_acc(float x, float* sp, float* cp) {
    float k = rintf(x * 0.63661977236758134f);
    float r = fmaf(k, -1.5707963705062866f, x);
    r = fmaf(k, 4.37113900018624e-8f, r);
    int q = (int)k;
    float z = r * r;
    float ss = 2.75573192e-6f;
    ss = fmaf(ss, z, -1.98412698e-4f);
    ss = fmaf(ss, z, 8.33333333e-3f);
    ss = fmaf(ss, z, -1.66666667e-1f);
    ss = fmaf(ss * z, r, r);
    float cc = -2.75573192e-7f;
    cc = fmaf(cc, z, 2.48015873e-5f);
    cc = fmaf(cc, z, -1.38888889e-3f);
    cc = fmaf(cc, z, 4.16666667e-2f);
    cc = fmaf(cc, z, -0.5f);
    cc = fmaf(cc, z, 1.0f);
    int qq = q & 3;
    float s_ = (qq & 1) ? cc : ss;
    float c_ = (qq & 1) ? ss : cc;
    if (qq == 1 || qq == 2) c_ = -c_;
    if (qq >= 2) s_ = -s_;
    *sp = s_; *cp = c_;
}

__device__ __forceinline__ float atan2_acc(float y, float x) {
    float ax = fabsf(x), ay = fabsf(y);
    float mx = fmaxf(ax, ay), mn = fminf(ax, ay);
    float t = (mx > 0.f) ? __fdiv_rn(mn, mx) : 0.f;
    float base = 0.f;
    if (t > 0.414213562f) { t = __fdiv_rn(t - 1.f, t + 1.f); base = 0.78539816339744831f; }
    float z = t * t;
    float p = -0.066666667f;
    p = fmaf(p, z,  0.076923077f);
    p = fmaf(p, z, -0.090909091f);
    p = fmaf(p, z,  0.111111111f);
    p = fmaf(p, z, -0.142857143f);
    p = fmaf(p, z,  0.2f);
    p = fmaf(p, z, -0.333333333f);
    float r = fmaf(t * z, p, t) + base;
    if (ay > ax) r = 1.57079632679489662f - r;
    if (x < 0.f) r = 3.14159265358979323f - r;
    return copysignf(r, y);
}

__global__ void twiddle_init() {
    int k = threadIdx.x;
    if (k < 129) {
        double a = -2.0 * 3.14159265358979323846 * (double)k / 256.0;
        float2 v = make_float2((float)cos(a), (float)sin(a));
        if (k == 0) v = make_float2(1.f, 0.f);
        g_tw[k] = v;
    }
}

// ---------------- FFT-256 (table = forward twiddles). sign=+1 fwd, -1 inv ----------------
__device__ __forceinline__ void fft256_tab(float2* s, const float2* tw, int t, float sign) {
#pragma unroll
    for (int kk = 0; kk < 2; kk++) {
        int i = t + (kk << 7);
        int j = __brev(i) >> 24;
        if (i < j) { float2 a = s[i]; s[i] = s[j]; s[j] = a; }
    }
    __syncthreads();
#pragma unroll
    for (int st = 1; st <= 8; st++) {
        int half = 1 << (st - 1);
        int g = t >> (st - 1);
        int p = t & (half - 1);
        int i0 = (g << st) + p;
        int i1 = i0 + half;
        float2 w = tw[p << (8 - st)];
        float wy = sign * w.y;
        float2 a = s[i0], b = s[i1];
        float2 wb = make_float2(w.x * b.x - wy * b.y, w.x * b.y + wy * b.x);
        s[i0] = make_float2(a.x + wb.x, a.y + wb.y);
        s[i1] = make_float2(a.x - wb.x, a.y - wb.y);
        __syncthreads();
    }
}

// ---- row forward rFFT, two real rows packed per complex FFT ----
__global__ void fft_row_fwd_pair(const float* __restrict__ x) {
    __shared__ float2 s[256];
    __shared__ float2 tw[128];
    int r = blockIdx.x & 127, bc = blockIdx.x >> 7, t = threadIdx.x;
    tw[t] = g_tw[t];
    const float* row0 = x + ((size_t)bc * 256 + 2 * r) * 256;
    const float* row1 = row0 + 256;
    s[t]       = make_float2(row0[t], row1[t]);
    s[t + 128] = make_float2(row0[t + 128], row1[t + 128]);
    __syncthreads();
    fft256_tab(s, tw, t, +1.f);
    size_t b0 = ((size_t)bc * 256 + 2 * r) * WF;
    size_t b1 = b0 + WF;
    float2 A = s[t];
    float2 Zr = s[(256 - t) & 255];
    g_XF[b0 + t] = make_float2(0.5f * (A.x + Zr.x), 0.5f * (A.y - Zr.y));
    g_XF[b1 + t] = make_float2(0.5f * (A.y + Zr.y), 0.5f * (Zr.x - A.x));
    if (t == 0) {
        float2 M = s[128];
        g_XF[b0 + 128] = make_float2(M.x, 0.f);
        g_XF[b1 + 128] = make_float2(M.y, 0.f);
    }
}

__global__ void fft_col_kernel(int dir) {
    __shared__ float2 S[16 * FPAD];
    __shared__ float2 tw[128];
    int k0 = blockIdx.x * 16;
    int c = blockIdx.y, b = blockIdx.z;
    int tid = threadIdx.x;
    if (tid < 128) tw[tid] = g_tw[tid];
    size_t base = ((size_t)(b * CC + c)) * HH * WF;

    for (int idx = tid; idx < 256 * 16; idx += 256) {
        int h = idx >> 4, kk = idx & 15;
        int k = k0 + kk;
        float2 v = (k < WF) ? g_XF[base + (size_t)h * WF + k] : make_float2(0.f, 0.f);
        S[kk * FPAD + h] = v;
    }
    __syncthreads();

    int f = tid >> 4;
    int l = tid & 15;
    float2* s = &S[f * FPAD];
#pragma unroll
    for (int m = 0; m < 16; m++) {
        int i = l + (m << 4);
        int j = __brev(i) >> 24;
        if (i < j) { float2 a = s[i]; s[i] = s[j]; s[j] = a; }
    }
    __syncthreads();
    float sign = dir ? -1.f : 1.f;
#pragma unroll
    for (int st = 1; st <= 8; st++) {
        int half = 1 << (st - 1);
#pragma unroll
        for (int m = 0; m < 8; m++) {
            int t = l + (m << 4);
            int g = t >> (st - 1);
            int p = t & (half - 1);
            int i0 = (g << st) + p;
            int i1 = i0 + half;
            float2 w = tw[p << (8 - st)];
            float wy = sign * w.y;
            float2 a = s[i0], bv = s[i1];
            float2 wb = make_float2(w.x * bv.x - wy * bv.y, w.x * bv.y + wy * bv.x);
            s[i0] = make_float2(a.x + wb.x, a.y + wb.y);
            s[i1] = make_float2(a.x - wb.x, a.y - wb.y);
        }
        __syncthreads();
    }

    if (dir == 0) {
        for (int idx = tid; idx < 256 * 16; idx += 256) {
            int h = idx >> 4, kk = idx & 15;
            int k = k0 + kk;
            if (k < WF) {
                float2 v = S[kk * FPAD + h];
                size_t o = base + (size_t)h * WF + k;
                g_amp[o] = __fsqrt_rn(fmaf(v.x, v.x, v.y * v.y));
                g_pha[o] = atan2_acc(v.y, v.x);
            }
        }
    } else {
        for (int idx = tid; idx < 256 * 16; idx += 256) {
            int h = idx >> 4, kk = idx & 15;
            int k = k0 + kk;
            if (k < WF) g_XF[base + (size_t)h * WF + k] = S[kk * FPAD + h];
        }
    }
}

// ---- row inverse rFFT, two rows per complex iFFT (drops Im at DC/Nyquist) ----
__global__ void ifft_row_pair() {
    __shared__ float2 s[256];
    __shared__ float2 tw[128];
    int r = blockIdx.x & 127, bc = blockIdx.x >> 7, t = threadIdx.x;
    tw[t] = g_tw[t];
    size_t b0 = ((size_t)bc * 256 + 2 * r) * WF;
    size_t b1 = b0 + WF;
    {
        float2 a1 = g_XF[b0 + t], a2 = g_XF[b1 + t];
        if (t == 0) {
            s[0] = make_float2(a1.x, a2.x);
            float2 m1 = g_XF[b0 + 128], m2 = g_XF[b1 + 128];
            s[128] = make_float2(m1.x, m2.x);
        } else {
            s[t] = make_float2(a1.x - a2.y, a1.y + a2.x);
            float2 c1 = g_XF[b0 + 128 - t], c2 = g_XF[b1 + 128 - t];
            s[t + 128] = make_float2(c1.x + c2.y, -c1.y + c2.x);
        }
    }
    __syncthreads();
    fft256_tab(s, tw, t, -1.f);
    const float inv = 1.f / 65536.f;
    float* orow0 = g_xr + ((size_t)bc * 256 + 2 * r) * 256;
    float* orow1 = orow0 + 256;
    orow0[t]       = fabsf(s[t].x * inv);
    orow0[t + 128] = fabsf(s[t + 128].x * inv);
    orow1[t]       = fabsf(s[t].y * inv);
    orow1[t + 128] = fabsf(s[t + 128].y * inv);
}

// ------- 3x3 pad-1 conv 64->18, register-prefetch pipeline (per-branch) -------
__global__ void __launch_bounds__(256, 3)
conv_off_kernel(const float* __restrict__ wp, const float* __restrict__ bp, int f) {
    __shared__ float TT[612];      // 34 rows x 18 cols
    __shared__ float WS[180];      // 9 taps x 20
    int w0b = blockIdx.x * 16, h0 = blockIdx.y * 32;
    int b = blockIdx.z;
    const float* src = f ? g_pha : g_amp;
    int tid = threadIdx.x;
    int tx = tid & 15, ty = tid >> 4;

    int i0 = tid, i1 = tid + 256, i2 = tid + 512;
    bool v0, v1, v2;
    int o0, o1, o2;
    {
        int r, cc, gh, gw;
        r = i0 / 18; cc = i0 - r * 18; gh = h0 + r - 1; gw = w0b + cc - 1;
        v0 = (gh >= 0 && gh < HH && gw >= 0 && gw < WF); o0 = gh * WF + gw;
        r = i1 / 18; cc = i1 - r * 18; gh = h0 + r - 1; gw = w0b + cc - 1;
        v1 = (gh >= 0 && gh < HH && gw >= 0 && gw < WF); o1 = gh * WF + gw;
        r = i2 / 18; cc = i2 - r * 18; gh = h0 + r - 1; gw = w0b + cc - 1;
        v2 = (i2 < 612) && (gh >= 0 && gh < HH && gw >= 0 && gw < WF); o2 = gh * WF + gw;
    }
    bool wq = tid < 162;
    int wk = tid / 18, wo = tid % 18;
    int wslot = wk * 20 + wo;
    int wbase = wo * CC * 9 + wk;     // + ic*9

    const float* P = src + (size_t)b * CC * HWF;
    float rA = v0 ? __ldg(P + o0) : 0.f;
    float rB = v1 ? __ldg(P + o1) : 0.f;
    float rC = v2 ? __ldg(P + o2) : 0.f;
    float rW = wq ? __ldg(wp + wbase) : 0.f;

    u64 acc0[9], acc1[9];
#pragma unroll
    for (int j = 0; j < 9; j++) { acc0[j] = pack2(0.f, 0.f); acc1[j] = pack2(0.f, 0.f); }

    for (int ic = 0; ic < CC; ic++) {
        __syncthreads();
        TT[i0] = rA;
        TT[i1] = rB;
        if (i2 < 612) TT[i2] = rC;
        if (wq) WS[wslot] = rW;
        if (ic < CC - 1) {
            const float* Pn = P + (size_t)(ic + 1) * HWF;
            rA = v0 ? __ldg(Pn + o0) : 0.f;
            rB = v1 ? __ldg(Pn + o1) : 0.f;
            rC = v2 ? __ldg(Pn + o2) : 0.f;
            rW = wq ? __ldg(wp + wbase + (ic + 1) * 9) : 0.f;
        }
        __syncthreads();
#pragma unroll
        for (int k = 0; k < 9; k++) {
            int ky = k / 3, kx = k % 3;
            float va = TT[(2 * ty + ky) * 18 + tx + kx];
            float vb = TT[(2 * ty + 1 + ky) * 18 + tx + kx];
            u64 V0 = pack2(va, va);
            u64 V1 = pack2(vb, vb);
            const float* Wr = &WS[k * 20];
            float4 q0 = *reinterpret_cast<const float4*>(Wr);
            float4 q1 = *reinterpret_cast<const float4*>(Wr + 4);
            float4 q2 = *reinterpret_cast<const float4*>(Wr + 8);
            float4 q3 = *reinterpret_cast<const float4*>(Wr + 12);
            u64 w8 = *reinterpret_cast<const u64*>(Wr + 16);
            u64 Wv[9] = { pack2(q0.x, q0.y), pack2(q0.z, q0.w),
                          pack2(q1.x, q1.y), pack2(q1.z, q1.w),
                          pack2(q2.x, q2.y), pack2(q2.z, q2.w),
                          pack2(q3.x, q3.y), pack2(q3.z, q3.w), w8 };
#pragma unroll
            for (int j = 0; j < 9; j++) {
                fma2(acc0[j], Wv[j], V0);
                fma2(acc1[j], Wv[j], V1);
            }
        }
    }
    int h = h0 + 2 * ty, w = w0b + tx;
    if (w < WF) {
#pragma unroll
        for (int j = 0; j < 9; j++) {
            float lo0, hi0, lo1, hi1;
            unpack2(acc0[j], lo0, hi0);
            unpack2(acc1[j], lo1, hi1);
            float blo = bp[2 * j], bhi = bp[2 * j + 1];
            size_t base = (size_t)((f * BB + b) * 18);
            g_offs[((base + 2 * j    ) * HH + h) * WF + w]     = lo0 + blo;
            g_offs[((base + 2 * j + 1) * HH + h) * WF + w]     = hi0 + bhi;
            g_offs[((base + 2 * j    ) * HH + h + 1) * WF + w] = lo1 + blo;
            g_offs[((base + 2 * j + 1) * HH + h + 1) * WF + w] = hi1 + bhi;
        }
    }
}

// ---------------- fused sampling-params + gather (per-branch) ----------------
__device__ __forceinline__ int padidx(float qx, float qy) {
    int X = (int)qx, Y = (int)qy;
    if (X >= 1 && X <= 256 && Y >= 1 && Y <= 129) return (X - 1) * WF + (Y - 1);
    return -1;
}

__global__ void gather_kernel(int f) {
    int t = blockIdx.x * 256 + threadIdx.x;
    if (t >= NP) return;
    int w = t % WF;
    int r = t / WF;
    int h = r % HH;
    int b = r / HH;

    const float* Pb = (f ? g_pha : g_amp) + (size_t)b * CC * HWF;
    float* Sbase = g_S + (size_t)f * SBR + ((size_t)b * CC * 9) * HWF + (size_t)h * WF + w;
    size_t obase = (size_t)((f * BB + b) * 18);
    const float HMax = 257.f, WMax = 130.f;

#pragma unroll
    for (int n = 0; n < 9; n++) {
        int i = n / 3, j = n % 3;
        float offx = g_offs[((obase + n    ) * HH + h) * WF + w];
        float offy = g_offs[((obase + n + 9) * HH + h) * WF + w];
        float px = (float)(h + 1) + (float)(i - 1) + offx;
        float py = (float)(w + 1) + (float)(j - 1) + offy;
        float qx = floorf(px), qy = floorf(py);
        float qltx = fminf(fmaxf(qx, 0.f), HMax);
        float qlty = fminf(fmaxf(qy, 0.f), WMax);
        float qrbx = fminf(fmaxf(qx + 1.f, 0.f), HMax);
        float qrby = fminf(fmaxf(qy + 1.f, 0.f), WMax);
        float cpx  = fminf(fmaxf(px, 0.f), HMax);
        float cpy  = fminf(fmaxf(py, 0.f), WMax);
        float glt = (1.f + (qltx - cpx)) * (1.f + (qlty - cpy));
        float grb = (1.f - (qrbx - cpx)) * (1.f - (qrby - cpy));
        float glb = (1.f + (qltx - cpx)) * (1.f - (qrby - cpy));
        float grt = (1.f - (qrbx - cpx)) * (1.f + (qlty - cpy));
        int ilt = padidx(qltx, qlty);
        int irb = padidx(qrbx, qrby);
        int ilb = padidx(qltx, qrby);
        int irt = padidx(qrbx, qlty);
        float* Sn = Sbase + (size_t)n * HWF;
#pragma unroll 4
        for (int c = 0; c < CC; c++) {
            const float* P = Pb + (size_t)c * HWF;
            float v = 0.f;
            if (ilt >= 0) v += glt * __ldg(P + ilt);
            if (irb >= 0) v += grb * __ldg(P + irb);
            if (ilb >= 0) v += glb * __ldg(P + ilb);
            if (irt >= 0) v += grt * __ldg(P + irt);
            Sn[(size_t)c * 9 * HWF] = v;
        }
    }
}

// ------- deform conv (per-branch): cp.async double-buffered, u64 weight loads -------
__global__ void conv_s3_kernel(const float* __restrict__ wc, int f) {
    __shared__ float SS[2][5346];    // 9 planes x 33 x 18
    __shared__ float WSS[2][288];
    int w0 = blockIdx.x * 16, h0 = blockIdx.y * 32;
    int bz = blockIdx.z;
    int og = bz & 1;
    int b = bz >> 1;
    int tid = threadIdx.x;
    int tx = tid & 15, ty = tid >> 4;
    u64 acc0[16], acc1[16];
#pragma unroll
    for (int j = 0; j < 16; j++) { acc0[j] = pack2(0.f, 0.f); acc1[j] = pack2(0.f, 0.f); }

    const int ni[3] = {2, 0, 1};
    const int dd[3] = {-1, 0, 0};
    const float* Sbr = g_S + (size_t)f * SBR + ((size_t)b * CC * 9) * HWF;

    int poff[3]; bool ppred[3];
#pragma unroll
    for (int u = 0; u < 3; u++) {
        int idx2 = tid + (u << 8);
        int rr = idx2 / 18, cc = idx2 - rr * 18;
        int gh = h0 - 1 + rr, gw = w0 - 1 + cc;
        ppred[u] = (idx2 < 594) && (gh >= 0 && gh < HH && gw >= 0 && gw < WF);
        poff[u] = gh * WF + gw;
    }
    int wo0 = ((og * 32 + (tid & 31)) * CC) * 9 + (tid >> 5);
    int idxw1 = tid + 256;
    int wo1 = ((og * 32 + (idxw1 & 31)) * CC) * 9 + (idxw1 >> 5);
    bool wp1 = idxw1 < 288;

    uint32_t tb[2], wb2[2];
    tb[0] = (uint32_t)__cvta_generic_to_shared(&SS[0][0]);
    tb[1] = (uint32_t)__cvta_generic_to_shared(&SS[1][0]);
    wb2[0] = (uint32_t)__cvta_generic_to_shared(&WSS[0][0]);
    wb2[1] = (uint32_t)__cvta_generic_to_shared(&WSS[1][0]);

    auto load_stage = [&](int ic, int bufi) {
        const float* Sb = Sbr + (size_t)ic * 9 * HWF;
#pragma unroll
        for (int n = 0; n < 9; n++) {
            const float* Pn = Sb + (size_t)n * HWF;
            uint32_t dbs = tb[bufi] + 4u * (n * 594);
#pragma unroll
            for (int u = 0; u < 3; u++) {
                int idx2 = tid + (u << 8);
                if (idx2 < 594) cpa4(dbs + 4u * idx2, Pn + poff[u], ppred[u]);
            }
        }
        cpa4(wb2[bufi] + 4u * tid, wc + wo0 + ic * 9, true);
        if (wp1) cpa4(wb2[bufi] + 4u * idxw1, wc + wo1 + ic * 9, true);
    };

    load_stage(0, 0);
    CP_COMMIT();

    for (int ic = 0; ic < CC; ic++) {
        int cur = ic & 1;
        if (ic + 1 < CC) {
            load_stage(ic + 1, cur ^ 1);
            CP_COMMIT();
            CP_WAIT1();
        } else {
            CP_WAIT0();
        }
        __syncthreads();
        const float* Sc = &SS[cur][0];
        const float* Wc = &WSS[cur][0];
#pragma unroll
        for (int rr = 0; rr < 3; rr++) {
#pragma unroll
            for (int c3 = 0; c3 < 3; c3++) {
                int n = ni[rr] * 3 + ni[c3];
                int row = 2 * ty + 1 + dd[rr];
                int col = tx + 1 + dd[c3];
                float v0 = Sc[n * 594 + row * 18 + col];
                float v1 = Sc[n * 594 + (row + 1) * 18 + col];
                u64 V0 = pack2(v0, v0);
                u64 V1 = pack2(v1, v1);
                int k = rr * 3 + c3;
#pragma unroll
                for (int j = 0; j < 16; j++) {
                    u64 Wv = *reinterpret_cast<const u64*>(&Wc[k * 32 + 2 * j]);
                    fma2(acc0[j], Wv, V0);
                    fma2(acc1[j], Wv, V1);
                }
            }
        }
        __syncthreads();
    }
    int oh = h0 + 2 * ty, ow = w0 + tx;
    if (ow < WF) {
        float* dst = f ? g_p3 : g_a3;
#pragma unroll
        for (int j = 0; j < 16; j++) {
            float lo0, hi0, lo1, hi1;
            unpack2(acc0[j], lo0, hi0);
            unpack2(acc1[j], lo1, hi1);
            int oc = og * 32 + 2 * j;
            dst[((size_t)(b * CC + oc    ) * HH + oh) * WF + ow]     = lo0;
            dst[((size_t)(b * CC + oc + 1) * HH + oh) * WF + ow]     = hi0;
            dst[((size_t)(b * CC + oc    ) * HH + oh + 1) * WF + ow] = lo1;
            dst[((size_t)(b * CC + oc + 1) * HH + oh + 1) * WF + ow] = hi1;
        }
    }
}

// ---------------- fused conv1x1(both branches) + combine ----------------
extern __shared__ float dynC[];
__global__ void combine1x1_kernel(const float* __restrict__ w1_a, const float* __restrict__ b1_a,
                                  const float* __restrict__ w1_p, const float* __restrict__ b1_p) {
    float* XSa = dynC;
    float* XSp = XSa + 64 * 33;
    float* WTa = XSp + 64 * 33;
    float* WTp = WTa + 64 * 64;
    int p0 = blockIdx.x * 32;
    int b = blockIdx.y;
    int tid = threadIdx.x;
    const float* sa = g_amp + (size_t)b * CC * HWF;
    const float* sp = g_pha + (size_t)b * CC * HWF;
    for (int idx = tid; idx < 2048; idx += 256) {
        int c = idx >> 5, p = idx & 31;
        XSa[c * 33 + p] = sa[(size_t)c * HWF + p0 + p];
        XSp[c * 33 + p] = sp[(size_t)c * HWF + p0 + p];
    }
    for (int idx = tid; idx < 4096; idx += 256) {
        int oc = idx >> 6, k = idx & 63;
        WTa[k * 64 + oc] = w1_a[idx];
        WTp[k * 64 + oc] = w1_p[idx];
    }
    __syncthreads();
    int px = tid & 31, ocg = tid >> 5;
    float a1acc[8] = {0.f, 0.f, 0.f, 0.f, 0.f, 0.f, 0.f, 0.f};
    float p1acc[8] = {0.f, 0.f, 0.f, 0.f, 0.f, 0.f, 0.f, 0.f};
    for (int k = 0; k < 64; k++) {
        float xa = XSa[k * 33 + px];
        float xp = XSp[k * 33 + px];
#pragma unroll
        for (int j = 0; j < 8; j++) {
            a1acc[j] = fmaf(WTa[k * 64 + ocg + 8 * j], xa, a1acc[j]);
            p1acc[j] = fmaf(WTp[k * 64 + ocg + 8 * j], xp, p1acc[j]);
        }
    }
#pragma unroll
    for (int j = 0; j < 8; j++) {
        int oc = ocg + 8 * j;
        float a1 = a1acc[j] + b1_a[oc];
        float p1 = p1acc[j] + b1_p[oc];
        size_t o = (size_t)(b * CC + oc) * HWF + p0 + px;
        float a3 = g_a3[o], p3 = g_p3[o];
        float s1, c1, s3, c3;
        sincos_acc(p1, &s1, &c1);
        sincos_acc(p3, &s3, &c3);
        g_XF[o] = make_float2(a1 * c3 + a3 * c1 + 3e-8f,
                              a3 * s1 + a1 * s3 + 2e-8f);
    }
}

// ------- final 5x5 conv: cp.async double-buffered, 4-ic batch (55KB smem) -------
extern __shared__ float dyn5[];
__global__ void conv5x5_kernel(const float* __restrict__ w0, const float* __restrict__ b0,
                               float* __restrict__ out) {
    float* T0 = dyn5;                      // 4 x 1332
    float* T1 = T0 + 4 * 1332;
    float* W0b = T1 + 4 * 1332;            // 1600
    float* W1b = W0b + 1600;
    int w0b = blockIdx.x * 32, h0 = blockIdx.y * 32;
    int bz = blockIdx.z;
    int og = bz & 3;
    int b = bz >> 2;
    int tid = threadIdx.x;
    int tx = tid & 15, ty = tid >> 4;
    u64 acc00[8], acc01[8], acc10[8], acc11[8];
#pragma unroll
    for (int j = 0; j < 8; j++) {
        acc00[j] = pack2(0.f, 0.f); acc01[j] = pack2(0.f, 0.f);
        acc10[j] = pack2(0.f, 0.f); acc11[j] = pack2(0.f, 0.f);
    }

    int poff[6], pdst[6]; bool ppred[6];
#pragma unroll
    for (int u = 0; u < 6; u++) {
        int idx2 = tid + (u << 8);
        int rr = idx2 / 36, cc = idx2 - rr * 36;
        int gh = h0 + rr - 2, gw = w0b + cc - 2;
        ppred[u] = (idx2 < 1296) && (gh >= 0 && gh < HH && gw >= 0 && gw < WW);
        poff[u] = gh * WW + gw;
        pdst[u] = rr * 37 + cc;
    }
    int wk0 = tid / 16, wo0 = tid % 16;
    int idxw1 = tid + 256;
    int wk1 = idxw1 / 16, wo1 = idxw1 % 16;
    bool wpq1 = idxw1 < 400;
    int wbase0 = ((og * 16 + wo0) * CC) * 25 + wk0;
    int wbase1 = ((og * 16 + wo1) * CC) * 25 + wk1;

    const float* Pb = g_xr + (size_t)(b * CC) * HH * WW;
    uint32_t tb[2], wb2[2];
    tb[0] = (uint32_t)__cvta_generic_to_shared(T0);
    tb[1] = (uint32_t)__cvta_generic_to_shared(T1);
    wb2[0] = (uint32_t)__cvta_generic_to_shared(W0b);
    wb2[1] = (uint32_t)__cvta_generic_to_shared(W1b);

    auto load_stage = [&](int ic0, int bufi) {
#pragma unroll
        for (int ii = 0; ii < 4; ii++) {
            const float* Pn = Pb + (size_t)(ic0 + ii) * HH * WW;
            uint32_t dbs = tb[bufi] + 4u * (ii * 1332);
#pragma unroll
            for (int u = 0; u < 6; u++) {
                int idx2 = tid + (u << 8);
                if (idx2 < 1296) cpa4(dbs + 4u * pdst[u], Pn + poff[u], ppred[u]);
            }
            uint32_t wdbs = wb2[bufi] + 4u * (ii * 400);
            cpa4(wdbs + 4u * tid, w0 + wbase0 + (ic0 + ii) * 25, true);
            if (wpq1) cpa4(wdbs + 4u * idxw1, w0 + wbase1 + (ic0 + ii) * 25, true);
        }
    };

    load_stage(0, 0);
    CP_COMMIT();

    for (int s = 0; s < 16; s++) {
        int cur = s & 1;
        if (s + 1 < 16) {
            load_stage((s + 1) * 4, cur ^ 1);
            CP_COMMIT();
            CP_WAIT1();
        } else {
            CP_WAIT0();
        }
        __syncthreads();
        const float* Tc = cur ? T1 : T0;
        const float* Wc = cur ? W1b : W0b;
#pragma unroll
        for (int ii = 0; ii < 4; ii++) {
            const float* Tb = &Tc[ii * 1332];
            const float* Wb = &Wc[ii * 400];
#pragma unroll
            for (int k = 0; k < 25; k++) {
                int ky = k / 5, kx = k % 5;
                const float* row0 = Tb + (2 * ty + ky) * 37 + 2 * tx + kx;
                float v00 = row0[0];
                float v01 = row0[1];
                float v10 = row0[37];
                float v11 = row0[38];
                u64 V00 = pack2(v00, v00);
                u64 V01 = pack2(v01, v01);
                u64 V10 = pack2(v10, v10);
                u64 V11 = pack2(v11, v11);
#pragma unroll
                for (int j = 0; j < 8; j++) {
                    u64 Wv = *reinterpret_cast<const u64*>(&Wb[k * 16 + 2 * j]);
                    fma2(acc00[j], Wv, V00);
                    fma2(acc01[j], Wv, V01);
                    fma2(acc10[j], Wv, V10);
                    fma2(acc11[j], Wv, V11);
                }
            }
        }
        __syncthreads();
    }
    int h = h0 + 2 * ty, w = w0b + 2 * tx;
#pragma unroll
    for (int j = 0; j < 8; j++) {
        int oc = og * 16 + 2 * j;
        float l00, h00, l01, h01, l10, h10, l11, h11;
        unpack2(acc00[j], l00, h00);
        unpack2(acc01[j], l01, h01);
        unpack2(acc10[j], l10, h10);
        unpack2(acc11[j], l11, h11);
        float blo = b0[oc], bhi = b0[oc + 1];
        float* o0 = out + ((size_t)(b * CC + oc) * HH + h) * WW + w;
        float* o1 = out + ((size_t)(b * CC + oc + 1) * HH + h) * WW + w;
        o0[0] = l00 + blo;  o0[1] = l01 + blo;
        o0[WW] = l10 + blo; o0[WW + 1] = l11 + blo;
        o1[0] = h00 + bhi;  o1[1] = h01 + bhi;
        o1[WW] = h10 + bhi; o1[WW + 1] = h11 + bhi;
    }
}

// ---------------- launcher (dual-stream branch overlap) ----------------
extern "C" void kernel_launch(void* const* d_in, const int* in_sizes, int n_in,
                              void* d_out, int out_size) {
    (void)in_sizes; (void)n_in; (void)out_size;
    const float* x    = (const float*)d_in[0];
    const float* wp_a = (const float*)d_in[1];
    const float* bp_a = (const float*)d_in[2];
    const float* wc_a = (const float*)d_in[3];
    const float* w1_a = (const float*)d_in[4];
    const float* b1_a = (const float*)d_in[5];
    const float* wp_p = (const float*)d_in[6];
    const float* bp_p = (const float*)d_in[7];
    const float* wc_p = (const float*)d_in[8];
    const float* w1_p = (const float*)d_in[9];
    const float* b1_p = (const float*)d_in[10];
    const float* w0   = (const float*)d_in[11];
    const float* b0   = (const float*)d_in[12];
    float* out = (float*)d_out;

    static cudaStream_t sA = 0, sB = 0;
    static cudaEvent_t evFork, evA, evB;
    static int init_done = 0;
    if (!init_done) {
        cudaStreamCreateWithFlags(&sA, cudaStreamNonBlocking);
        cudaStreamCreateWithFlags(&sB, cudaStreamNonBlocking);
        cudaEventCreateWithFlags(&evFork, cudaEventDisableTiming);
        cudaEventCreateWithFlags(&evA, cudaEventDisableTiming);
        cudaEventCreateWithFlags(&evB, cudaEventDisableTiming);
        cudaFuncSetAttribute(combine1x1_kernel, cudaFuncAttributeMaxDynamicSharedMemorySize, 49664);
        cudaFuncSetAttribute(conv5x5_kernel, cudaFuncAttributeMaxDynamicSharedMemorySize, 55424);
        init_done = 1;
    }

    twiddle_init<<<1, 129>>>();

    fft_row_fwd_pair<<<BB * CC * 128, 128>>>(x);
    fft_col_kernel<<<dim3(9, CC, BB), 256>>>(0);

    // fork: amp branch on sA, pha branch on sB
    cudaEventRecord(evFork, 0);
    cudaStreamWaitEvent(sA, evFork, 0);
    cudaStreamWaitEvent(sB, evFork, 0);

    conv_off_kernel<<<dim3(9, 8, BB), 256, 0, sA>>>(wp_a, bp_a, 0);
    gather_kernel<<<dim3((NP + 255) / 256), 256, 0, sA>>>(0);
    conv_s3_kernel<<<dim3(9, 8, BB * 2), 256, 0, sA>>>(wc_a, 0);

    conv_off_kernel<<<dim3(9, 8, BB), 256, 0, sB>>>(wp_p, bp_p, 1);
    gather_kernel<<<dim3((NP + 255) / 256), 256, 0, sB>>>(1);
    conv_s3_kernel<<<dim3(9, 8, BB * 2), 256, 0, sB>>>(wc_p, 1);

    // join
    cudaEventRecord(evA, sA);
    cudaEventRecord(evB, sB);
    cudaStreamWaitEvent(0, evA, 0);
    cudaStreamWaitEvent(0, evB, 0);

    // fused 1x1 conv + recombine, then inverse transform
    combine1x1_kernel<<<dim3(HWF / 32, BB), 256, 49664>>>(w1_a, b1_a, w1_p, b1_p);
    fft_col_kernel<<<dim3(9, CC, BB), 256>>>(1);
    ifft_row_pair<<<BB * CC * 128, 128>>>();

    conv5x5_kernel<<<dim3(8, 8, BB * 4), 256, 55424>>>(w0, b0, out);
}

// round 15
// speedup vs baseline: 1.2671x; 1.0232x over previous
#include <cuda_runtime.h>
#include <stdint.h>
#include <math.h>

#define BB 4
#define CC 64
#define HH 256
#define WW 256
#define WF 129
#define HWF (HH*WF)            // 33024
#define NPIX (BB*CC*HWF)       // 8454144
#define NP (BB*HWF)            // 132096
#define FPAD 261

// ---------------- scratch (branch axis f: 0=amp, 1=pha) ----------------
__device__ float2 g_XF[NPIX];
__device__ float  g_amp[NPIX];
__device__ float  g_pha[NPIX];
__device__ float  g_a3[NPIX];
__device__ float  g_p3[NPIX];
__device__ float  g_offs[2*BB*18*HWF];
__device__ float  g_S[(size_t)2*BB*CC*9*HWF];   // sample planes [f][b][c][n][h][w]
__device__ float  g_xr[(size_t)BB*CC*HH*WW];
__device__ float2 g_tw[129];

#define SBR ((size_t)BB*CC*9*HWF)

// ---------------- packed f32x2 helpers ----------------
typedef unsigned long long u64;
__device__ __forceinline__ u64 pack2(float lo, float hi) {
    u64 r; asm("mov.b64 %0, {%1, %2};" : "=l"(r) : "f"(lo), "f"(hi)); return r;
}
__device__ __forceinline__ void unpack2(u64 v, float& lo, float& hi) {
    asm("mov.b64 {%0, %1}, %2;" : "=f"(lo), "=f"(hi) : "l"(v));
}
__device__ __forceinline__ void fma2(u64& d, u64 a, u64 b) {
    asm("fma.rn.f32x2 %0, %1, %2, %0;" : "+l"(d) : "l"(a), "l"(b));
}

// ---------------- cp.async helpers ----------------
__device__ __forceinline__ void cpa4(uint32_t dst, const float* src, bool pred) {
    int sz = pred ? 4 : 0;
    asm volatile("cp.async.ca.shared.global [%0], [%1], 4, %2;" :: "r"(dst), "l"(src), "r"(sz));
}
#define CP_COMMIT() asm volatile("cp.async.commit_group;" ::: "memory")
#define CP_WAIT1()  asm volatile("cp.async.wait_group 1;" ::: "memory")
#define CP_WAIT0()  asm volatile("cp.async.wait_group 0;" ::: "memory")

// ---------------- precise transcendentals ----------------
__device__ __forceinline__ void sincos_acc(float x, float* sp, float* cp) {
    float k = rintf(x * 0.63661977236758134f);
    float r = fmaf(k, -1.5707963705062866f, x);
    r = fmaf(k, 4.37113900018624e-8f, r);
    int q = (int)k;
    float z = r * r;
    float ss = 2.75573192e-6f;
    ss = fmaf(ss, z, -1.98412698e-4f);
    ss = fmaf(ss, z, 8.33333333e-3f);
    ss = fmaf(ss, z, -1.66666667e-1f);
    ss = fmaf(ss * z, r, r);
    float cc = -2.75573192e-7f;
    cc = fmaf(cc, z, 2.48015873e-5f);
    cc = fmaf(cc, z, -1.38888889e-3f);
    cc = fmaf(cc, z, 4.16666667e-2f);
    cc = fmaf(cc, z, -0.5f);
    cc = fmaf(cc, z, 1.0f);
    int qq = q & 3;
    float s_ = (qq & 1) ? cc : ss;
    float c_ = (qq & 1) ? ss : cc;
    if (qq == 1 || qq == 2) c_ = -c_;
    if (qq >= 2) s_ = -s_;
    *sp = s_; *cp = c_;
}

__device__ __forceinline__ float atan2_acc(float y, float x) {
    float ax = fabsf(x), ay = fabsf(y);
    float mx = fmaxf(ax, ay), mn = fminf(ax, ay);
    float t = (mx > 0.f) ? __fdiv_rn(mn, mx) : 0.f;
    float base = 0.f;
    if (t > 0.414213562f) { t = __fdiv_rn(t - 1.f, t + 1.f); base = 0.78539816339744831f; }
    float z = t * t;
    float p = -0.066666667f;
    p = fmaf(p, z,  0.076923077f);
    p = fmaf(p, z, -0.090909091f);
    p = fmaf(p, z,  0.111111111f);
    p = fmaf(p, z, -0.142857143f);
    p = fmaf(p, z,  0.2f);
    p = fmaf(p, z, -0.333333333f);
    float r = fmaf(t * z, p, t) + base;
    if (ay > ax) r = 1.57079632679489662f - r;
    if (x < 0.f) r = 3.14159265358979323f - r;
    return copysignf(r, y);
}

__global__ void twiddle_init() {
    int k = threadIdx.x;
    if (k < 129) {
        double a = -2.0 * 3.14159265358979323846 * (double)k / 256.0;
        float2 v = make_float2((float)cos(a), (float)sin(a));
        if (k == 0) v = make_float2(1.f, 0.f);
        g_tw[k] = v;
    }
}

// ---------------- FFT-256 (table = forward twiddles). sign=+1 fwd, -1 inv ----------------
__device__ __forceinline__ void fft256_tab(float2* s, const float2* tw, int t, float sign) {
#pragma unroll
    for (int kk = 0; kk < 2; kk++) {
        int i = t + (kk << 7);
        int j = __brev(i) >> 24;
        if (i < j) { float2 a = s[i]; s[i] = s[j]; s[j] = a; }
    }
    __syncthreads();
#pragma unroll
    for (int st = 1; st <= 8; st++) {
        int half = 1 << (st - 1);
        int g = t >> (st - 1);
        int p = t & (half - 1);
        int i0 = (g << st) + p;
        int i1 = i0 + half;
        float2 w = tw[p << (8 - st)];
        float wy = sign * w.y;
        float2 a = s[i0], b = s[i1];
        float2 wb = make_float2(w.x * b.x - wy * b.y, w.x * b.y + wy * b.x);
        s[i0] = make_float2(a.x + wb.x, a.y + wb.y);
        s[i1] = make_float2(a.x - wb.x, a.y - wb.y);
        __syncthreads();
    }
}

// ---- row forward rFFT, two real rows packed per complex FFT ----
__global__ void fft_row_fwd_pair(const float* __restrict__ x) {
    __shared__ float2 s[256];
    __shared__ float2 tw[128];
    int r = blockIdx.x & 127, bc = blockIdx.x >> 7, t = threadIdx.x;
    tw[t] = g_tw[t];
    const float* row0 = x + ((size_t)bc * 256 + 2 * r) * 256;
    const float* row1 = row0 + 256;
    s[t]       = make_float2(row0[t], row1[t]);
    s[t + 128] = make_float2(row0[t + 128], row1[t + 128]);
    __syncthreads();
    fft256_tab(s, tw, t, +1.f);
    size_t b0 = ((size_t)bc * 256 + 2 * r) * WF;
    size_t b1 = b0 + WF;
    float2 A = s[t];
    float2 Zr = s[(256 - t) & 255];
    g_XF[b0 + t] = make_float2(0.5f * (A.x + Zr.x), 0.5f * (A.y - Zr.y));
    g_XF[b1 + t] = make_float2(0.5f * (A.y + Zr.y), 0.5f * (Zr.x - A.x));
    if (t == 0) {
        float2 M = s[128];
        g_XF[b0 + 128] = make_float2(M.x, 0.f);
        g_XF[b1 + 128] = make_float2(M.y, 0.f);
    }
}

__global__ void fft_col_kernel(int dir) {
    __shared__ float2 S[16 * FPAD];
    __shared__ float2 tw[128];
    int k0 = blockIdx.x * 16;
    int c = blockIdx.y, b = blockIdx.z;
    int tid = threadIdx.x;
    if (tid < 128) tw[tid] = g_tw[tid];
    size_t base = ((size_t)(b * CC + c)) * HH * WF;

    for (int idx = tid; idx < 256 * 16; idx += 256) {
        int h = idx >> 4, kk = idx & 15;
        int k = k0 + kk;
        float2 v = (k < WF) ? g_XF[base + (size_t)h * WF + k] : make_float2(0.f, 0.f);
        S[kk * FPAD + h] = v;
    }
    __syncthreads();

    int f = tid >> 4;
    int l = tid & 15;
    float2* s = &S[f * FPAD];
#pragma unroll
    for (int m = 0; m < 16; m++) {
        int i = l + (m << 4);
        int j = __brev(i) >> 24;
        if (i < j) { float2 a = s[i]; s[i] = s[j]; s[j] = a; }
    }
    __syncthreads();
    float sign = dir ? -1.f : 1.f;
#pragma unroll
    for (int st = 1; st <= 8; st++) {
        int half = 1 << (st - 1);
#pragma unroll
        for (int m = 0; m < 8; m++) {
            int t = l + (m << 4);
            int g = t >> (st - 1);
            int p = t & (half - 1);
            int i0 = (g << st) + p;
            int i1 = i0 + half;
            float2 w = tw[p << (8 - st)];
            float wy = sign * w.y;
            float2 a = s[i0], bv = s[i1];
            float2 wb = make_float2(w.x * bv.x - wy * bv.y, w.x * bv.y + wy * bv.x);
            s[i0] = make_float2(a.x + wb.x, a.y + wb.y);
            s[i1] = make_float2(a.x - wb.x, a.y - wb.y);
        }
        __syncthreads();
    }

    if (dir == 0) {
        for (int idx = tid; idx < 256 * 16; idx += 256) {
            int h = idx >> 4, kk = idx & 15;
            int k = k0 + kk;
            if (k < WF) {
                float2 v = S[kk * FPAD + h];
                size_t o = base + (size_t)h * WF + k;
                g_amp[o] = __fsqrt_rn(fmaf(v.x, v.x, v.y * v.y));
                g_pha[o] = atan2_acc(v.y, v.x);
            }
        }
    } else {
        for (int idx = tid; idx < 256 * 16; idx += 256) {
            int h = idx >> 4, kk = idx & 15;
            int k = k0 + kk;
            if (k < WF) g_XF[base + (size_t)h * WF + k] = S[kk * FPAD + h];
        }
    }
}

// ---- row inverse rFFT, two rows per complex iFFT (drops Im at DC/Nyquist) ----
__global__ void ifft_row_pair() {
    __shared__ float2 s[256];
    __shared__ float2 tw[128];
    int r = blockIdx.x & 127, bc = blockIdx.x >> 7, t = threadIdx.x;
    tw[t] = g_tw[t];
    size_t b0 = ((size_t)bc * 256 + 2 * r) * WF;
    size_t b1 = b0 + WF;
    {
        float2 a1 = g_XF[b0 + t], a2 = g_XF[b1 + t];
        if (t == 0) {
            s[0] = make_float2(a1.x, a2.x);
            float2 m1 = g_XF[b0 + 128], m2 = g_XF[b1 + 128];
            s[128] = make_float2(m1.x, m2.x);
        } else {
            s[t] = make_float2(a1.x - a2.y, a1.y + a2.x);
            float2 c1 = g_XF[b0 + 128 - t], c2 = g_XF[b1 + 128 - t];
            s[t + 128] = make_float2(c1.x + c2.y, -c1.y + c2.x);
        }
    }
    __syncthreads();
    fft256_tab(s, tw, t, -1.f);
    const float inv = 1.f / 65536.f;
    float* orow0 = g_xr + ((size_t)bc * 256 + 2 * r) * 256;
    float* orow1 = orow0 + 256;
    orow0[t]       = fabsf(s[t].x * inv);
    orow0[t + 128] = fabsf(s[t + 128].x * inv);
    orow1[t]       = fabsf(s[t].y * inv);
    orow1[t + 128] = fabsf(s[t + 128].y * inv);
}

// ------- 3x3 pad-1 conv 64->18, register-prefetch pipeline (per-branch) -------
__global__ void __launch_bounds__(256, 3)
conv_off_kernel(const float* __restrict__ wp, const float* __restrict__ bp, int f) {
    __shared__ float TT[612];      // 34 rows x 18 cols
    __shared__ float WS[180];      // 9 taps x 20
    int w0b = blockIdx.x * 16, h0 = blockIdx.y * 32;
    int b = blockIdx.z;
    const float* src = f ? g_pha : g_amp;
    int tid = threadIdx.x;
    int tx = tid & 15, ty = tid >> 4;

    int i0 = tid, i1 = tid + 256, i2 = tid + 512;
    bool v0, v1, v2;
    int o0, o1, o2;
    {
        int r, cc, gh, gw;
        r = i0 / 18; cc = i0 - r * 18; gh = h0 + r - 1; gw = w0b + cc - 1;
        v0 = (gh >= 0 && gh < HH && gw >= 0 && gw < WF); o0 = gh * WF + gw;
        r = i1 / 18; cc = i1 - r * 18; gh = h0 + r - 1; gw = w0b + cc - 1;
        v1 = (gh >= 0 && gh < HH && gw >= 0 && gw < WF); o1 = gh * WF + gw;
        r = i2 / 18; cc = i2 - r * 18; gh = h0 + r - 1; gw = w0b + cc - 1;
        v2 = (i2 < 612) && (gh >= 0 && gh < HH && gw >= 0 && gw < WF); o2 = gh * WF + gw;
    }
    bool wq = tid < 162;
    int wk = tid / 18, wo = tid % 18;
    int wslot = wk * 20 + wo;
    int wbase = wo * CC * 9 + wk;     // + ic*9

    const float* P = src + (size_t)b * CC * HWF;
    float rA = v0 ? __ldg(P + o0) : 0.f;
    float rB = v1 ? __ldg(P + o1) : 0.f;
    float rC = v2 ? __ldg(P + o2) : 0.f;
    float rW = wq ? __ldg(wp + wbase) : 0.f;

    u64 acc0[9], acc1[9];
#pragma unroll
    for (int j = 0; j < 9; j++) { acc0[j] = pack2(0.f, 0.f); acc1[j] = pack2(0.f, 0.f); }

    for (int ic = 0; ic < CC; ic++) {
        __syncthreads();
        TT[i0] = rA;
        TT[i1] = rB;
        if (i2 < 612) TT[i2] = rC;
        if (wq) WS[wslot] = rW;
        if (ic < CC - 1) {
            const float* Pn = P + (size_t)(ic + 1) * HWF;
            rA = v0 ? __ldg(Pn + o0) : 0.f;
            rB = v1 ? __ldg(Pn + o1) : 0.f;
            rC = v2 ? __ldg(Pn + o2) : 0.f;
            rW = wq ? __ldg(wp + wbase + (ic + 1) * 9) : 0.f;
        }
        __syncthreads();
#pragma unroll
        for (int k = 0; k < 9; k++) {
            int ky = k / 3, kx = k % 3;
            float va = TT[(2 * ty + ky) * 18 + tx + kx];
            float vb = TT[(2 * ty + 1 + ky) * 18 + tx + kx];
            u64 V0 = pack2(va, va);
            u64 V1 = pack2(vb, vb);
            const float* Wr = &WS[k * 20];
            float4 q0 = *reinterpret_cast<const float4*>(Wr);
            float4 q1 = *reinterpret_cast<const float4*>(Wr + 4);
            float4 q2 = *reinterpret_cast<const float4*>(Wr + 8);
            float4 q3 = *reinterpret_cast<const float4*>(Wr + 12);
            u64 w8 = *reinterpret_cast<const u64*>(Wr + 16);
            u64 Wv[9] = { pack2(q0.x, q0.y), pack2(q0.z, q0.w),
                          pack2(q1.x, q1.y), pack2(q1.z, q1.w),
                          pack2(q2.x, q2.y), pack2(q2.z, q2.w),
                          pack2(q3.x, q3.y), pack2(q3.z, q3.w), w8 };
#pragma unroll
            for (int j = 0; j < 9; j++) {
                fma2(acc0[j], Wv[j], V0);
                fma2(acc1[j], Wv[j], V1);
            }
        }
    }
    int h = h0 + 2 * ty, w = w0b + tx;
    if (w < WF) {
#pragma unroll
        for (int j = 0; j < 9; j++) {
            float lo0, hi0, lo1, hi1;
            unpack2(acc0[j], lo0, hi0);
            unpack2(acc1[j], lo1, hi1);
            float blo = bp[2 * j], bhi = bp[2 * j + 1];
            size_t base = (size_t)((f * BB + b) * 18);
            g_offs[((base + 2 * j    ) * HH + h) * WF + w]     = lo0 + blo;
            g_offs[((base + 2 * j + 1) * HH + h) * WF + w]     = hi0 + bhi;
            g_offs[((base + 2 * j    ) * HH + h + 1) * WF + w] = lo1 + blo;
            g_offs[((base + 2 * j + 1) * HH + h + 1) * WF + w] = hi1 + bhi;
        }
    }
}

// ---------------- fused sampling-params + gather: thread per (pixel, 8-ch group) ----------------
__device__ __forceinline__ int padidx(float qx, float qy) {
    int X = (int)qx, Y = (int)qy;
    if (X >= 1 && X <= 256 && Y >= 1 && Y <= 129) return (X - 1) * WF + (Y - 1);
    return -1;
}

__global__ void gather_kernel(int f) {
    int t = blockIdx.x * 256 + threadIdx.x;
    if (t >= NP * 8) return;
    int w = t % WF;
    int r = t / WF;
    int h = r % HH; r /= HH;
    int cg = r & 7;
    int b = r >> 3;

    const float* Pb = (f ? g_pha : g_amp) + (size_t)(b * CC + cg * 8) * HWF;
    float* Sbase = g_S + (size_t)f * SBR + ((size_t)(b * CC + cg * 8) * 9) * HWF + (size_t)h * WF + w;
    size_t obase = (size_t)((f * BB + b) * 18);
    const float HMax = 257.f, WMax = 130.f;

#pragma unroll
    for (int n = 0; n < 9; n++) {
        int i = n / 3, j = n % 3;
        float offx = g_offs[((obase + n    ) * HH + h) * WF + w];
        float offy = g_offs[((obase + n + 9) * HH + h) * WF + w];
        float px = (float)(h + 1) + (float)(i - 1) + offx;
        float py = (float)(w + 1) + (float)(j - 1) + offy;
        float qx = floorf(px), qy = floorf(py);
        float qltx = fminf(fmaxf(qx, 0.f), HMax);
        float qlty = fminf(fmaxf(qy, 0.f), WMax);
        float qrbx = fminf(fmaxf(qx + 1.f, 0.f), HMax);
        float qrby = fminf(fmaxf(qy + 1.f, 0.f), WMax);
        float cpx  = fminf(fmaxf(px, 0.f), HMax);
        float cpy  = fminf(fmaxf(py, 0.f), WMax);
        float glt = (1.f + (qltx - cpx)) * (1.f + (qlty - cpy));
        float grb = (1.f - (qrbx - cpx)) * (1.f - (qrby - cpy));
        float glb = (1.f + (qltx - cpx)) * (1.f - (qrby - cpy));
        float grt = (1.f - (qrbx - cpx)) * (1.f + (qlty - cpy));
        int ilt = padidx(qltx, qlty);
        int irb = padidx(qrbx, qrby);
        int ilb = padidx(qltx, qrby);
        int irt = padidx(qrbx, qlty);
        float* Sn = Sbase + (size_t)n * HWF;
#pragma unroll
        for (int c = 0; c < 8; c++) {
            const float* P = Pb + (size_t)c * HWF;
            float v = 0.f;
            if (ilt >= 0) v += glt * __ldg(P + ilt);
            if (irb >= 0) v += grb * __ldg(P + irb);
            if (ilb >= 0) v += glb * __ldg(P + ilb);
            if (irt >= 0) v += grt * __ldg(P + irt);
            Sn[(size_t)c * 9 * HWF] = v;
        }
    }
}

// ------- deform conv (per-branch): cp.async double-buffered, u64 weight loads -------
__global__ void conv_s3_kernel(const float* __restrict__ wc, int f) {
    __shared__ float SS[2][5346];    // 9 planes x 33 x 18
    __shared__ float WSS[2][288];
    int w0 = blockIdx.x * 16, h0 = blockIdx.y * 32;
    int bz = blockIdx.z;
    int og = bz & 1;
    int b = bz >> 1;
    int tid = threadIdx.x;
    int tx = tid & 15, ty = tid >> 4;
    u64 acc0[16], acc1[16];
#pragma unroll
    for (int j = 0; j < 16; j++) { acc0[j] = pack2(0.f, 0.f); acc1[j] = pack2(0.f, 0.f); }

    const int ni[3] = {2, 0, 1};
    const int dd[3] = {-1, 0, 0};
    const float* Sbr = g_S + (size_t)f * SBR + ((size_t)b * CC * 9) * HWF;

    int poff[3]; bool ppred[3];
#pragma unroll
    for (int u = 0; u < 3; u++) {
        int idx2 = tid + (u << 8);
        int rr = idx2 / 18, cc = idx2 - rr * 18;
        int gh = h0 - 1 + rr, gw = w0 - 1 + cc;
        ppred[u] = (idx2 < 594) && (gh >= 0 && gh < HH && gw >= 0 && gw < WF);
        poff[u] = gh * WF + gw;
    }
    int wo0 = ((og * 32 + (tid & 31)) * CC) * 9 + (tid >> 5);
    int idxw1 = tid + 256;
    int wo1 = ((og * 32 + (idxw1 & 31)) * CC) * 9 + (idxw1 >> 5);
    bool wp1 = idxw1 < 288;

    uint32_t tb[2], wb2[2];
    tb[0] = (uint32_t)__cvta_generic_to_shared(&SS[0][0]);
    tb[1] = (uint32_t)__cvta_generic_to_shared(&SS[1][0]);
    wb2[0] = (uint32_t)__cvta_generic_to_shared(&WSS[0][0]);
    wb2[1] = (uint32_t)__cvta_generic_to_shared(&WSS[1][0]);

    auto load_stage = [&](int ic, int bufi) {
        const float* Sb = Sbr + (size_t)ic * 9 * HWF;
#pragma unroll
        for (int n = 0; n < 9; n++) {
            const float* Pn = Sb + (size_t)n * HWF;
            uint32_t dbs = tb[bufi] + 4u * (n * 594);
#pragma unroll
            for (int u = 0; u < 3; u++) {
                int idx2 = tid + (u << 8);
                if (idx2 < 594) cpa4(dbs + 4u * idx2, Pn + poff[u], ppred[u]);
            }
        }
        cpa4(wb2[bufi] + 4u * tid, wc + wo0 + ic * 9, true);
        if (wp1) cpa4(wb2[bufi] + 4u * idxw1, wc + wo1 + ic * 9, true);
    };

    load_stage(0, 0);
    CP_COMMIT();

    for (int ic = 0; ic < CC; ic++) {
        int cur = ic & 1;
        if (ic + 1 < CC) {
            load_stage(ic + 1, cur ^ 1);
            CP_COMMIT();
            CP_WAIT1();
        } else {
            CP_WAIT0();
        }
        __syncthreads();
        const float* Sc = &SS[cur][0];
        const float* Wc = &WSS[cur][0];
#pragma unroll
        for (int rr = 0; rr < 3; rr++) {
#pragma unroll
            for (int c3 = 0; c3 < 3; c3++) {
                int n = ni[rr] * 3 + ni[c3];
                int row = 2 * ty + 1 + dd[rr];
                int col = tx + 1 + dd[c3];
                float v0 = Sc[n * 594 + row * 18 + col];
                float v1 = Sc[n * 594 + (row + 1) * 18 + col];
                u64 V0 = pack2(v0, v0);
                u64 V1 = pack2(v1, v1);
                int k = rr * 3 + c3;
#pragma unroll
                for (int j = 0; j < 16; j++) {
                    u64 Wv = *reinterpret_cast<const u64*>(&Wc[k * 32 + 2 * j]);
                    fma2(acc0[j], Wv, V0);
                    fma2(acc1[j], Wv, V1);
                }
            }
        }
        __syncthreads();
    }
    int oh = h0 + 2 * ty, ow = w0 + tx;
    if (ow < WF) {
        float* dst = f ? g_p3 : g_a3;
#pragma unroll
        for (int j = 0; j < 16; j++) {
            float lo0, hi0, lo1, hi1;
            unpack2(acc0[j], lo0, hi0);
            unpack2(acc1[j], lo1, hi1);
            int oc = og * 32 + 2 * j;
            dst[((size_t)(b * CC + oc    ) * HH + oh) * WF + ow]     = lo0;
            dst[((size_t)(b * CC + oc + 1) * HH + oh) * WF + ow]     = hi0;
            dst[((size_t)(b * CC + oc    ) * HH + oh + 1) * WF + ow] = lo1;
            dst[((size_t)(b * CC + oc + 1) * HH + oh + 1) * WF + ow] = hi1;
        }
    }
}

// ---------------- fused conv1x1(both branches) + combine ----------------
extern __shared__ float dynC[];
__global__ void combine1x1_kernel(const float* __restrict__ w1_a, const float* __restrict__ b1_a,
                                  const float* __restrict__ w1_p, const float* __restrict__ b1_p) {
    float* XSa = dynC;
    float* XSp = XSa + 64 * 33;
    float* WTa = XSp + 64 * 33;
    float* WTp = WTa + 64 * 64;
    int p0 = blockIdx.x * 32;
    int b = blockIdx.y;
    int tid = threadIdx.x;
    const float* sa = g_amp + (size_t)b * CC * HWF;
    const float* sp = g_pha + (size_t)b * CC * HWF;
    for (int idx = tid; idx < 2048; idx += 256) {
        int c = idx >> 5, p = idx & 31;
        XSa[c * 33 + p] = sa[(size_t)c * HWF + p0 + p];
        XSp[c * 33 + p] = sp[(size_t)c * HWF + p0 + p];
    }
    for (int idx = tid; idx < 4096; idx += 256) {
        int oc = idx >> 6, k = idx & 63;
        WTa[k * 64 + oc] = w1_a[idx];
        WTp[k * 64 + oc] = w1_p[idx];
    }
    __syncthreads();
    int px = tid & 31, ocg = tid >> 5;
    float a1acc[8] = {0.f, 0.f, 0.f, 0.f, 0.f, 0.f, 0.f, 0.f};
    float p1acc[8] = {0.f, 0.f, 0.f, 0.f, 0.f, 0.f, 0.f, 0.f};
    for (int k = 0; k < 64; k++) {
        float xa = XSa[k * 33 + px];
        float xp = XSp[k * 33 + px];
#pragma unroll
        for (int j = 0; j < 8; j++) {
            a1acc[j] = fmaf(WTa[k * 64 + ocg + 8 * j], xa, a1acc[j]);
            p1acc[j] = fmaf(WTp[k * 64 + ocg + 8 * j], xp, p1acc[j]);
        }
    }
#pragma unroll
    for (int j = 0; j < 8; j++) {
        int oc = ocg + 8 * j;
        float a1 = a1acc[j] + b1_a[oc];
        float p1 = p1acc[j] + b1_p[oc];
        size_t o = (size_t)(b * CC + oc) * HWF + p0 + px;
        float a3 = g_a3[o], p3 = g_p3[o];
        float s1, c1, s3, c3;
        sincos_acc(p1, &s1, &c1);
        sincos_acc(p3, &s3, &c3);
        g_XF[o] = make_float2(a1 * c3 + a3 * c1 + 3e-8f,
                              a3 * s1 + a1 * s3 + 2e-8f);
    }
}

// ------- final 5x5 conv: cp.async double-buffered, 4-ic batch (55KB smem) -------
extern __shared__ float dyn5[];
__global__ void conv5x5_kernel(const float* __restrict__ w0, const float* __restrict__ b0,
                               float* __restrict__ out) {
    float* T0 = dyn5;                      // 4 x 1332
    float* T1 = T0 + 4 * 1332;
    float* W0b = T1 + 4 * 1332;            // 1600
    float* W1b = W0b + 1600;
    int w0b = blockIdx.x * 32, h0 = blockIdx.y * 32;
    int bz = blockIdx.z;
    int og = bz & 3;
    int b = bz >> 2;
    int tid = threadIdx.x;
    int tx = tid & 15, ty = tid >> 4;
    u64 acc00[8], acc01[8], acc10[8], acc11[8];
#pragma unroll
    for (int j = 0; j < 8; j++) {
        acc00[j] = pack2(0.f, 0.f); acc01[j] = pack2(0.f, 0.f);
        acc10[j] = pack2(0.f, 0.f); acc11[j] = pack2(0.f, 0.f);
    }

    int poff[6], pdst[6]; bool ppred[6];
#pragma unroll
    for (int u = 0; u < 6; u++) {
        int idx2 = tid + (u << 8);
        int rr = idx2 / 36, cc = idx2 - rr * 36;
        int gh = h0 + rr - 2, gw = w0b + cc - 2;
        ppred[u] = (idx2 < 1296) && (gh >= 0 && gh < HH && gw >= 0 && gw < WW);
        poff[u] = gh * WW + gw;
        pdst[u] = rr * 37 + cc;
    }
    int wk0 = tid / 16, wo0 = tid % 16;
    int idxw1 = tid + 256;
    int wk1 = idxw1 / 16, wo1 = idxw1 % 16;
    bool wpq1 = idxw1 < 400;
    int wbase0 = ((og * 16 + wo0) * CC) * 25 + wk0;
    int wbase1 = ((og * 16 + wo1) * CC) * 25 + wk1;

    const float* Pb = g_xr + (size_t)(b * CC) * HH * WW;
    uint32_t tb[2], wb2[2];
    tb[0] = (uint32_t)__cvta_generic_to_shared(T0);
    tb[1] = (uint32_t)__cvta_generic_to_shared(T1);
    wb2[0] = (uint32_t)__cvta_generic_to_shared(W0b);
    wb2[1] = (uint32_t)__cvta_generic_to_shared(W1b);

    auto load_stage = [&](int ic0, int bufi) {
#pragma unroll
        for (int ii = 0; ii < 4; ii++) {
            const float* Pn = Pb + (size_t)(ic0 + ii) * HH * WW;
            uint32_t dbs = tb[bufi] + 4u * (ii * 1332);
#pragma unroll
            for (int u = 0; u < 6; u++) {
                int idx2 = tid + (u << 8);
                if (idx2 < 1296) cpa4(dbs + 4u * pdst[u], Pn + poff[u], ppred[u]);
            }
            uint32_t wdbs = wb2[bufi] + 4u * (ii * 400);
            cpa4(wdbs + 4u * tid, w0 + wbase0 + (ic0 + ii) * 25, true);
            if (wpq1) cpa4(wdbs + 4u * idxw1, w0 + wbase1 + (ic0 + ii) * 25, true);
        }
    };

    load_stage(0, 0);
    CP_COMMIT();

    for (int s = 0; s < 16; s++) {
        int cur = s & 1;
        if (s + 1 < 16) {
            load_stage((s + 1) * 4, cur ^ 1);
            CP_COMMIT();
            CP_WAIT1();
        } else {
            CP_WAIT0();
        }
        __syncthreads();
        const float* Tc = cur ? T1 : T0;
        const float* Wc = cur ? W1b : W0b;
#pragma unroll
        for (int ii = 0; ii < 4; ii++) {
            const float* Tb = &Tc[ii * 1332];
            const float* Wb = &Wc[ii * 400];
#pragma unroll
            for (int k = 0; k < 25; k++) {
                int ky = k / 5, kx = k % 5;
                const float* row0 = Tb + (2 * ty + ky) * 37 + 2 * tx + kx;
                float v00 = row0[0];
                float v01 = row0[1];
                float v10 = row0[37];
                float v11 = row0[38];
                u64 V00 = pack2(v00, v00);
                u64 V01 = pack2(v01, v01);
                u64 V10 = pack2(v10, v10);
                u64 V11 = pack2(v11, v11);
#pragma unroll
                for (int j = 0; j < 8; j++) {
                    u64 Wv = *reinterpret_cast<const u64*>(&Wb[k * 16 + 2 * j]);
                    fma2(acc00[j], Wv, V00);
                    fma2(acc01[j], Wv, V01);
                    fma2(acc10[j], Wv, V10);
                    fma2(acc11[j], Wv, V11);
                }
            }
        }
        __syncthreads();
    }
    int h = h0 + 2 * ty, w = w0b + 2 * tx;
#pragma unroll
    for (int j = 0; j < 8; j++) {
        int oc = og * 16 + 2 * j;
        float l00, h00, l01, h01, l10, h10, l11, h11;
        unpack2(acc00[j], l00, h00);
        unpack2(acc01[j], l01, h01);
        unpack2(acc10[j], l10, h10);
        unpack2(acc11[j], l11, h11);
        float blo = b0[oc], bhi = b0[oc + 1];
        float* o0 = out + ((size_t)(b * CC + oc) * HH + h) * WW + w;
        float* o1 = out + ((size_t)(b * CC + oc + 1) * HH + h) * WW + w;
        o0[0] = l00 + blo;  o0[1] = l01 + blo;
        o0[WW] = l10 + blo; o0[WW + 1] = l11 + blo;
        o1[0] = h00 + bhi;  o1[1] = h01 + bhi;
        o1[WW] = h10 + bhi; o1[WW + 1] = h11 + bhi;
    }
}

// ---------------- launcher (dual-stream branch overlap) ----------------
extern "C" void kernel_launch(void* const* d_in, const int* in_sizes, int n_in,
                              void* d_out, int out_size) {
    (void)in_sizes; (void)n_in; (void)out_size;
    const float* x    = (const float*)d_in[0];
    const float* wp_a = (const float*)d_in[1];
    const float* bp_a = (const float*)d_in[2];
    const float* wc_a = (const float*)d_in[3];
    const float* w1_a = (const float*)d_in[4];
    const float* b1_a = (const float*)d_in[5];
    const float* wp_p = (const float*)d_in[6];
    const float* bp_p = (const float*)d_in[7];
    const float* wc_p = (const float*)d_in[8];
    const float* w1_p = (const float*)d_in[9];
    const float* b1_p = (const float*)d_in[10];
    const float* w0   = (const float*)d_in[11];
    const float* b0   = (const float*)d_in[12];
    float* out = (float*)d_out;

    static cudaStream_t sA = 0, sB = 0;
    static cudaEvent_t evFork, evA, evB;
    static int init_done = 0;
    if (!init_done) {
        cudaStreamCreateWithFlags(&sA, cudaStreamNonBlocking);
        cudaStreamCreateWithFlags(&sB, cudaStreamNonBlocking);
        cudaEventCreateWithFlags(&evFork, cudaEventDisableTiming);
        cudaEventCreateWithFlags(&evA, cudaEventDisableTiming);
        cudaEventCreateWithFlags(&evB, cudaEventDisableTiming);
        cudaFuncSetAttribute(combine1x1_kernel, cudaFuncAttributeMaxDynamicSharedMemorySize, 49664);
        cudaFuncSetAttribute(conv5x5_kernel, cudaFuncAttributeMaxDynamicSharedMemorySize, 55424);
        init_done = 1;
    }

    twiddle_init<<<1, 129>>>();

    fft_row_fwd_pair<<<BB * CC * 128, 128>>>(x);
    fft_col_kernel<<<dim3(9, CC, BB), 256>>>(0);

    // fork: amp branch on sA, pha branch on sB
    cudaEventRecord(evFork, 0);
    cudaStreamWaitEvent(sA, evFork, 0);
    cudaStreamWaitEvent(sB, evFork, 0);

    conv_off_kernel<<<dim3(9, 8, BB), 256, 0, sA>>>(wp_a, bp_a, 0);
    gather_kernel<<<dim3((NP * 8 + 255) / 256), 256, 0, sA>>>(0);
    conv_s3_kernel<<<dim3(9, 8, BB * 2), 256, 0, sA>>>(wc_a, 0);

    conv_off_kernel<<<dim3(9, 8, BB), 256, 0, sB>>>(wp_p, bp_p, 1);
    gather_kernel<<<dim3((NP * 8 + 255) / 256), 256, 0, sB>>>(1);
    conv_s3_kernel<<<dim3(9, 8, BB * 2), 256, 0, sB>>>(wc_p, 1);

    // join
    cudaEventRecord(evA, sA);
    cudaEventRecord(evB, sB);
    cudaStreamWaitEvent(0, evA, 0);
    cudaStreamWaitEvent(0, evB, 0);

    // fused 1x1 conv + recombine, then inverse transform
    combine1x1_kernel<<<dim3(HWF / 32, BB), 256, 49664>>>(w1_a, b1_a, w1_p, b1_p);
    fft_col_kernel<<<dim3(9, CC, BB), 256>>>(1);
    ifft_row_pair<<<BB * CC * 128, 128>>>();

    conv5x5_kernel<<<dim3(8, 8, BB * 4), 256, 55424>>>(w0, b0, out);
}

// round 16
// speedup vs baseline: 1.2704x; 1.0026x over previous
#include <cuda_runtime.h>
#include <stdint.h>
#include <math.h>

#define BB 4
#define CC 64
#define HH 256
#define WW 256
#define WF 129
#define HWF (HH*WF)            // 33024
#define NPIX (BB*CC*HWF)       // 8454144
#define NP (BB*HWF)            // 132096
#define FPAD 261

// ---------------- scratch (branch axis f: 0=amp, 1=pha) ----------------
__device__ float2 g_XF[NPIX];
__device__ float  g_amp[NPIX];
__device__ float  g_pha[NPIX];
__device__ float  g_a3[NPIX];
__device__ float  g_p3[NPIX];
__device__ float  g_offs[2*BB*18*HWF];
__device__ float  g_S[(size_t)2*BB*CC*9*HWF];   // sample planes [f][b][c][n][h][w]
__device__ float  g_xr[(size_t)BB*CC*HH*WW];
__device__ float2 g_tw[192];

#define SBR ((size_t)BB*CC*9*HWF)

// ---------------- packed f32x2 helpers ----------------
typedef unsigned long long u64;
__device__ __forceinline__ u64 pack2(float lo, float hi) {
    u64 r; asm("mov.b64 %0, {%1, %2};" : "=l"(r) : "f"(lo), "f"(hi)); return r;
}
__device__ __forceinline__ void unpack2(u64 v, float& lo, float& hi) {
    asm("mov.b64 {%0, %1}, %2;" : "=f"(lo), "=f"(hi) : "l"(v));
}
__device__ __forceinline__ void fma2(u64& d, u64 a, u64 b) {
    asm("fma.rn.f32x2 %0, %1, %2, %0;" : "+l"(d) : "l"(a), "l"(b));
}

// ---------------- cp.async helpers ----------------
__device__ __forceinline__ void cpa4(uint32_t dst, const float* src, bool pred) {
    int sz = pred ? 4 : 0;
    asm volatile("cp.async.ca.shared.global [%0], [%1], 4, %2;" :: "r"(dst), "l"(src), "r"(sz));
}
#define CP_COMMIT() asm volatile("cp.async.commit_group;" ::: "memory")
#define CP_WAIT1()  asm volatile("cp.async.wait_group 1;" ::: "memory")
#define CP_WAIT0()  asm volatile("cp.async.wait_group 0;" ::: "memory")

// ---------------- precise transcendentals ----------------
__device__ __forceinline__ void sincos_acc(float x, float* sp, float* cp) {
    float k = rintf(x * 0.63661977236758134f);
    float r = fmaf(k, -1.5707963705062866f, x);
    r = fmaf(k, 4.37113900018624e-8f, r);
    int q = (int)k;
    float z = r * r;
    float ss = 2.75573192e-6f;
    ss = fmaf(ss, z, -1.98412698e-4f);
    ss = fmaf(ss, z, 8.33333333e-3f);
    ss = fmaf(ss, z, -1.66666667e-1f);
    ss = fmaf(ss * z, r, r);
    float cc = -2.75573192e-7f;
    cc = fmaf(cc, z, 2.48015873e-5f);
    cc = fmaf(cc, z, -1.38888889e-3f);
    cc = fmaf(cc, z, 4.16666667e-2f);
    cc = fmaf(cc, z, -0.5f);
    cc = fmaf(cc, z, 1.0f);
    int qq = q & 3;
    float s_ = (qq & 1) ? cc : ss;
    float c_ = (qq & 1) ? ss : cc;
    if (qq == 1 || qq == 2) c_ = -c_;
    if (qq >= 2) s_ = -s_;
    *sp = s_; *cp = c_;
}

__device__ __forceinline__ float atan2_acc(float y, float x) {
    float ax = fabsf(x), ay = fabsf(y);
    float mx = fmaxf(ax, ay), mn = fminf(ax, ay);
    float t = (mx > 0.f) ? __fdiv_rn(mn, mx) : 0.f;
    float base = 0.f;
    if (t > 0.414213562f) { t = __fdiv_rn(t - 1.f, t + 1.f); base = 0.78539816339744831f; }
    float z = t * t;
    float p = -0.066666667f;
    p = fmaf(p, z,  0.076923077f);
    p = fmaf(p, z, -0.090909091f);
    p = fmaf(p, z,  0.111111111f);
    p = fmaf(p, z, -0.142857143f);
    p = fmaf(p, z,  0.2f);
    p = fmaf(p, z, -0.333333333f);
    float r = fmaf(t * z, p, t) + base;
    if (ay > ax) r = 1.57079632679489662f - r;
    if (x < 0.f) r = 3.14159265358979323f - r;
    return copysignf(r, y);
}

__global__ void twiddle_init() {
    int k = threadIdx.x;
    if (k < 192) {
        double a = -2.0 * 3.14159265358979323846 * (double)k / 256.0;
        float2 v = make_float2((float)cos(a), (float)sin(a));
        if (k == 0) v = make_float2(1.f, 0.f);
        g_tw[k] = v;
    }
}

// ---------------- radix-2 FFT-256 (rows). sign=+1 fwd, -1 inv ----------------
__device__ __forceinline__ void fft256_tab(float2* s, const float2* tw, int t, float sign) {
#pragma unroll
    for (int kk = 0; kk < 2; kk++) {
        int i = t + (kk << 7);
        int j = __brev(i) >> 24;
        if (i < j) { float2 a = s[i]; s[i] = s[j]; s[j] = a; }
    }
    __syncthreads();
#pragma unroll
    for (int st = 1; st <= 8; st++) {
        int half = 1 << (st - 1);
        int g = t >> (st - 1);
        int p = t & (half - 1);
        int i0 = (g << st) + p;
        int i1 = i0 + half;
        float2 w = tw[p << (8 - st)];
        float wy = sign * w.y;
        float2 a = s[i0], b = s[i1];
        float2 wb = make_float2(w.x * b.x - wy * b.y, w.x * b.y + wy * b.x);
        s[i0] = make_float2(a.x + wb.x, a.y + wb.y);
        s[i1] = make_float2(a.x - wb.x, a.y - wb.y);
        __syncthreads();
    }
}

// ---- row forward rFFT, two real rows packed per complex FFT ----
__global__ void fft_row_fwd_pair(const float* __restrict__ x) {
    __shared__ float2 s[256];
    __shared__ float2 tw[128];
    int r = blockIdx.x & 127, bc = blockIdx.x >> 7, t = threadIdx.x;
    tw[t] = g_tw[t];
    const float* row0 = x + ((size_t)bc * 256 + 2 * r) * 256;
    const float* row1 = row0 + 256;
    s[t]       = make_float2(row0[t], row1[t]);
    s[t + 128] = make_float2(row0[t + 128], row1[t + 128]);
    __syncthreads();
    fft256_tab(s, tw, t, +1.f);
    size_t b0 = ((size_t)bc * 256 + 2 * r) * WF;
    size_t b1 = b0 + WF;
    float2 A = s[t];
    float2 Zr = s[(256 - t) & 255];
    g_XF[b0 + t] = make_float2(0.5f * (A.x + Zr.x), 0.5f * (A.y - Zr.y));
    g_XF[b1 + t] = make_float2(0.5f * (A.y + Zr.y), 0.5f * (Zr.x - A.x));
    if (t == 0) {
        float2 M = s[128];
        g_XF[b0 + 128] = make_float2(M.x, 0.f);
        g_XF[b1 + 128] = make_float2(M.y, 0.f);
    }
}

// ---- column FFT: radix-4 DIT, warp-local syncs ----
__device__ __forceinline__ int rev4(int i) {
    return ((i & 3) << 6) | (((i >> 2) & 3) << 4) | (((i >> 4) & 3) << 2) | ((i >> 6) & 3);
}

__global__ void fft_col_kernel(int dir) {
    __shared__ float2 S[16 * FPAD];
    __shared__ float2 tw[192];
    int k0 = blockIdx.x * 16;
    int c = blockIdx.y, b = blockIdx.z;
    int tid = threadIdx.x;
    if (tid < 192) tw[tid] = g_tw[tid];
    size_t base = ((size_t)(b * CC + c)) * HH * WF;

    for (int idx = tid; idx < 256 * 16; idx += 256) {
        int h = idx >> 4, kk = idx & 15;
        int k = k0 + kk;
        float2 v = (k < WF) ? g_XF[base + (size_t)h * WF + k] : make_float2(0.f, 0.f);
        S[kk * FPAD + h] = v;
    }
    __syncthreads();

    int f = tid >> 4;
    int l = tid & 15;
    float2* s = &S[f * FPAD];

    // base-4 digit reversal (warp-local: FFT data private to its 16 lanes)
#pragma unroll
    for (int m = 0; m < 16; m++) {
        int i = l + (m << 4);
        int j = rev4(i);
        if (i < j) { float2 a = s[i]; s[i] = s[j]; s[j] = a; }
    }
    __syncwarp();

    float sgn = dir ? -1.f : 1.f;   // twiddle conj for inverse
    float di  = dir ? -1.f : 1.f;   // -i (fwd) / +i (inv) factor
#pragma unroll
    for (int st = 0; st < 4; st++) {
        int q_ = 1 << (2 * st);
        int tstep = 64 >> (2 * st);
#pragma unroll
        for (int m = 0; m < 4; m++) {
            int bidx = l + (m << 4);
            int g = bidx >> (2 * st);
            int p = bidx & (q_ - 1);
            int i0 = g * (q_ << 2) + p;
            int i1 = i0 + q_;
            int i2 = i1 + q_;
            int i3 = i2 + q_;
            int e = p * tstep;
            float2 x0 = s[i0], x1 = s[i1], x2 = s[i2], x3 = s[i3];
            float2 w1 = tw[e], w2 = tw[2 * e], w3 = tw[3 * e];
            float w1y = sgn * w1.y, w2y = sgn * w2.y, w3y = sgn * w3.y;
            float2 u1 = make_float2(w1.x * x1.x - w1y * x1.y, w1.x * x1.y + w1y * x1.x);
            float2 u2 = make_float2(w2.x * x2.x - w2y * x2.y, w2.x * x2.y + w2y * x2.x);
            float2 u3 = make_float2(w3.x * x3.x - w3y * x3.y, w3.x * x3.y + w3y * x3.x);
            float2 A = make_float2(x0.x + u2.x, x0.y + u2.y);
            float2 C = make_float2(x0.x - u2.x, x0.y - u2.y);
            float2 Bv = make_float2(u1.x + u3.x, u1.y + u3.y);
            float2 D = make_float2(u1.x - u3.x, u1.y - u3.y);
            s[i0] = make_float2(A.x + Bv.x, A.y + Bv.y);
            s[i2] = make_float2(A.x - Bv.x, A.y - Bv.y);
            s[i1] = make_float2(C.x + di * D.y, C.y - di * D.x);
            s[i3] = make_float2(C.x - di * D.y, C.y + di * D.x);
        }
        __syncwarp();
    }
    __syncthreads();

    if (dir == 0) {
        for (int idx = tid; idx < 256 * 16; idx += 256) {
            int h = idx >> 4, kk = idx & 15;
            int k = k0 + kk;
            if (k < WF) {
                float2 v = S[kk * FPAD + h];
                size_t o = base + (size_t)h * WF + k;
                g_amp[o] = __fsqrt_rn(fmaf(v.x, v.x, v.y * v.y));
                g_pha[o] = atan2_acc(v.y, v.x);
            }
        }
    } else {
        for (int idx = tid; idx < 256 * 16; idx += 256) {
            int h = idx >> 4, kk = idx & 15;
            int k = k0 + kk;
            if (k < WF) g_XF[base + (size_t)h * WF + k] = S[kk * FPAD + h];
        }
    }
}

// ---- row inverse rFFT, two rows per complex iFFT (drops Im at DC/Nyquist) ----
__global__ void ifft_row_pair() {
    __shared__ float2 s[256];
    __shared__ float2 tw[128];
    int r = blockIdx.x & 127, bc = blockIdx.x >> 7, t = threadIdx.x;
    tw[t] = g_tw[t];
    size_t b0 = ((size_t)bc * 256 + 2 * r) * WF;
    size_t b1 = b0 + WF;
    {
        float2 a1 = g_XF[b0 + t], a2 = g_XF[b1 + t];
        if (t == 0) {
            s[0] = make_float2(a1.x, a2.x);
            float2 m1 = g_XF[b0 + 128], m2 = g_XF[b1 + 128];
            s[128] = make_float2(m1.x, m2.x);
        } else {
            s[t] = make_float2(a1.x - a2.y, a1.y + a2.x);
            float2 c1 = g_XF[b0 + 128 - t], c2 = g_XF[b1 + 128 - t];
            s[t + 128] = make_float2(c1.x + c2.y, -c1.y + c2.x);
        }
    }
    __syncthreads();
    fft256_tab(s, tw, t, -1.f);
    const float inv = 1.f / 65536.f;
    float* orow0 = g_xr + ((size_t)bc * 256 + 2 * r) * 256;
    float* orow1 = orow0 + 256;
    orow0[t]       = fabsf(s[t].x * inv);
    orow0[t + 128] = fabsf(s[t + 128].x * inv);
    orow1[t]       = fabsf(s[t].y * inv);
    orow1[t + 128] = fabsf(s[t + 128].y * inv);
}

// ------- 3x3 pad-1 conv 64->18, register-prefetch pipeline (per-branch) -------
__global__ void __launch_bounds__(256, 3)
conv_off_kernel(const float* __restrict__ wp, const float* __restrict__ bp, int f) {
    __shared__ float TT[612];      // 34 rows x 18 cols
    __shared__ float WS[180];      // 9 taps x 20
    int w0b = blockIdx.x * 16, h0 = blockIdx.y * 32;
    int b = blockIdx.z;
    const float* src = f ? g_pha : g_amp;
    int tid = threadIdx.x;
    int tx = tid & 15, ty = tid >> 4;

    int i0 = tid, i1 = tid + 256, i2 = tid + 512;
    bool v0, v1, v2;
    int o0, o1, o2;
    {
        int r, cc, gh, gw;
        r = i0 / 18; cc = i0 - r * 18; gh = h0 + r - 1; gw = w0b + cc - 1;
        v0 = (gh >= 0 && gh < HH && gw >= 0 && gw < WF); o0 = gh * WF + gw;
        r = i1 / 18; cc = i1 - r * 18; gh = h0 + r - 1; gw = w0b + cc - 1;
        v1 = (gh >= 0 && gh < HH && gw >= 0 && gw < WF); o1 = gh * WF + gw;
        r = i2 / 18; cc = i2 - r * 18; gh = h0 + r - 1; gw = w0b + cc - 1;
        v2 = (i2 < 612) && (gh >= 0 && gh < HH && gw >= 0 && gw < WF); o2 = gh * WF + gw;
    }
    bool wq = tid < 162;
    int wk = tid / 18, wo = tid % 18;
    int wslot = wk * 20 + wo;
    int wbase = wo * CC * 9 + wk;     // + ic*9

    const float* P = src + (size_t)b * CC * HWF;
    float rA = v0 ? __ldg(P + o0) : 0.f;
    float rB = v1 ? __ldg(P + o1) : 0.f;
    float rC = v2 ? __ldg(P + o2) : 0.f;
    float rW = wq ? __ldg(wp + wbase) : 0.f;

    u64 acc0[9], acc1[9];
#pragma unroll
    for (int j = 0; j < 9; j++) { acc0[j] = pack2(0.f, 0.f); acc1[j] = pack2(0.f, 0.f); }

    for (int ic = 0; ic < CC; ic++) {
        __syncthreads();
        TT[i0] = rA;
        TT[i1] = rB;
        if (i2 < 612) TT[i2] = rC;
        if (wq) WS[wslot] = rW;
        if (ic < CC - 1) {
            const float* Pn = P + (size_t)(ic + 1) * HWF;
            rA = v0 ? __ldg(Pn + o0) : 0.f;
            rB = v1 ? __ldg(Pn + o1) : 0.f;
            rC = v2 ? __ldg(Pn + o2) : 0.f;
            rW = wq ? __ldg(wp + wbase + (ic + 1) * 9) : 0.f;
        }
        __syncthreads();
#pragma unroll
        for (int k = 0; k < 9; k++) {
            int ky = k / 3, kx = k % 3;
            float va = TT[(2 * ty + ky) * 18 + tx + kx];
            float vb = TT[(2 * ty + 1 + ky) * 18 + tx + kx];
            u64 V0 = pack2(va, va);
            u64 V1 = pack2(vb, vb);
            const float* Wr = &WS[k * 20];
            float4 q0 = *reinterpret_cast<const float4*>(Wr);
            float4 q1 = *reinterpret_cast<const float4*>(Wr + 4);
            float4 q2 = *reinterpret_cast<const float4*>(Wr + 8);
            float4 q3 = *reinterpret_cast<const float4*>(Wr + 12);
            u64 w8 = *reinterpret_cast<const u64*>(Wr + 16);
            u64 Wv[9] = { pack2(q0.x, q0.y), pack2(q0.z, q0.w),
                          pack2(q1.x, q1.y), pack2(q1.z, q1.w),
                          pack2(q2.x, q2.y), pack2(q2.z, q2.w),
                          pack2(q3.x, q3.y), pack2(q3.z, q3.w), w8 };
#pragma unroll
            for (int j = 0; j < 9; j++) {
                fma2(acc0[j], Wv[j], V0);
                fma2(acc1[j], Wv[j], V1);
            }
        }
    }
    int h = h0 + 2 * ty, w = w0b + tx;
    if (w < WF) {
#pragma unroll
        for (int j = 0; j < 9; j++) {
            float lo0, hi0, lo1, hi1;
            unpack2(acc0[j], lo0, hi0);
            unpack2(acc1[j], lo1, hi1);
            float blo = bp[2 * j], bhi = bp[2 * j + 1];
            size_t base = (size_t)((f * BB + b) * 18);
            g_offs[((base + 2 * j    ) * HH + h) * WF + w]     = lo0 + blo;
            g_offs[((base + 2 * j + 1) * HH + h) * WF + w]     = hi0 + bhi;
            g_offs[((base + 2 * j    ) * HH + h + 1) * WF + w] = lo1 + blo;
            g_offs[((base + 2 * j + 1) * HH + h + 1) * WF + w] = hi1 + bhi;
        }
    }
}

// ---------------- fused sampling-params + gather: thread per (pixel, 8-ch group) ----------------
__device__ __forceinline__ int padidx(float qx, float qy) {
    int X = (int)qx, Y = (int)qy;
    if (X >= 1 && X <= 256 && Y >= 1 && Y <= 129) return (X - 1) * WF + (Y - 1);
    return -1;
}

__global__ void gather_kernel(int f) {
    int t = blockIdx.x * 256 + threadIdx.x;
    if (t >= NP * 8) return;
    int w = t % WF;
    int r = t / WF;
    int h = r % HH; r /= HH;
    int cg = r & 7;
    int b = r >> 3;

    const float* Pb = (f ? g_pha : g_amp) + (size_t)(b * CC + cg * 8) * HWF;
    float* Sbase = g_S + (size_t)f * SBR + ((size_t)(b * CC + cg * 8) * 9) * HWF + (size_t)h * WF + w;
    size_t obase = (size_t)((f * BB + b) * 18);
    const float HMax = 257.f, WMax = 130.f;

#pragma unroll
    for (int n = 0; n < 9; n++) {
        int i = n / 3, j = n % 3;
        float offx = g_offs[((obase + n    ) * HH + h) * WF + w];
        float offy = g_offs[((obase + n + 9) * HH + h) * WF + w];
        float px = (float)(h + 1) + (float)(i - 1) + offx;
        float py = (float)(w + 1) + (float)(j - 1) + offy;
        float qx = floorf(px), qy = floorf(py);
        float qltx = fminf(fmaxf(qx, 0.f), HMax);
        float qlty = fminf(fmaxf(qy, 0.f), WMax);
        float qrbx = fminf(fmaxf(qx + 1.f, 0.f), HMax);
        float qrby = fminf(fmaxf(qy + 1.f, 0.f), WMax);
        float cpx  = fminf(fmaxf(px, 0.f), HMax);
        float cpy  = fminf(fmaxf(py, 0.f), WMax);
        float glt = (1.f + (qltx - cpx)) * (1.f + (qlty - cpy));
        float grb = (1.f - (qrbx - cpx)) * (1.f - (qrby - cpy));
        float glb = (1.f + (qltx - cpx)) * (1.f - (qrby - cpy));
        float grt = (1.f - (qrbx - cpx)) * (1.f + (qlty - cpy));
        int ilt = padidx(qltx, qlty);
        int irb = padidx(qrbx, qrby);
        int ilb = padidx(qltx, qrby);
        int irt = padidx(qrbx, qlty);
        float* Sn = Sbase + (size_t)n * HWF;
#pragma unroll
        for (int c = 0; c < 8; c++) {
            const float* P = Pb + (size_t)c * HWF;
            float v = 0.f;
            if (ilt >= 0) v += glt * __ldg(P + ilt);
            if (irb >= 0) v += grb * __ldg(P + irb);
            if (ilb >= 0) v += glb * __ldg(P + ilb);
            if (irt >= 0) v += grt * __ldg(P + irt);
            Sn[(size_t)c * 9 * HWF] = v;
        }
    }
}

// ------- deform conv (per-branch): cp.async double-buffered, u64 weight loads -------
__global__ void conv_s3_kernel(const float* __restrict__ wc, int f) {
    __shared__ float SS[2][5346];    // 9 planes x 33 x 18
    __shared__ float WSS[2][288];
    int w0 = blockIdx.x * 16, h0 = blockIdx.y * 32;
    int bz = blockIdx.z;
    int og = bz & 1;
    int b = bz >> 1;
    int tid = threadIdx.x;
    int tx = tid & 15, ty = tid >> 4;
    u64 acc0[16], acc1[16];
#pragma unroll
    for (int j = 0; j < 16; j++) { acc0[j] = pack2(0.f, 0.f); acc1[j] = pack2(0.f, 0.f); }

    const int ni[3] = {2, 0, 1};
    const int dd[3] = {-1, 0, 0};
    const float* Sbr = g_S + (size_t)f * SBR + ((size_t)b * CC * 9) * HWF;

    int poff[3]; bool ppred[3];
#pragma unroll
    for (int u = 0; u < 3; u++) {
        int idx2 = tid + (u << 8);
        int rr = idx2 / 18, cc = idx2 - rr * 18;
        int gh = h0 - 1 + rr, gw = w0 - 1 + cc;
        ppred[u] = (idx2 < 594) && (gh >= 0 && gh < HH && gw >= 0 && gw < WF);
        poff[u] = gh * WF + gw;
    }
    int wo0 = ((og * 32 + (tid & 31)) * CC) * 9 + (tid >> 5);
    int idxw1 = tid + 256;
    int wo1 = ((og * 32 + (idxw1 & 31)) * CC) * 9 + (idxw1 >> 5);
    bool wp1 = idxw1 < 288;

    uint32_t tb[2], wb2[2];
    tb[0] = (uint32_t)__cvta_generic_to_shared(&SS[0][0]);
    tb[1] = (uint32_t)__cvta_generic_to_shared(&SS[1][0]);
    wb2[0] = (uint32_t)__cvta_generic_to_shared(&WSS[0][0]);
    wb2[1] = (uint32_t)__cvta_generic_to_shared(&WSS[1][0]);

    auto load_stage = [&](int ic, int bufi) {
        const float* Sb = Sbr + (size_t)ic * 9 * HWF;
#pragma unroll
        for (int n = 0; n < 9; n++) {
            const float* Pn = Sb + (size_t)n * HWF;
            uint32_t dbs = tb[bufi] + 4u * (n * 594);
#pragma unroll
            for (int u = 0; u < 3; u++) {
                int idx2 = tid + (u << 8);
                if (idx2 < 594) cpa4(dbs + 4u * idx2, Pn + poff[u], ppred[u]);
            }
        }
        cpa4(wb2[bufi] + 4u * tid, wc + wo0 + ic * 9, true);
        if (wp1) cpa4(wb2[bufi] + 4u * idxw1, wc + wo1 + ic * 9, true);
    };

    load_stage(0, 0);
    CP_COMMIT();

    for (int ic = 0; ic < CC; ic++) {
        int cur = ic & 1;
        if (ic + 1 < CC) {
            load_stage(ic + 1, cur ^ 1);
            CP_COMMIT();
            CP_WAIT1();
        } else {
            CP_WAIT0();
        }
        __syncthreads();
        const float* Sc = &SS[cur][0];
        const float* Wc = &WSS[cur][0];
#pragma unroll
        for (int rr = 0; rr < 3; rr++) {
#pragma unroll
            for (int c3 = 0; c3 < 3; c3++) {
                int n = ni[rr] * 3 + ni[c3];
                int row = 2 * ty + 1 + dd[rr];
                int col = tx + 1 + dd[c3];
                float v0 = Sc[n * 594 + row * 18 + col];
                float v1 = Sc[n * 594 + (row + 1) * 18 + col];
                u64 V0 = pack2(v0, v0);
                u64 V1 = pack2(v1, v1);
                int k = rr * 3 + c3;
#pragma unroll
                for (int j = 0; j < 16; j++) {
                    u64 Wv = *reinterpret_cast<const u64*>(&Wc[k * 32 + 2 * j]);
                    fma2(acc0[j], Wv, V0);
                    fma2(acc1[j], Wv, V1);
                }
            }
        }
        __syncthreads();
    }
    int oh = h0 + 2 * ty, ow = w0 + tx;
    if (ow < WF) {
        float* dst = f ? g_p3 : g_a3;
#pragma unroll
        for (int j = 0; j < 16; j++) {
            float lo0, hi0, lo1, hi1;
            unpack2(acc0[j], lo0, hi0);
            unpack2(acc1[j], lo1, hi1);
            int oc = og * 32 + 2 * j;
            dst[((size_t)(b * CC + oc    ) * HH + oh) * WF + ow]     = lo0;
            dst[((size_t)(b * CC + oc + 1) * HH + oh) * WF + ow]     = hi0;
            dst[((size_t)(b * CC + oc    ) * HH + oh + 1) * WF + ow] = lo1;
            dst[((size_t)(b * CC + oc + 1) * HH + oh + 1) * WF + ow] = hi1;
        }
    }
}

// ---------------- fused conv1x1(both branches) + combine ----------------
extern __shared__ float dynC[];
__global__ void combine1x1_kernel(const float* __restrict__ w1_a, const float* __restrict__ b1_a,
                                  const float* __restrict__ w1_p, const float* __restrict__ b1_p) {
    float* XSa = dynC;
    float* XSp = XSa + 64 * 33;
    float* WTa = XSp + 64 * 33;
    float* WTp = WTa + 64 * 64;
    int p0 = blockIdx.x * 32;
    int b = blockIdx.y;
    int tid = threadIdx.x;
    const float* sa = g_amp + (size_t)b * CC * HWF;
    const float* sp = g_pha + (size_t)b * CC * HWF;
    for (int idx = tid; idx < 2048; idx += 256) {
        int c = idx >> 5, p = idx & 31;
        XSa[c * 33 + p] = sa[(size_t)c * HWF + p0 + p];
        XSp[c * 33 + p] = sp[(size_t)c * HWF + p0 + p];
    }
    for (int idx = tid; idx < 4096; idx += 256) {
        int oc = idx >> 6, k = idx & 63;
        WTa[k * 64 + oc] = w1_a[idx];
        WTp[k * 64 + oc] = w1_p[idx];
    }
    __syncthreads();
    int px = tid & 31, ocg = tid >> 5;
    float a1acc[8] = {0.f, 0.f, 0.f, 0.f, 0.f, 0.f, 0.f, 0.f};
    float p1acc[8] = {0.f, 0.f, 0.f, 0.f, 0.f, 0.f, 0.f, 0.f};
    for (int k = 0; k < 64; k++) {
        float xa = XSa[k * 33 + px];
        float xp = XSp[k * 33 + px];
#pragma unroll
        for (int j = 0; j < 8; j++) {
            a1acc[j] = fmaf(WTa[k * 64 + ocg + 8 * j], xa, a1acc[j]);
            p1acc[j] = fmaf(WTp[k * 64 + ocg + 8 * j], xp, p1acc[j]);
        }
    }
#pragma unroll
    for (int j = 0; j < 8; j++) {
        int oc = ocg + 8 * j;
        float a1 = a1acc[j] + b1_a[oc];
        float p1 = p1acc[j] + b1_p[oc];
        size_t o = (size_t)(b * CC + oc) * HWF + p0 + px;
        float a3 = g_a3[o], p3 = g_p3[o];
        float s1, c1, s3, c3;
        sincos_acc(p1, &s1, &c1);
        sincos_acc(p3, &s3, &c3);
        g_XF[o] = make_float2(a1 * c3 + a3 * c1 + 3e-8f,
                              a3 * s1 + a1 * s3 + 2e-8f);
    }
}

// ------- final 5x5 conv: cp.async double-buffered, 4-ic batch (55KB smem) -------
extern __shared__ float dyn5[];
__global__ void conv5x5_kernel(const float* __restrict__ w0, const float* __restrict__ b0,
                               float* __restrict__ out) {
    float* T0 = dyn5;                      // 4 x 1332
    float* T1 = T0 + 4 * 1332;
    float* W0b = T1 + 4 * 1332;            // 1600
    float* W1b = W0b + 1600;
    int w0b = blockIdx.x * 32, h0 = blockIdx.y * 32;
    int bz = blockIdx.z;
    int og = bz & 3;
    int b = bz >> 2;
    int tid = threadIdx.x;
    int tx = tid & 15, ty = tid >> 4;
    u64 acc00[8], acc01[8], acc10[8], acc11[8];
#pragma unroll
    for (int j = 0; j < 8; j++) {
        acc00[j] = pack2(0.f, 0.f); acc01[j] = pack2(0.f, 0.f);
        acc10[j] = pack2(0.f, 0.f); acc11[j] = pack2(0.f, 0.f);
    }

    int poff[6], pdst[6]; bool ppred[6];
#pragma unroll
    for (int u = 0; u < 6; u++) {
        int idx2 = tid + (u << 8);
        int rr = idx2 / 36, cc = idx2 - rr * 36;
        int gh = h0 + rr - 2, gw = w0b + cc - 2;
        ppred[u] = (idx2 < 1296) && (gh >= 0 && gh < HH && gw >= 0 && gw < WW);
        poff[u] = gh * WW + gw;
        pdst[u] = rr * 37 + cc;
    }
    int wk0 = tid / 16, wo0 = tid % 16;
    int idxw1 = tid + 256;
    int wk1 = idxw1 / 16, wo1 = idxw1 % 16;
    bool wpq1 = idxw1 < 400;
    int wbase0 = ((og * 16 + wo0) * CC) * 25 + wk0;
    int wbase1 = ((og * 16 + wo1) * CC) * 25 + wk1;

    const float* Pb = g_xr + (size_t)(b * CC) * HH * WW;
    uint32_t tb[2], wb2[2];
    tb[0] = (uint32_t)__cvta_generic_to_shared(T0);
    tb[1] = (uint32_t)__cvta_generic_to_shared(T1);
    wb2[0] = (uint32_t)__cvta_generic_to_shared(W0b);
    wb2[1] = (uint32_t)__cvta_generic_to_shared(W1b);

    auto load_stage = [&](int ic0, int bufi) {
#pragma unroll
        for (int ii = 0; ii < 4; ii++) {
            const float* Pn = Pb + (size_t)(ic0 + ii) * HH * WW;
            uint32_t dbs = tb[bufi] + 4u * (ii * 1332);
#pragma unroll
            for (int u = 0; u < 6; u++) {
                int idx2 = tid + (u << 8);
                if (idx2 < 1296) cpa4(dbs + 4u * pdst[u], Pn + poff[u], ppred[u]);
            }
            uint32_t wdbs = wb2[bufi] + 4u * (ii * 400);
            cpa4(wdbs + 4u * tid, w0 + wbase0 + (ic0 + ii) * 25, true);
            if (wpq1) cpa4(wdbs + 4u * idxw1, w0 + wbase1 + (ic0 + ii) * 25, true);
        }
    };

    load_stage(0, 0);
    CP_COMMIT();

    for (int s = 0; s < 16; s++) {
        int cur = s & 1;
        if (s + 1 < 16) {
            load_stage((s + 1) * 4, cur ^ 1);
            CP_COMMIT();
            CP_WAIT1();
        } else {
            CP_WAIT0();
        }
        __syncthreads();
        const float* Tc = cur ? T1 : T0;
        const float* Wc = cur ? W1b : W0b;
#pragma unroll
        for (int ii = 0; ii < 4; ii++) {
            const float* Tb = &Tc[ii * 1332];
            const float* Wb = &Wc[ii * 400];
#pragma unroll
            for (int k = 0; k < 25; k++) {
                int ky = k / 5, kx = k % 5;
                const float* row0 = Tb + (2 * ty + ky) * 37 + 2 * tx + kx;
                float v00 = row0[0];
                float v01 = row0[1];
                float v10 = row0[37];
                float v11 = row0[38];
                u64 V00 = pack2(v00, v00);
                u64 V01 = pack2(v01, v01);
                u64 V10 = pack2(v10, v10);
                u64 V11 = pack2(v11, v11);
#pragma unroll
                for (int j = 0; j < 8; j++) {
                    u64 Wv = *reinterpret_cast<const u64*>(&Wb[k * 16 + 2 * j]);
                    fma2(acc00[j], Wv, V00);
                    fma2(acc01[j], Wv, V01);
                    fma2(acc10[j], Wv, V10);
                    fma2(acc11[j], Wv, V11);
                }
            }
        }
        __syncthreads();
    }
    int h = h0 + 2 * ty, w = w0b + 2 * tx;
#pragma unroll
    for (int j = 0; j < 8; j++) {
        int oc = og * 16 + 2 * j;
        float l00, h00, l01, h01, l10, h10, l11, h11;
        unpack2(acc00[j], l00, h00);
        unpack2(acc01[j], l01, h01);
        unpack2(acc10[j], l10, h10);
        unpack2(acc11[j], l11, h11);
        float blo = b0[oc], bhi = b0[oc + 1];
        float* o0 = out + ((size_t)(b * CC + oc) * HH + h) * WW + w;
        float* o1 = out + ((size_t)(b * CC + oc + 1) * HH + h) * WW + w;
        o0[0] = l00 + blo;  o0[1] = l01 + blo;
        o0[WW] = l10 + blo; o0[WW + 1] = l11 + blo;
        o1[0] = h00 + bhi;  o1[1] = h01 + bhi;
        o1[WW] = h10 + bhi; o1[WW + 1] = h11 + bhi;
    }
}

// ---------------- launcher (dual-stream branch overlap) ----------------
extern "C" void kernel_launch(void* const* d_in, const int* in_sizes, int n_in,
                              void* d_out, int out_size) {
    (void)in_sizes; (void)n_in; (void)out_size;
    const float* x    = (const float*)d_in[0];
    const float* wp_a = (const float*)d_in[1];
    const float* bp_a = (const float*)d_in[2];
    const float* wc_a = (const float*)d_in[3];
    const float* w1_a = (const float*)d_in[4];
    const float* b1_a = (const float*)d_in[5];
    const float* wp_p = (const float*)d_in[6];
    const float* bp_p = (const float*)d_in[7];
    const float* wc_p = (const float*)d_in[8];
    const float* w1_p = (const float*)d_in[9];
    const float* b1_p = (const float*)d_in[10];
    const float* w0   = (const float*)d_in[11];
    const float* b0   = (const float*)d_in[12];
    float* out = (float*)d_out;

    static cudaStream_t sA = 0, sB = 0;
    static cudaEvent_t evFork, evA, evB;
    static int init_done = 0;
    if (!init_done) {
        cudaStreamCreateWithFlags(&sA, cudaStreamNonBlocking);
        cudaStreamCreateWithFlags(&sB, cudaStreamNonBlocking);
        cudaEventCreateWithFlags(&evFork, cudaEventDisableTiming);
        cudaEventCreateWithFlags(&evA, cudaEventDisableTiming);
        cudaEventCreateWithFlags(&evB, cudaEventDisableTiming);
        cudaFuncSetAttribute(combine1x1_kernel, cudaFuncAttributeMaxDynamicSharedMemorySize, 49664);
        cudaFuncSetAttribute(conv5x5_kernel, cudaFuncAttributeMaxDynamicSharedMemorySize, 55424);
        init_done = 1;
    }

    twiddle_init<<<1, 192>>>();

    fft_row_fwd_pair<<<BB * CC * 128, 128>>>(x);
    fft_col_kernel<<<dim3(9, CC, BB), 256>>>(0);

    // fork: amp branch on sA, pha branch on sB
    cudaEventRecord(evFork, 0);
    cudaStreamWaitEvent(sA, evFork, 0);
    cudaStreamWaitEvent(sB, evFork, 0);

    conv_off_kernel<<<dim3(9, 8, BB), 256, 0, sA>>>(wp_a, bp_a, 0);
    gather_kernel<<<dim3((NP * 8 + 255) / 256), 256, 0, sA>>>(0);
    conv_s3_kernel<<<dim3(9, 8, BB * 2), 256, 0, sA>>>(wc_a, 0);

    conv_off_kernel<<<dim3(9, 8, BB), 256, 0, sB>>>(wp_p, bp_p, 1);
    gather_kernel<<<dim3((NP * 8 + 255) / 256), 256, 0, sB>>>(1);
    conv_s3_kernel<<<dim3(9, 8, BB * 2), 256, 0, sB>>>(wc_p, 1);

    // join
    cudaEventRecord(evA, sA);
    cudaEventRecord(evB, sB);
    cudaStreamWaitEvent(0, evA, 0);
    cudaStreamWaitEvent(0, evB, 0);

    // fused 1x1 conv + recombine, then inverse transform
    combine1x1_kernel<<<dim3(HWF / 32, BB), 256, 49664>>>(w1_a, b1_a, w1_p, b1_p);
    fft_col_kernel<<<dim3(9, CC, BB), 256>>>(1);
    ifft_row_pair<<<BB * CC * 128, 128>>>();

    conv5x5_kernel<<<dim3(8, 8, BB * 4), 256, 55424>>>(w0, b0, out);
}